// round 2
// baseline (speedup 1.0000x reference)
#include <cuda_runtime.h>
#include <math.h>

#define D_MODEL 1024
#define N_STD   12
#define N_WAVE  4
#define D_K     64
#define STD_DIM 768
#define SEQ     1024
#define BATCH   4
#define M_ROWS  (BATCH*SEQ)   // 4096

// Scratch (allocation-free rule: __device__ globals)
__device__ float g_Q[M_ROWS*STD_DIM];
__device__ float g_K[M_ROWS*STD_DIM];
__device__ float g_V[M_ROWS*D_MODEL];
__device__ float g_A[M_ROWS*D_MODEL];

// ---------------------------------------------------------------------------
// SGEMM: C[M,N] = A[M,K] @ W[K,N] + bias   (A,W,C row-major; y = x@W + b)
// 64x64 block tile, BK=16, 256 threads, 4x4 per-thread microtile.
// ---------------------------------------------------------------------------
__global__ __launch_bounds__(256) void sgemm_bias(
    const float* __restrict__ A, const float* __restrict__ W,
    const float* __restrict__ bias, float* __restrict__ C,
    int M, int N, int K)
{
    __shared__ float As[16][64];   // [k][row]  (A tile transposed)
    __shared__ float Bs[16][64];   // [k][col]

    const int tid = threadIdx.x;
    const int tx = tid & 15, ty = tid >> 4;
    const int bm = blockIdx.y * 64, bn = blockIdx.x * 64;

    float acc[4][4] = {};

    const int ar  = tid >> 2, ac4 = tid & 3;    // A loader: row 0..63, col4 0..3
    const int br  = tid >> 4, bc4 = tid & 15;   // W loader: row 0..15, col4 0..15

    const float* Aptr = A + (size_t)(bm + ar) * K + ac4 * 4;
    const float* Wptr = W + (size_t)br * N + bn + bc4 * 4;

    for (int k0 = 0; k0 < K; k0 += 16) {
        float4 a4 = *(const float4*)(Aptr + k0);
        As[ac4*4+0][ar] = a4.x;
        As[ac4*4+1][ar] = a4.y;
        As[ac4*4+2][ar] = a4.z;
        As[ac4*4+3][ar] = a4.w;
        *(float4*)&Bs[br][bc4*4] = *(const float4*)(Wptr + (size_t)k0 * N);
        __syncthreads();

#pragma unroll
        for (int k = 0; k < 16; k++) {
            float4 av = *(const float4*)&As[k][ty*4];
            float4 bv = *(const float4*)&Bs[k][tx*4];
            float aa[4] = {av.x, av.y, av.z, av.w};
            float bb[4] = {bv.x, bv.y, bv.z, bv.w};
#pragma unroll
            for (int i = 0; i < 4; i++)
#pragma unroll
                for (int j = 0; j < 4; j++)
                    acc[i][j] += aa[i] * bb[j];
        }
        __syncthreads();
    }

#pragma unroll
    for (int i = 0; i < 4; i++) {
        int row = bm + ty*4 + i;
#pragma unroll
        for (int j = 0; j < 4; j++) {
            int col = bn + tx*4 + j;
            C[(size_t)row * N + col] = acc[i][j] + bias[col];
        }
    }
}

// ---------------------------------------------------------------------------
// Fused causal attention (flash-style, online softmax).
// Grid: (SEQ/8, 16 heads, BATCH). Block: 256 threads = 8 warps.
// One warp owns one query row. 32-key tiles staged in smem.
// Heads 0..3 ("wave"): q=k = wave_amp chunk (6 dims), scale 1/sqrt(6).
// Heads 4..15: Q/K from projections (64 dims), scale 1/8.
// V always 64 dims from g_V. Output -> g_A laid out [B,S,16,64].
// ---------------------------------------------------------------------------
__global__ __launch_bounds__(256) void attn_kernel(
    const float* __restrict__ Qb, const float* __restrict__ Kb,
    const float* __restrict__ Vb, const float* __restrict__ wav,
    float* __restrict__ Ab)
{
    __shared__ float qs[8][68];    // padded stride 68 -> conflict-free float4
    __shared__ float ks[32][68];
    __shared__ float vs[32][64];
    __shared__ float ps[8][32];

    const int b = blockIdx.z, h = blockIdx.y;
    const int qbase = blockIdx.x * 8;
    const int tid = threadIdx.x;
    const int warp = tid >> 5, lane = tid & 31;
    const int i = qbase + warp;                 // this warp's query row
    const bool is_wave = (h < N_WAVE);
    const float scale = is_wave ? 0.4082482904638631f : 0.125f;

    // Stage q for this warp's row
    if (is_wave) {
        if (lane < 6) qs[warp][lane] = wav[(size_t)(b*SEQ + i)*24 + h*6 + lane];
    } else {
        const float* qrow = Qb + (size_t)(b*SEQ + i)*STD_DIM + (h - N_WAVE)*D_K;
        qs[warp][lane]      = qrow[lane];
        qs[warp][lane + 32] = qrow[lane + 32];
    }
    __syncthreads();

    float m = -INFINITY, l = 0.f;
    float2 o = make_float2(0.f, 0.f);
    const int ntiles = qbase / 32 + 1;          // causal: only tiles <= diagonal

    for (int jt = 0; jt < ntiles; jt++) {
        const int j0 = jt * 32;

        // ---- stage K tile ----
        if (is_wave) {
            if (tid < 192) {
                int r = tid / 6, c = tid % 6;
                ks[r][c] = wav[(size_t)(b*SEQ + j0 + r)*24 + h*6 + c];
            }
        } else {
#pragma unroll
            for (int u = 0; u < 4; u++) {
                int lin = tid + u*256;
                int r = lin >> 5, c = lin & 31;
                *(float2*)&ks[r][c*2] =
                    *(const float2*)(Kb + (size_t)(b*SEQ + j0 + r)*STD_DIM + (h - N_WAVE)*D_K + c*2);
            }
        }
        // ---- stage V tile ----
#pragma unroll
        for (int u = 0; u < 4; u++) {
            int lin = tid + u*256;
            int r = lin >> 5, c = lin & 31;
            *(float2*)&vs[r][c*2] =
                *(const float2*)(Vb + (size_t)(b*SEQ + j0 + r)*D_MODEL + h*D_K + c*2);
        }
        __syncthreads();

        // ---- score for key (j0 + lane) ----
        float s = 0.f;
        if (is_wave) {
#pragma unroll
            for (int c = 0; c < 6; c++) s += qs[warp][c] * ks[lane][c];
        } else {
#pragma unroll
            for (int d4 = 0; d4 < 16; d4++) {
                float4 q4 = *(const float4*)&qs[warp][d4*4];
                float4 k4 = *(const float4*)&ks[lane][d4*4];
                s += q4.x*k4.x + q4.y*k4.y + q4.z*k4.z + q4.w*k4.w;
            }
        }
        s *= scale;
        if (j0 + lane > i) s = -INFINITY;       // causal mask

        // ---- online softmax (warp = one row) ----
        float tmax = s;
#pragma unroll
        for (int off = 16; off; off >>= 1)
            tmax = fmaxf(tmax, __shfl_xor_sync(0xffffffffu, tmax, off));
        float mnew = fmaxf(m, tmax);            // finite: diag tile always has valid key
        float p   = __expf(s - mnew);           // -inf -> 0
        float fac = __expf(m - mnew);           // first tile: exp(-inf)=0
        float psum = p;
#pragma unroll
        for (int off = 16; off; off >>= 1)
            psum += __shfl_xor_sync(0xffffffffu, psum, off);
        l = l * fac + psum;
        ps[warp][lane] = p;
        o.x *= fac; o.y *= fac;
        __syncwarp();

        // ---- accumulate P·V : lane owns dims (2*lane, 2*lane+1) ----
#pragma unroll
        for (int jj = 0; jj < 32; jj++) {
            float pj = ps[warp][jj];            // smem broadcast
            float2 v2 = *(const float2*)&vs[jj][lane*2];
            o.x += pj * v2.x;
            o.y += pj * v2.y;
        }
        m = mnew;
        __syncthreads();
    }

    float inv = 1.f / l;
    float2 res = make_float2(o.x * inv, o.y * inv);
    *(float2*)(Ab + (size_t)(b*SEQ + i)*D_MODEL + h*D_K + lane*2) = res;
}

// ---------------------------------------------------------------------------
extern "C" void kernel_launch(void* const* d_in, const int* in_sizes, int n_in,
                              void* d_out, int out_size)
{
    const float* x   = (const float*)d_in[0];
    const float* wav = (const float*)d_in[1];
    // d_in[2] = causal_mask (implicit: lower-triangular; unused)
    const float* Wq  = (const float*)d_in[3];
    const float* bq  = (const float*)d_in[4];
    const float* Wk  = (const float*)d_in[5];
    const float* bk  = (const float*)d_in[6];
    const float* Wv  = (const float*)d_in[7];
    const float* bv  = (const float*)d_in[8];
    const float* Wo  = (const float*)d_in[9];
    const float* bo  = (const float*)d_in[10];
    float* out = (float*)d_out;

    float *gQ, *gK, *gV, *gA;
    cudaGetSymbolAddress((void**)&gQ, g_Q);
    cudaGetSymbolAddress((void**)&gK, g_K);
    cudaGetSymbolAddress((void**)&gV, g_V);
    cudaGetSymbolAddress((void**)&gA, g_A);

    // Projections
    sgemm_bias<<<dim3(STD_DIM/64, M_ROWS/64), 256>>>(x,  Wq, bq, gQ, M_ROWS, STD_DIM, D_MODEL);
    sgemm_bias<<<dim3(STD_DIM/64, M_ROWS/64), 256>>>(x,  Wk, bk, gK, M_ROWS, STD_DIM, D_MODEL);
    sgemm_bias<<<dim3(D_MODEL/64, M_ROWS/64), 256>>>(x,  Wv, bv, gV, M_ROWS, D_MODEL, D_MODEL);

    // Fused causal attention (wave + std heads)
    attn_kernel<<<dim3(SEQ/8, N_WAVE + N_STD, BATCH), 256>>>(gQ, gK, gV, wav, gA);

    // Output projection -> d_out
    sgemm_bias<<<dim3(D_MODEL/64, M_ROWS/64), 256>>>(gA, Wo, bo, out, M_ROWS, D_MODEL, D_MODEL);
}

// round 3
// speedup vs baseline: 1.3139x; 1.3139x over previous
#include <cuda_runtime.h>
#include <math.h>

#define D_MODEL 1024
#define N_STD   12
#define N_WAVE  4
#define D_K     64
#define STD_DIM 768
#define SEQ     1024
#define BATCH   4
#define M_ROWS  (BATCH*SEQ)   // 4096

#define BQ 128
#define BK 32
// smem strides (floats)
#define QS_S 132
#define KS_S 36
#define VS_S 68
#define PS_S 132
#define SMEM_FLOATS (64*QS_S + 64*KS_S + 32*VS_S + 32*PS_S)   // 17152
#define SMEM_BYTES  (SMEM_FLOATS*4)                            // 68608

// Scratch (allocation-free rule: __device__ globals)
__device__ float g_Q[M_ROWS*STD_DIM];
__device__ float g_K[M_ROWS*STD_DIM];
__device__ float g_V[M_ROWS*D_MODEL];
__device__ float g_A[M_ROWS*D_MODEL];

// ---------------------------------------------------------------------------
// SGEMM: C[M,N] = A[M,K] @ W[K,N] + bias  (row-major). 64x64 tile, BK=16,
// 256 threads, 4x4 microtile.  (unchanged from R1 — ~31 TF/s)
// ---------------------------------------------------------------------------
__global__ __launch_bounds__(256) void sgemm_bias(
    const float* __restrict__ A, const float* __restrict__ W,
    const float* __restrict__ bias, float* __restrict__ C,
    int M, int N, int K)
{
    __shared__ float As[16][64];
    __shared__ float Bs[16][64];

    const int tid = threadIdx.x;
    const int tx = tid & 15, ty = tid >> 4;
    const int bm = blockIdx.y * 64, bn = blockIdx.x * 64;

    float acc[4][4] = {};

    const int ar  = tid >> 2, ac4 = tid & 3;
    const int br  = tid >> 4, bc4 = tid & 15;

    const float* Aptr = A + (size_t)(bm + ar) * K + ac4 * 4;
    const float* Wptr = W + (size_t)br * N + bn + bc4 * 4;

    for (int k0 = 0; k0 < K; k0 += 16) {
        float4 a4 = *(const float4*)(Aptr + k0);
        As[ac4*4+0][ar] = a4.x;
        As[ac4*4+1][ar] = a4.y;
        As[ac4*4+2][ar] = a4.z;
        As[ac4*4+3][ar] = a4.w;
        *(float4*)&Bs[br][bc4*4] = *(const float4*)(Wptr + (size_t)k0 * N);
        __syncthreads();

#pragma unroll
        for (int k = 0; k < 16; k++) {
            float4 av = *(const float4*)&As[k][ty*4];
            float4 bv = *(const float4*)&Bs[k][tx*4];
            float aa[4] = {av.x, av.y, av.z, av.w};
            float bb[4] = {bv.x, bv.y, bv.z, bv.w};
#pragma unroll
            for (int i = 0; i < 4; i++)
#pragma unroll
                for (int j = 0; j < 4; j++)
                    acc[i][j] += aa[i] * bb[j];
        }
        __syncthreads();
    }

#pragma unroll
    for (int i = 0; i < 4; i++) {
        int row = bm + ty*4 + i;
#pragma unroll
        for (int j = 0; j < 4; j++)
            C[(size_t)row * N + bn + tx*4 + j] = acc[i][j] + bias[bn + tx*4 + j];
    }
}

// ---------------------------------------------------------------------------
// Blocked causal flash attention. Block: 128 queries x (32-key tiles),
// 256 threads as 16(ty: 8 queries each) x 16(tx).
//   score phase: tx -> 2 keys,  8q x 2k microtile  (16 FMA / ~2.5 LDS)
//   PV    phase: tx -> 4 dims,  8q x 4d microtile  (32 FMA / 3 LDS.128)
// Online softmax per row; O + stats in registers.
// ---------------------------------------------------------------------------
__global__ __launch_bounds__(256, 1) void attn_kernel(
    const float* __restrict__ Qb, const float* __restrict__ Kb,
    const float* __restrict__ Vb, const float* __restrict__ wav,
    float* __restrict__ Ab)
{
    extern __shared__ float smem[];
    float* Qs = smem;                  // [64][QS_S]  d-major
    float* Ks = Qs + 64*QS_S;          // [64][KS_S]  d-major
    float* Vs = Ks + 64*KS_S;          // [32][VS_S]  k-major
    float* Ps = Vs + 32*VS_S;          // [32][PS_S]  k-major (P transposed)

    const int b = blockIdx.z, h = blockIdx.y;
    const int q0 = (gridDim.x - 1 - blockIdx.x) * BQ;   // heavy blocks first
    const int tid = threadIdx.x;
    const int ty = tid >> 4, tx = tid & 15;
    const bool is_wave = (h < N_WAVE);
    const float scale = is_wave ? 0.4082482904638631f : 0.125f;
    const int hh = h - N_WAVE;

    // ---- stage Q (once per block) ----
    if (is_wave) {
        if (tid < BQ) {
            const float* wr = wav + (size_t)(b*SEQ + q0 + tid)*24 + h*6;
#pragma unroll
            for (int c = 0; c < 6; c++) Qs[c*QS_S + tid] = wr[c];
            Qs[6*QS_S + tid] = 0.f; Qs[7*QS_S + tid] = 0.f;
        }
        if (tid < BK) { Ks[6*KS_S + tid] = 0.f; Ks[7*KS_S + tid] = 0.f; }
    } else {
        const float* Qg = Qb + (size_t)(b*SEQ + q0)*STD_DIM + hh*D_K;
#pragma unroll
        for (int p = 0; p < 8; p++) {
            int row = p*16 + (tid >> 4);
            int d4  = (tid & 15)*4;
            float4 v = *(const float4*)(Qg + (size_t)row*STD_DIM + d4);
            Qs[(d4+0)*QS_S + row] = v.x;
            Qs[(d4+1)*QS_S + row] = v.y;
            Qs[(d4+2)*QS_S + row] = v.z;
            Qs[(d4+3)*QS_S + row] = v.w;
        }
    }

    float m[8], l[8], acc[8][4];
#pragma unroll
    for (int r = 0; r < 8; r++) {
        m[r] = -INFINITY; l[r] = 0.f;
#pragma unroll
        for (int c = 0; c < 4; c++) acc[r][c] = 0.f;
    }

    const int ntiles = q0/BK + 4;   // keys up to q0+127
    for (int jt = 0; jt < ntiles; jt++) {
        const int j0 = jt * BK;
        __syncthreads();            // protect Ks/Vs/Ps from previous iteration

        // ---- stage K tile (transposed) ----
        if (is_wave) {
            if (tid < BK) {
                const float* wr = wav + (size_t)(b*SEQ + j0 + tid)*24 + h*6;
#pragma unroll
                for (int c = 0; c < 6; c++) Ks[c*KS_S + tid] = wr[c];
            }
        } else {
            const float* Kg = Kb + (size_t)(b*SEQ + j0)*STD_DIM + hh*D_K;
#pragma unroll
            for (int p = 0; p < 2; p++) {
                int row = p*16 + (tid >> 4);
                int d4  = (tid & 15)*4;
                float4 v = *(const float4*)(Kg + (size_t)row*STD_DIM + d4);
                Ks[(d4+0)*KS_S + row] = v.x;
                Ks[(d4+1)*KS_S + row] = v.y;
                Ks[(d4+2)*KS_S + row] = v.z;
                Ks[(d4+3)*KS_S + row] = v.w;
            }
        }
        // ---- stage V tile ----
        {
            const float* Vg = Vb + (size_t)(b*SEQ + j0)*D_MODEL + h*D_K;
#pragma unroll
            for (int p = 0; p < 2; p++) {
                int row = p*16 + (tid >> 4);
                int d4  = (tid & 15)*4;
                *(float4*)(Vs + row*VS_S + d4) =
                    *(const float4*)(Vg + (size_t)row*D_MODEL + d4);
            }
        }
        __syncthreads();

        // ---- scores: 8q x 2k per thread ----
        float s[8][2];
#pragma unroll
        for (int r = 0; r < 8; r++) { s[r][0] = 0.f; s[r][1] = 0.f; }

        if (is_wave) {
#pragma unroll
            for (int d = 0; d < 8; d++) {
                float4 qa = *(const float4*)(Qs + d*QS_S + ty*8);
                float4 qb_ = *(const float4*)(Qs + d*QS_S + ty*8 + 4);
                float2 kk = *(const float2*)(Ks + d*KS_S + tx*2);
                float qr[8] = {qa.x,qa.y,qa.z,qa.w,qb_.x,qb_.y,qb_.z,qb_.w};
#pragma unroll
                for (int r = 0; r < 8; r++) {
                    s[r][0] += qr[r]*kk.x;
                    s[r][1] += qr[r]*kk.y;
                }
            }
        } else {
#pragma unroll
            for (int d = 0; d < 64; d++) {
                float4 qa = *(const float4*)(Qs + d*QS_S + ty*8);
                float4 qb_ = *(const float4*)(Qs + d*QS_S + ty*8 + 4);
                float2 kk = *(const float2*)(Ks + d*KS_S + tx*2);
                float qr[8] = {qa.x,qa.y,qa.z,qa.w,qb_.x,qb_.y,qb_.z,qb_.w};
#pragma unroll
                for (int r = 0; r < 8; r++) {
                    s[r][0] += qr[r]*kk.x;
                    s[r][1] += qr[r]*kk.y;
                }
            }
        }

        // ---- online softmax per row (reduce over 16 tx lanes) ----
#pragma unroll
        for (int r = 0; r < 8; r++) {
            int iglob = q0 + ty*8 + r;
            float s0 = s[r][0]*scale, s1 = s[r][1]*scale;
            if (j0 + tx*2 + 0 > iglob) s0 = -INFINITY;
            if (j0 + tx*2 + 1 > iglob) s1 = -INFINITY;
            float rm = fmaxf(s0, s1);
#pragma unroll
            for (int off = 8; off; off >>= 1)
                rm = fmaxf(rm, __shfl_xor_sync(0xffffffffu, rm, off));
            float mnew = fmaxf(m[r], rm);
            float p0 = __expf(s0 - mnew);
            float p1 = __expf(s1 - mnew);
            float fac = __expf(m[r] - mnew);
            float ps = p0 + p1;
#pragma unroll
            for (int off = 8; off; off >>= 1)
                ps += __shfl_xor_sync(0xffffffffu, ps, off);
            l[r] = l[r]*fac + ps;
            m[r] = mnew;
            Ps[(tx*2+0)*PS_S + ty*8 + r] = p0;
            Ps[(tx*2+1)*PS_S + ty*8 + r] = p1;
#pragma unroll
            for (int c = 0; c < 4; c++) acc[r][c] *= fac;
        }
        __syncthreads();

        // ---- PV: 8q x 4d per thread ----
#pragma unroll
        for (int j = 0; j < BK; j++) {
            float4 pa = *(const float4*)(Ps + j*PS_S + ty*8);
            float4 pb = *(const float4*)(Ps + j*PS_S + ty*8 + 4);
            float4 vv = *(const float4*)(Vs + j*VS_S + tx*4);
            float pr[8] = {pa.x,pa.y,pa.z,pa.w,pb.x,pb.y,pb.z,pb.w};
#pragma unroll
            for (int r = 0; r < 8; r++) {
                acc[r][0] += pr[r]*vv.x;
                acc[r][1] += pr[r]*vv.y;
                acc[r][2] += pr[r]*vv.z;
                acc[r][3] += pr[r]*vv.w;
            }
        }
    }

    // ---- epilogue ----
#pragma unroll
    for (int r = 0; r < 8; r++) {
        float inv = 1.f / l[r];
        float4 o = make_float4(acc[r][0]*inv, acc[r][1]*inv,
                               acc[r][2]*inv, acc[r][3]*inv);
        *(float4*)(Ab + (size_t)(b*SEQ + q0 + ty*8 + r)*D_MODEL + h*D_K + tx*4) = o;
    }
}

// ---------------------------------------------------------------------------
extern "C" void kernel_launch(void* const* d_in, const int* in_sizes, int n_in,
                              void* d_out, int out_size)
{
    const float* x   = (const float*)d_in[0];
    const float* wav = (const float*)d_in[1];
    // d_in[2] = causal_mask (implicit lower-triangular; unused)
    const float* Wq  = (const float*)d_in[3];
    const float* bq  = (const float*)d_in[4];
    const float* Wk  = (const float*)d_in[5];
    const float* bk  = (const float*)d_in[6];
    const float* Wv  = (const float*)d_in[7];
    const float* bv  = (const float*)d_in[8];
    const float* Wo  = (const float*)d_in[9];
    const float* bo  = (const float*)d_in[10];
    float* out = (float*)d_out;

    float *gQ, *gK, *gV, *gA;
    cudaGetSymbolAddress((void**)&gQ, g_Q);
    cudaGetSymbolAddress((void**)&gK, g_K);
    cudaGetSymbolAddress((void**)&gV, g_V);
    cudaGetSymbolAddress((void**)&gA, g_A);

    cudaFuncSetAttribute(attn_kernel,
        cudaFuncAttributeMaxDynamicSharedMemorySize, SMEM_BYTES);

    // Projections
    sgemm_bias<<<dim3(STD_DIM/64, M_ROWS/64), 256>>>(x,  Wq, bq, gQ, M_ROWS, STD_DIM, D_MODEL);
    sgemm_bias<<<dim3(STD_DIM/64, M_ROWS/64), 256>>>(x,  Wk, bk, gK, M_ROWS, STD_DIM, D_MODEL);
    sgemm_bias<<<dim3(D_MODEL/64, M_ROWS/64), 256>>>(x,  Wv, bv, gV, M_ROWS, D_MODEL, D_MODEL);

    // Fused causal attention (wave + std heads)
    attn_kernel<<<dim3(SEQ/BQ, N_WAVE + N_STD, BATCH), 256, SMEM_BYTES>>>(gQ, gK, gV, wav, gA);

    // Output projection -> d_out
    sgemm_bias<<<dim3(D_MODEL/64, M_ROWS/64), 256>>>(gA, Wo, bo, out, M_ROWS, D_MODEL, D_MODEL);
}

// round 5
// speedup vs baseline: 1.6951x; 1.2901x over previous
#include <cuda_runtime.h>
#include <math.h>

#define D_MODEL 1024
#define N_STD   12
#define N_WAVE  4
#define D_K     64
#define STD_DIM 768
#define SEQ     1024
#define BATCH   4
#define M_ROWS  (BATCH*SEQ)   // 4096

#define BQ 128
#define BK 32
// attn smem strides (floats)
#define QS_S 132
#define KS_S 36
#define VS_S 68
#define PS_S 132
#define ATTN_SMEM_FLOATS (64*QS_S + 64*KS_S + 32*VS_S + 32*PS_S)   // 17152
#define ATTN_SMEM_BYTES  (ATTN_SMEM_FLOATS*4)                       // 68608

// Scratch (allocation-free rule: __device__ globals)
__device__ float g_Q[M_ROWS*STD_DIM];
__device__ float g_K[M_ROWS*STD_DIM];
__device__ float g_V[M_ROWS*D_MODEL];
__device__ float g_A[M_ROWS*D_MODEL];

// ---------------------------------------------------------------------------
// SGEMM core: 128x128 tile, BK=8, double-buffered smem, 256 threads,
// 8x8 microtile per thread (rows ty*4 & ty*4+64, cols tx*4 & tx*4+64).
// C[bm:bm+128, bn:bn+128] = A[bm:,0:K] @ W[0:K, bn:] + bias
// A row stride = K; W and C row stride = ldw.
// ---------------------------------------------------------------------------
__device__ __forceinline__ void sgemm128_core(
    const float* __restrict__ A, const float* __restrict__ W,
    const float* __restrict__ bias, float* __restrict__ C,
    int K, int ldw, int bm, int bn)
{
    __shared__ float As[2][8][132];   // [buf][k][m]  (132: conflict-free stores)
    __shared__ float Bs[2][8][128];   // [buf][k][n]

    const int tid = threadIdx.x;
    const int tx = tid & 15, ty = tid >> 4;

    // loaders
    const int ar = tid >> 1;          // A row within tile (0..127)
    const int ak = (tid & 1) * 4;     // A k-offset (0 or 4)
    const int bk = tid >> 5;          // B k row (0..7)
    const int bc = (tid & 31) * 4;    // B col (0..124)

    const float* Ap = A + (size_t)(bm + ar) * K + ak;
    const float* Wp = W + (size_t)bk * ldw + bn + bc;

    float4 af = *(const float4*)(Ap);
    float4 bf = *(const float4*)(Wp);
    int buf = 0;
    As[0][ak+0][ar] = af.x;
    As[0][ak+1][ar] = af.y;
    As[0][ak+2][ar] = af.z;
    As[0][ak+3][ar] = af.w;
    *(float4*)&Bs[0][bk][bc] = bf;
    __syncthreads();

    float acc[8][8];
#pragma unroll
    for (int i = 0; i < 8; i++)
#pragma unroll
        for (int j = 0; j < 8; j++) acc[i][j] = 0.f;

    for (int k0 = 8; k0 <= K; k0 += 8) {
        float4 afn, bfn;
        const bool more = (k0 < K);
        if (more) {
            afn = *(const float4*)(Ap + k0);
            bfn = *(const float4*)(Wp + (size_t)k0 * ldw);
        }
#pragma unroll
        for (int k = 0; k < 8; k++) {
            float4 a0 = *(const float4*)&As[buf][k][ty*4];
            float4 a1 = *(const float4*)&As[buf][k][ty*4 + 64];
            float4 b0 = *(const float4*)&Bs[buf][k][tx*4];
            float4 b1 = *(const float4*)&Bs[buf][k][tx*4 + 64];
            float aa[8] = {a0.x,a0.y,a0.z,a0.w,a1.x,a1.y,a1.z,a1.w};
            float bb[8] = {b0.x,b0.y,b0.z,b0.w,b1.x,b1.y,b1.z,b1.w};
#pragma unroll
            for (int i = 0; i < 8; i++)
#pragma unroll
                for (int j = 0; j < 8; j++)
                    acc[i][j] += aa[i] * bb[j];
        }
        if (more) {
            buf ^= 1;
            As[buf][ak+0][ar] = afn.x;
            As[buf][ak+1][ar] = afn.y;
            As[buf][ak+2][ar] = afn.z;
            As[buf][ak+3][ar] = afn.w;
            *(float4*)&Bs[buf][bk][bc] = bfn;
            __syncthreads();
        }
    }

    // epilogue
    float4 bias0 = *(const float4*)&bias[bn + tx*4];
    float4 bias1 = *(const float4*)&bias[bn + tx*4 + 64];
    float bb0[4] = {bias0.x, bias0.y, bias0.z, bias0.w};
    float bb1[4] = {bias1.x, bias1.y, bias1.z, bias1.w};
#pragma unroll
    for (int ih = 0; ih < 2; ih++) {
#pragma unroll
        for (int i = 0; i < 4; i++) {
            int row = bm + ih*64 + ty*4 + i;
            float* Crow = C + (size_t)row * ldw + bn;
            float4 o0, o1;
            o0.x = acc[ih*4+i][0] + bb0[0];
            o0.y = acc[ih*4+i][1] + bb0[1];
            o0.z = acc[ih*4+i][2] + bb0[2];
            o0.w = acc[ih*4+i][3] + bb0[3];
            o1.x = acc[ih*4+i][4] + bb1[0];
            o1.y = acc[ih*4+i][5] + bb1[1];
            o1.z = acc[ih*4+i][6] + bb1[2];
            o1.w = acc[ih*4+i][7] + bb1[3];
            *(float4*)(Crow + tx*4)      = o0;
            *(float4*)(Crow + tx*4 + 64) = o1;
        }
    }
}

// Fused Q/K/V projection: N-space = [Q 768 | K 768 | V 1024], grid.x = 20
__global__ __launch_bounds__(256) void qkv_gemm(
    const float* __restrict__ x,
    const float* __restrict__ Wq, const float* __restrict__ bq,
    const float* __restrict__ Wk, const float* __restrict__ bk_,
    const float* __restrict__ Wv, const float* __restrict__ bv_,
    float* __restrict__ gQ, float* __restrict__ gK, float* __restrict__ gV)
{
    const int bn_g = blockIdx.x * 128;
    const int bm   = blockIdx.y * 128;
    const float* W; const float* bias; float* C; int ldw, bn;
    if (bn_g < 768)       { W = Wq; bias = bq;  C = gQ; ldw = 768;  bn = bn_g; }
    else if (bn_g < 1536) { W = Wk; bias = bk_; C = gK; ldw = 768;  bn = bn_g - 768; }
    else                  { W = Wv; bias = bv_; C = gV; ldw = 1024; bn = bn_g - 1536; }
    sgemm128_core(x, W, bias, C, D_MODEL, ldw, bm, bn);
}

// Generic square-ish GEMM (used for O projection)
__global__ __launch_bounds__(256) void o_gemm(
    const float* __restrict__ A, const float* __restrict__ W,
    const float* __restrict__ bias, float* __restrict__ C)
{
    sgemm128_core(A, W, bias, C, D_MODEL, D_MODEL, blockIdx.y*128, blockIdx.x*128);
}

// ---------------------------------------------------------------------------
// Blocked causal flash attention. 128 queries x 32-key tiles, 256 threads
// as 16(ty: 8 queries) x 16(tx). 2 CTAs/SM via launch bounds.
// ---------------------------------------------------------------------------
__global__ __launch_bounds__(256, 2) void attn_kernel(
    const float* __restrict__ Qb, const float* __restrict__ Kb,
    const float* __restrict__ Vb, const float* __restrict__ wav,
    float* __restrict__ Ab)
{
    extern __shared__ float smem[];
    float* Qs = smem;                  // [64][QS_S]  d-major
    float* Ks = Qs + 64*QS_S;          // [64][KS_S]  d-major
    float* Vs = Ks + 64*KS_S;          // [32][VS_S]  k-major
    float* Ps = Vs + 32*VS_S;          // [32][PS_S]  k-major (P transposed)

    const int b = blockIdx.z, h = blockIdx.y;
    const int q0 = (gridDim.x - 1 - blockIdx.x) * BQ;   // heavy blocks first
    const int tid = threadIdx.x;
    const int ty = tid >> 4, tx = tid & 15;
    const bool is_wave = (h < N_WAVE);
    const float scale = is_wave ? 0.4082482904638631f : 0.125f;
    const int hh = h - N_WAVE;

    // ---- stage Q (once per block) ----
    if (is_wave) {
        if (tid < BQ) {
            const float* wr = wav + (size_t)(b*SEQ + q0 + tid)*24 + h*6;
#pragma unroll
            for (int c = 0; c < 6; c++) Qs[c*QS_S + tid] = wr[c];
            Qs[6*QS_S + tid] = 0.f; Qs[7*QS_S + tid] = 0.f;
        }
        if (tid < BK) { Ks[6*KS_S + tid] = 0.f; Ks[7*KS_S + tid] = 0.f; }
    } else {
        const float* Qg = Qb + (size_t)(b*SEQ + q0)*STD_DIM + hh*D_K;
#pragma unroll
        for (int p = 0; p < 8; p++) {
            int row = p*16 + (tid >> 4);
            int d4  = (tid & 15)*4;
            float4 v = *(const float4*)(Qg + (size_t)row*STD_DIM + d4);
            Qs[(d4+0)*QS_S + row] = v.x;
            Qs[(d4+1)*QS_S + row] = v.y;
            Qs[(d4+2)*QS_S + row] = v.z;
            Qs[(d4+3)*QS_S + row] = v.w;
        }
    }

    float m[8], l[8], acc[8][4];
#pragma unroll
    for (int r = 0; r < 8; r++) {
        m[r] = -INFINITY; l[r] = 0.f;
#pragma unroll
        for (int c = 0; c < 4; c++) acc[r][c] = 0.f;
    }

    const int ntiles = q0/BK + 4;   // keys up to q0+127
    for (int jt = 0; jt < ntiles; jt++) {
        const int j0 = jt * BK;
        __syncthreads();            // protect Ks/Vs/Ps from previous iteration

        // ---- stage K tile (transposed) ----
        if (is_wave) {
            if (tid < BK) {
                const float* wr = wav + (size_t)(b*SEQ + j0 + tid)*24 + h*6;
#pragma unroll
                for (int c = 0; c < 6; c++) Ks[c*KS_S + tid] = wr[c];
            }
        } else {
            const float* Kg = Kb + (size_t)(b*SEQ + j0)*STD_DIM + hh*D_K;
#pragma unroll
            for (int p = 0; p < 2; p++) {
                int row = p*16 + (tid >> 4);
                int d4  = (tid & 15)*4;
                float4 v = *(const float4*)(Kg + (size_t)row*STD_DIM + d4);
                Ks[(d4+0)*KS_S + row] = v.x;
                Ks[(d4+1)*KS_S + row] = v.y;
                Ks[(d4+2)*KS_S + row] = v.z;
                Ks[(d4+3)*KS_S + row] = v.w;
            }
        }
        // ---- stage V tile ----
        {
            const float* Vg = Vb + (size_t)(b*SEQ + j0)*D_MODEL + h*D_K;
#pragma unroll
            for (int p = 0; p < 2; p++) {
                int row = p*16 + (tid >> 4);
                int d4  = (tid & 15)*4;
                *(float4*)(Vs + row*VS_S + d4) =
                    *(const float4*)(Vg + (size_t)row*D_MODEL + d4);
            }
        }
        __syncthreads();

        // ---- scores: 8q x 2k per thread ----
        float s[8][2];
#pragma unroll
        for (int r = 0; r < 8; r++) { s[r][0] = 0.f; s[r][1] = 0.f; }

        const int ndims = is_wave ? 8 : 64;
        for (int d = 0; d < ndims; d++) {
            float4 qa = *(const float4*)(Qs + d*QS_S + ty*8);
            float4 qb_ = *(const float4*)(Qs + d*QS_S + ty*8 + 4);
            float2 kk = *(const float2*)(Ks + d*KS_S + tx*2);
            float qr[8] = {qa.x,qa.y,qa.z,qa.w,qb_.x,qb_.y,qb_.z,qb_.w};
#pragma unroll
            for (int r = 0; r < 8; r++) {
                s[r][0] += qr[r]*kk.x;
                s[r][1] += qr[r]*kk.y;
            }
        }

        // ---- online softmax per row (reduce over 16 tx lanes) ----
#pragma unroll
        for (int r = 0; r < 8; r++) {
            int iglob = q0 + ty*8 + r;
            float s0 = s[r][0]*scale, s1 = s[r][1]*scale;
            if (j0 + tx*2 + 0 > iglob) s0 = -INFINITY;
            if (j0 + tx*2 + 1 > iglob) s1 = -INFINITY;
            float rm = fmaxf(s0, s1);
#pragma unroll
            for (int off = 8; off; off >>= 1)
                rm = fmaxf(rm, __shfl_xor_sync(0xffffffffu, rm, off));
            float mnew = fmaxf(m[r], rm);
            float p0 = __expf(s0 - mnew);
            float p1 = __expf(s1 - mnew);
            float fac = __expf(m[r] - mnew);
            float ps = p0 + p1;
#pragma unroll
            for (int off = 8; off; off >>= 1)
                ps += __shfl_xor_sync(0xffffffffu, ps, off);
            l[r] = l[r]*fac + ps;
            m[r] = mnew;
            Ps[(tx*2+0)*PS_S + ty*8 + r] = p0;
            Ps[(tx*2+1)*PS_S + ty*8 + r] = p1;
#pragma unroll
            for (int c = 0; c < 4; c++) acc[r][c] *= fac;
        }
        __syncthreads();

        // ---- PV: 8q x 4d per thread ----
#pragma unroll
        for (int j = 0; j < BK; j++) {
            float4 pa = *(const float4*)(Ps + j*PS_S + ty*8);
            float4 pb = *(const float4*)(Ps + j*PS_S + ty*8 + 4);
            float4 vv = *(const float4*)(Vs + j*VS_S + tx*4);
            float pr[8] = {pa.x,pa.y,pa.z,pa.w,pb.x,pb.y,pb.z,pb.w};
#pragma unroll
            for (int r = 0; r < 8; r++) {
                acc[r][0] += pr[r]*vv.x;
                acc[r][1] += pr[r]*vv.y;
                acc[r][2] += pr[r]*vv.z;
                acc[r][3] += pr[r]*vv.w;
            }
        }
    }

    // ---- epilogue ----
#pragma unroll
    for (int r = 0; r < 8; r++) {
        float inv = 1.f / l[r];
        float4 o = make_float4(acc[r][0]*inv, acc[r][1]*inv,
                               acc[r][2]*inv, acc[r][3]*inv);
        *(float4*)(Ab + (size_t)(b*SEQ + q0 + ty*8 + r)*D_MODEL + h*D_K + tx*4) = o;
    }
}

// ---------------------------------------------------------------------------
extern "C" void kernel_launch(void* const* d_in, const int* in_sizes, int n_in,
                              void* d_out, int out_size)
{
    const float* x   = (const float*)d_in[0];
    const float* wav = (const float*)d_in[1];
    // d_in[2] = causal_mask (implicit lower-triangular; unused)
    const float* Wq  = (const float*)d_in[3];
    const float* bq  = (const float*)d_in[4];
    const float* Wk  = (const float*)d_in[5];
    const float* bk  = (const float*)d_in[6];
    const float* Wv  = (const float*)d_in[7];
    const float* bv  = (const float*)d_in[8];
    const float* Wo  = (const float*)d_in[9];
    const float* bo  = (const float*)d_in[10];
    float* out = (float*)d_out;

    float *gQ, *gK, *gV, *gA;
    cudaGetSymbolAddress((void**)&gQ, g_Q);
    cudaGetSymbolAddress((void**)&gK, g_K);
    cudaGetSymbolAddress((void**)&gV, g_V);
    cudaGetSymbolAddress((void**)&gA, g_A);

    cudaFuncSetAttribute(attn_kernel,
        cudaFuncAttributeMaxDynamicSharedMemorySize, ATTN_SMEM_BYTES);

    // Fused Q/K/V projections: N-space 2560 = 20 tiles of 128
    qkv_gemm<<<dim3(20, M_ROWS/128), 256>>>(x, Wq, bq, Wk, bk, Wv, bv, gQ, gK, gV);

    // Fused causal attention (wave + std heads)
    attn_kernel<<<dim3(SEQ/BQ, N_WAVE + N_STD, BATCH), 256, ATTN_SMEM_BYTES>>>(gQ, gK, gV, wav, gA);

    // Output projection -> d_out
    o_gemm<<<dim3(D_MODEL/128, M_ROWS/128), 256>>>(gA, Wo, bo, out);
}

// round 6
// speedup vs baseline: 2.6409x; 1.5580x over previous
#include <cuda_runtime.h>
#include <math.h>

#define D_MODEL 1024
#define N_STD   12
#define N_WAVE  4
#define D_K     64
#define STD_DIM 768
#define SEQ     1024
#define BATCH   4
#define M_ROWS  (BATCH*SEQ)   // 4096

#define BQ 128
#define BK 32
// attn smem strides (floats)
#define QS_S 132
#define KS_S 36
#define VS_S 68
#define PS_S 132
#define ATTN_SMEM_FLOATS (64*QS_S + 64*KS_S + 32*VS_S + 32*PS_S)   // 17152
#define ATTN_SMEM_BYTES  (ATTN_SMEM_FLOATS*4)                       // 68608

// tf32 GEMM tiling
#define GBK  16
#define AS_S 20     // As row stride (m-major [128][AS_S]) — conflict-free frag reads
#define BS_S 136    // Bs row stride ([16][BS_S]) — conflict-free frag reads

// Scratch (allocation-free rule: __device__ globals)
__device__ float g_Q[M_ROWS*STD_DIM];
__device__ float g_K[M_ROWS*STD_DIM];
__device__ float g_V[M_ROWS*D_MODEL];
__device__ float g_A[M_ROWS*D_MODEL];

__device__ __forceinline__ unsigned f2tf32(float f) {
    unsigned r;
    asm("cvt.rna.tf32.f32 %0, %1;" : "=r"(r) : "f"(f));
    return r;
}

__device__ __forceinline__ void mma_tf32(float c[4],
    unsigned a0, unsigned a1, unsigned a2, unsigned a3,
    unsigned b0, unsigned b1)
{
    asm volatile(
        "mma.sync.aligned.m16n8k8.row.col.f32.tf32.tf32.f32 "
        "{%0,%1,%2,%3}, {%4,%5,%6,%7}, {%8,%9}, {%0,%1,%2,%3};"
        : "+f"(c[0]), "+f"(c[1]), "+f"(c[2]), "+f"(c[3])
        : "r"(a0), "r"(a1), "r"(a2), "r"(a3), "r"(b0), "r"(b1));
}

// ---------------------------------------------------------------------------
// TF32 tensor-core GEMM core: 128x128 tile, BK=16, double-buffered,
// 256 threads = 2(m) x 4(n) warps; warp tile 64x32 = 4x4 m16n8k8 fragments.
// C[bm:bm+128, bn:bn+128] = A[bm:, 0:K] @ W[0:K, bn:] + bias
// A row stride = K; W and C row stride = ldw. K % 16 == 0.
// ---------------------------------------------------------------------------
__device__ __forceinline__ void tf32gemm128_core(
    const float* __restrict__ A, const float* __restrict__ W,
    const float* __restrict__ bias, float* __restrict__ C,
    int K, int ldw, int bm, int bn)
{
    __shared__ unsigned As[2][128][AS_S];   // tf32 bits, [m][k]
    __shared__ unsigned Bs[2][GBK][BS_S];   // tf32 bits, [k][n]

    const int tid  = threadIdx.x;
    const int lane = tid & 31;
    const int wid  = tid >> 5;
    const int warp_m = wid >> 2;     // 0..1 -> 64 rows
    const int warp_n = wid & 3;      // 0..3 -> 32 cols
    const int g = lane >> 2;         // groupID 0..7
    const int q = lane & 3;          // threadID-in-group 0..3

    // staging coordinates (2 float4 each for A and B per thread)
    const int ar0 = tid >> 2,        akc0 = (tid & 3) * 4;          // i = tid
    const int ar1 = (tid + 256) >> 2, akc1 = ((tid + 256) & 3) * 4; // i = tid+256
    const int bk0 = tid >> 5,        bnc0 = (tid & 31) * 4;
    const int bk1 = (tid + 256) >> 5, bnc1 = ((tid + 256) & 31) * 4;

    const float* Ap0 = A + (size_t)(bm + ar0) * K + akc0;
    const float* Ap1 = A + (size_t)(bm + ar1) * K + akc1;
    const float* Wp0 = W + (size_t)bk0 * ldw + bn + bnc0;
    const float* Wp1 = W + (size_t)bk1 * ldw + bn + bnc1;

    // ---- initial stage (k0 = 0) ----
    {
        float4 a0v = *(const float4*)Ap0;
        float4 a1v = *(const float4*)Ap1;
        float4 b0v = *(const float4*)Wp0;
        float4 b1v = *(const float4*)Wp1;
        As[0][ar0][akc0+0] = f2tf32(a0v.x); As[0][ar0][akc0+1] = f2tf32(a0v.y);
        As[0][ar0][akc0+2] = f2tf32(a0v.z); As[0][ar0][akc0+3] = f2tf32(a0v.w);
        As[0][ar1][akc1+0] = f2tf32(a1v.x); As[0][ar1][akc1+1] = f2tf32(a1v.y);
        As[0][ar1][akc1+2] = f2tf32(a1v.z); As[0][ar1][akc1+3] = f2tf32(a1v.w);
        uint4 bb0 = make_uint4(f2tf32(b0v.x), f2tf32(b0v.y), f2tf32(b0v.z), f2tf32(b0v.w));
        uint4 bb1 = make_uint4(f2tf32(b1v.x), f2tf32(b1v.y), f2tf32(b1v.z), f2tf32(b1v.w));
        *(uint4*)&Bs[0][bk0][bnc0] = bb0;
        *(uint4*)&Bs[0][bk1][bnc1] = bb1;
    }
    __syncthreads();

    float acc[4][4][4];
#pragma unroll
    for (int mt = 0; mt < 4; mt++)
#pragma unroll
        for (int nt = 0; nt < 4; nt++)
#pragma unroll
            for (int i = 0; i < 4; i++) acc[mt][nt][i] = 0.f;

    int buf = 0;
    for (int k0 = GBK; k0 <= K; k0 += GBK) {
        float4 na0, na1, nb0, nb1;
        const bool more = (k0 < K);
        if (more) {
            na0 = *(const float4*)(Ap0 + k0);
            na1 = *(const float4*)(Ap1 + k0);
            nb0 = *(const float4*)(Wp0 + (size_t)k0 * ldw);
            nb1 = *(const float4*)(Wp1 + (size_t)k0 * ldw);
        }

#pragma unroll
        for (int ks = 0; ks < 2; ks++) {
            const int k8 = ks * 8;
            unsigned a[4][4], b[4][2];
#pragma unroll
            for (int mt = 0; mt < 4; mt++) {
                int r = warp_m*64 + mt*16 + g;
                a[mt][0] = As[buf][r    ][k8 + q];
                a[mt][1] = As[buf][r + 8][k8 + q];
                a[mt][2] = As[buf][r    ][k8 + q + 4];
                a[mt][3] = As[buf][r + 8][k8 + q + 4];
            }
#pragma unroll
            for (int nt = 0; nt < 4; nt++) {
                int c = warp_n*32 + nt*8 + g;
                b[nt][0] = Bs[buf][k8 + q    ][c];
                b[nt][1] = Bs[buf][k8 + q + 4][c];
            }
#pragma unroll
            for (int mt = 0; mt < 4; mt++)
#pragma unroll
                for (int nt = 0; nt < 4; nt++)
                    mma_tf32(acc[mt][nt],
                             a[mt][0], a[mt][1], a[mt][2], a[mt][3],
                             b[nt][0], b[nt][1]);
        }

        if (more) {
            buf ^= 1;
            As[buf][ar0][akc0+0] = f2tf32(na0.x); As[buf][ar0][akc0+1] = f2tf32(na0.y);
            As[buf][ar0][akc0+2] = f2tf32(na0.z); As[buf][ar0][akc0+3] = f2tf32(na0.w);
            As[buf][ar1][akc1+0] = f2tf32(na1.x); As[buf][ar1][akc1+1] = f2tf32(na1.y);
            As[buf][ar1][akc1+2] = f2tf32(na1.z); As[buf][ar1][akc1+3] = f2tf32(na1.w);
            uint4 u0 = make_uint4(f2tf32(nb0.x), f2tf32(nb0.y), f2tf32(nb0.z), f2tf32(nb0.w));
            uint4 u1 = make_uint4(f2tf32(nb1.x), f2tf32(nb1.y), f2tf32(nb1.z), f2tf32(nb1.w));
            *(uint4*)&Bs[buf][bk0][bnc0] = u0;
            *(uint4*)&Bs[buf][bk1][bnc1] = u1;
            __syncthreads();
        }
    }

    // ---- epilogue: c0,c1 -> (row g, cols 2q..2q+1); c2,c3 -> row g+8 ----
#pragma unroll
    for (int mt = 0; mt < 4; mt++) {
        int r0 = bm + warp_m*64 + mt*16 + g;
#pragma unroll
        for (int nt = 0; nt < 4; nt++) {
            int col = bn + warp_n*32 + nt*8 + 2*q;
            float2 bb = *(const float2*)&bias[col];
            float2 o0 = make_float2(acc[mt][nt][0] + bb.x, acc[mt][nt][1] + bb.y);
            float2 o1 = make_float2(acc[mt][nt][2] + bb.x, acc[mt][nt][3] + bb.y);
            *(float2*)&C[(size_t)r0 * ldw + col]       = o0;
            *(float2*)&C[(size_t)(r0+8) * ldw + col]   = o1;
        }
    }
}

// Fused Q/K/V projection: N-space = [Q 768 | K 768 | V 1024], grid.x = 20
__global__ __launch_bounds__(256) void qkv_gemm(
    const float* __restrict__ x,
    const float* __restrict__ Wq, const float* __restrict__ bq,
    const float* __restrict__ Wk, const float* __restrict__ bk_,
    const float* __restrict__ Wv, const float* __restrict__ bv_,
    float* __restrict__ gQ, float* __restrict__ gK, float* __restrict__ gV)
{
    const int bn_g = blockIdx.x * 128;
    const int bm   = blockIdx.y * 128;
    const float* W; const float* bias; float* C; int ldw, bn;
    if (bn_g < 768)       { W = Wq; bias = bq;  C = gQ; ldw = 768;  bn = bn_g; }
    else if (bn_g < 1536) { W = Wk; bias = bk_; C = gK; ldw = 768;  bn = bn_g - 768; }
    else                  { W = Wv; bias = bv_; C = gV; ldw = 1024; bn = bn_g - 1536; }
    tf32gemm128_core(x, W, bias, C, D_MODEL, ldw, bm, bn);
}

// O projection
__global__ __launch_bounds__(256) void o_gemm(
    const float* __restrict__ A, const float* __restrict__ W,
    const float* __restrict__ bias, float* __restrict__ C)
{
    tf32gemm128_core(A, W, bias, C, D_MODEL, D_MODEL, blockIdx.y*128, blockIdx.x*128);
}

// ---------------------------------------------------------------------------
// Blocked causal flash attention (unchanged from R5 — measured ~330us).
// 128 queries x 32-key tiles, 256 threads as 16(ty: 8 queries) x 16(tx).
// ---------------------------------------------------------------------------
__global__ __launch_bounds__(256, 2) void attn_kernel(
    const float* __restrict__ Qb, const float* __restrict__ Kb,
    const float* __restrict__ Vb, const float* __restrict__ wav,
    float* __restrict__ Ab)
{
    extern __shared__ float smem[];
    float* Qs = smem;                  // [64][QS_S]  d-major
    float* Ks = Qs + 64*QS_S;          // [64][KS_S]  d-major
    float* Vs = Ks + 64*KS_S;          // [32][VS_S]  k-major
    float* Ps = Vs + 32*VS_S;          // [32][PS_S]  k-major (P transposed)

    const int b = blockIdx.z, h = blockIdx.y;
    const int q0 = (gridDim.x - 1 - blockIdx.x) * BQ;   // heavy blocks first
    const int tid = threadIdx.x;
    const int ty = tid >> 4, tx = tid & 15;
    const bool is_wave = (h < N_WAVE);
    const float scale = is_wave ? 0.4082482904638631f : 0.125f;
    const int hh = h - N_WAVE;

    // ---- stage Q (once per block) ----
    if (is_wave) {
        if (tid < BQ) {
            const float* wr = wav + (size_t)(b*SEQ + q0 + tid)*24 + h*6;
#pragma unroll
            for (int c = 0; c < 6; c++) Qs[c*QS_S + tid] = wr[c];
            Qs[6*QS_S + tid] = 0.f; Qs[7*QS_S + tid] = 0.f;
        }
        if (tid < BK) { Ks[6*KS_S + tid] = 0.f; Ks[7*KS_S + tid] = 0.f; }
    } else {
        const float* Qg = Qb + (size_t)(b*SEQ + q0)*STD_DIM + hh*D_K;
#pragma unroll
        for (int p = 0; p < 8; p++) {
            int row = p*16 + (tid >> 4);
            int d4  = (tid & 15)*4;
            float4 v = *(const float4*)(Qg + (size_t)row*STD_DIM + d4);
            Qs[(d4+0)*QS_S + row] = v.x;
            Qs[(d4+1)*QS_S + row] = v.y;
            Qs[(d4+2)*QS_S + row] = v.z;
            Qs[(d4+3)*QS_S + row] = v.w;
        }
    }

    float m[8], l[8], acc[8][4];
#pragma unroll
    for (int r = 0; r < 8; r++) {
        m[r] = -INFINITY; l[r] = 0.f;
#pragma unroll
        for (int c = 0; c < 4; c++) acc[r][c] = 0.f;
    }

    const int ntiles = q0/BK + 4;   // keys up to q0+127
    for (int jt = 0; jt < ntiles; jt++) {
        const int j0 = jt * BK;
        __syncthreads();            // protect Ks/Vs/Ps from previous iteration

        // ---- stage K tile (transposed) ----
        if (is_wave) {
            if (tid < BK) {
                const float* wr = wav + (size_t)(b*SEQ + j0 + tid)*24 + h*6;
#pragma unroll
                for (int c = 0; c < 6; c++) Ks[c*KS_S + tid] = wr[c];
            }
        } else {
            const float* Kg = Kb + (size_t)(b*SEQ + j0)*STD_DIM + hh*D_K;
#pragma unroll
            for (int p = 0; p < 2; p++) {
                int row = p*16 + (tid >> 4);
                int d4  = (tid & 15)*4;
                float4 v = *(const float4*)(Kg + (size_t)row*STD_DIM + d4);
                Ks[(d4+0)*KS_S + row] = v.x;
                Ks[(d4+1)*KS_S + row] = v.y;
                Ks[(d4+2)*KS_S + row] = v.z;
                Ks[(d4+3)*KS_S + row] = v.w;
            }
        }
        // ---- stage V tile ----
        {
            const float* Vg = Vb + (size_t)(b*SEQ + j0)*D_MODEL + h*D_K;
#pragma unroll
            for (int p = 0; p < 2; p++) {
                int row = p*16 + (tid >> 4);
                int d4  = (tid & 15)*4;
                *(float4*)(Vs + row*VS_S + d4) =
                    *(const float4*)(Vg + (size_t)row*D_MODEL + d4);
            }
        }
        __syncthreads();

        // ---- scores: 8q x 2k per thread ----
        float s[8][2];
#pragma unroll
        for (int r = 0; r < 8; r++) { s[r][0] = 0.f; s[r][1] = 0.f; }

        const int ndims = is_wave ? 8 : 64;
        for (int d = 0; d < ndims; d++) {
            float4 qa = *(const float4*)(Qs + d*QS_S + ty*8);
            float4 qb_ = *(const float4*)(Qs + d*QS_S + ty*8 + 4);
            float2 kk = *(const float2*)(Ks + d*KS_S + tx*2);
            float qr[8] = {qa.x,qa.y,qa.z,qa.w,qb_.x,qb_.y,qb_.z,qb_.w};
#pragma unroll
            for (int r = 0; r < 8; r++) {
                s[r][0] += qr[r]*kk.x;
                s[r][1] += qr[r]*kk.y;
            }
        }

        // ---- online softmax per row (reduce over 16 tx lanes) ----
#pragma unroll
        for (int r = 0; r < 8; r++) {
            int iglob = q0 + ty*8 + r;
            float s0 = s[r][0]*scale, s1 = s[r][1]*scale;
            if (j0 + tx*2 + 0 > iglob) s0 = -INFINITY;
            if (j0 + tx*2 + 1 > iglob) s1 = -INFINITY;
            float rm = fmaxf(s0, s1);
#pragma unroll
            for (int off = 8; off; off >>= 1)
                rm = fmaxf(rm, __shfl_xor_sync(0xffffffffu, rm, off));
            float mnew = fmaxf(m[r], rm);
            float p0 = __expf(s0 - mnew);
            float p1 = __expf(s1 - mnew);
            float fac = __expf(m[r] - mnew);
            float ps = p0 + p1;
#pragma unroll
            for (int off = 8; off; off >>= 1)
                ps += __shfl_xor_sync(0xffffffffu, ps, off);
            l[r] = l[r]*fac + ps;
            m[r] = mnew;
            Ps[(tx*2+0)*PS_S + ty*8 + r] = p0;
            Ps[(tx*2+1)*PS_S + ty*8 + r] = p1;
#pragma unroll
            for (int c = 0; c < 4; c++) acc[r][c] *= fac;
        }
        __syncthreads();

        // ---- PV: 8q x 4d per thread ----
#pragma unroll
        for (int j = 0; j < BK; j++) {
            float4 pa = *(const float4*)(Ps + j*PS_S + ty*8);
            float4 pb = *(const float4*)(Ps + j*PS_S + ty*8 + 4);
            float4 vv = *(const float4*)(Vs + j*VS_S + tx*4);
            float pr[8] = {pa.x,pa.y,pa.z,pa.w,pb.x,pb.y,pb.z,pb.w};
#pragma unroll
            for (int r = 0; r < 8; r++) {
                acc[r][0] += pr[r]*vv.x;
                acc[r][1] += pr[r]*vv.y;
                acc[r][2] += pr[r]*vv.z;
                acc[r][3] += pr[r]*vv.w;
            }
        }
    }

    // ---- epilogue ----
#pragma unroll
    for (int r = 0; r < 8; r++) {
        float inv = 1.f / l[r];
        float4 o = make_float4(acc[r][0]*inv, acc[r][1]*inv,
                               acc[r][2]*inv, acc[r][3]*inv);
        *(float4*)(Ab + (size_t)(b*SEQ + q0 + ty*8 + r)*D_MODEL + h*D_K + tx*4) = o;
    }
}

// ---------------------------------------------------------------------------
extern "C" void kernel_launch(void* const* d_in, const int* in_sizes, int n_in,
                              void* d_out, int out_size)
{
    const float* x   = (const float*)d_in[0];
    const float* wav = (const float*)d_in[1];
    // d_in[2] = causal_mask (implicit lower-triangular; unused)
    const float* Wq  = (const float*)d_in[3];
    const float* bq  = (const float*)d_in[4];
    const float* Wk  = (const float*)d_in[5];
    const float* bk  = (const float*)d_in[6];
    const float* Wv  = (const float*)d_in[7];
    const float* bv  = (const float*)d_in[8];
    const float* Wo  = (const float*)d_in[9];
    const float* bo  = (const float*)d_in[10];
    float* out = (float*)d_out;

    float *gQ, *gK, *gV, *gA;
    cudaGetSymbolAddress((void**)&gQ, g_Q);
    cudaGetSymbolAddress((void**)&gK, g_K);
    cudaGetSymbolAddress((void**)&gV, g_V);
    cudaGetSymbolAddress((void**)&gA, g_A);

    cudaFuncSetAttribute(attn_kernel,
        cudaFuncAttributeMaxDynamicSharedMemorySize, ATTN_SMEM_BYTES);

    // Fused Q/K/V projections (tf32 tensor cores): N-space 2560 = 20 tiles
    qkv_gemm<<<dim3(20, M_ROWS/128), 256>>>(x, Wq, bq, Wk, bk, Wv, bv, gQ, gK, gV);

    // Fused causal attention (wave + std heads)
    attn_kernel<<<dim3(SEQ/BQ, N_WAVE + N_STD, BATCH), 256, ATTN_SMEM_BYTES>>>(gQ, gK, gV, wav, gA);

    // Output projection -> d_out (tf32 tensor cores)
    o_gemm<<<dim3(D_MODEL/128, M_ROWS/128), 256>>>(gA, Wo, bo, out);
}

// round 7
// speedup vs baseline: 4.0470x; 1.5324x over previous
#include <cuda_runtime.h>
#include <math.h>

#define D_MODEL 1024
#define N_STD   12
#define N_WAVE  4
#define D_K     64
#define STD_DIM 768
#define SEQ     1024
#define BATCH   4
#define M_ROWS  (BATCH*SEQ)   // 4096

#define BQ 128
#define BK 32

// attn smem strides (uints)
#define QS2 68     // Qs [128 rows][k]   : frag bank = 4g+q (68%32==4)
#define KS2 40     // Ks [64 k][keys]    : frag bank = 8q+g (40%32==8)
#define VS2 72     // Vs [32 k][dims]    : frag bank = 8q+g (72%32==8)
#define PS2 36     // Ps per-warp [16][k]: frag bank = 4g+q (36%32==4)
#define ATTN_SMEM_BYTES ((128*QS2 + 64*KS2 + 32*VS2 + 8*16*PS2)*4)  // 72704

// tf32 GEMM tiling
#define GBK  16
#define AS_S 20
#define BS_S 136

// Scratch (allocation-free rule: __device__ globals). tf32 bit patterns.
__device__ unsigned g_Xt [M_ROWS*D_MODEL];
__device__ unsigned g_Wqt[D_MODEL*STD_DIM];
__device__ unsigned g_Wkt[D_MODEL*STD_DIM];
__device__ unsigned g_Wvt[D_MODEL*D_MODEL];
__device__ unsigned g_Wot[D_MODEL*D_MODEL];
__device__ unsigned g_Q  [M_ROWS*STD_DIM];
__device__ unsigned g_K  [M_ROWS*STD_DIM];
__device__ unsigned g_V  [M_ROWS*D_MODEL];
__device__ unsigned g_A  [M_ROWS*D_MODEL];

__device__ __forceinline__ unsigned f2tf32(float f) {
    unsigned r;
    asm("cvt.rna.tf32.f32 %0, %1;" : "=r"(r) : "f"(f));
    return r;
}

__device__ __forceinline__ void mma_tf32(float c[4],
    unsigned a0, unsigned a1, unsigned a2, unsigned a3,
    unsigned b0, unsigned b1)
{
    asm volatile(
        "mma.sync.aligned.m16n8k8.row.col.f32.tf32.tf32.f32 "
        "{%0,%1,%2,%3}, {%4,%5,%6,%7}, {%8,%9}, {%0,%1,%2,%3};"
        : "+f"(c[0]), "+f"(c[1]), "+f"(c[2]), "+f"(c[3])
        : "r"(a0), "r"(a1), "r"(a2), "r"(a3), "r"(b0), "r"(b1));
}

// ---------------------------------------------------------------------------
// fp32 -> tf32-bits bulk convert (bandwidth-bound, runs once per graph replay)
// ---------------------------------------------------------------------------
__global__ __launch_bounds__(256) void cvt_tf32(
    const float4* __restrict__ src, uint4* __restrict__ dst, int n4)
{
    int i = blockIdx.x * blockDim.x + threadIdx.x;
    if (i < n4) {
        float4 v = src[i];
        dst[i] = make_uint4(f2tf32(v.x), f2tf32(v.y), f2tf32(v.z), f2tf32(v.w));
    }
}

// ---------------------------------------------------------------------------
// TF32 GEMM core, pre-converted operands: 128x128 tile, BK=16, double-buffered,
// 256 threads = 2(m) x 4(n) warps; warp tile 64x32 = 4x4 m16n8k8 fragments.
// OUT_TF32: store C as tf32 bit patterns (for downstream mma consumers).
// ---------------------------------------------------------------------------
template<bool OUT_TF32>
__device__ __forceinline__ void tf32gemm128_core(
    const unsigned* __restrict__ A, const unsigned* __restrict__ W,
    const float* __restrict__ bias, void* __restrict__ Cv,
    int K, int ldw, int bm, int bn)
{
    __shared__ unsigned As[2][128][AS_S];   // [m][k]
    __shared__ unsigned Bs[2][GBK][BS_S];   // [k][n]

    const int tid  = threadIdx.x;
    const int lane = tid & 31;
    const int wid  = tid >> 5;
    const int warp_m = wid >> 2;
    const int warp_n = wid & 3;
    const int g = lane >> 2;
    const int q = lane & 3;

    const int ar0 = tid >> 2,         akc0 = (tid & 3) * 4;
    const int ar1 = (tid + 256) >> 2,  akc1 = ((tid + 256) & 3) * 4;
    const int bk0 = tid >> 5,         bnc0 = (tid & 31) * 4;
    const int bk1 = (tid + 256) >> 5,  bnc1 = ((tid + 256) & 31) * 4;

    const unsigned* Ap0 = A + (size_t)(bm + ar0) * K + akc0;
    const unsigned* Ap1 = A + (size_t)(bm + ar1) * K + akc1;
    const unsigned* Wp0 = W + (size_t)bk0 * ldw + bn + bnc0;
    const unsigned* Wp1 = W + (size_t)bk1 * ldw + bn + bnc1;

    *(uint4*)&As[0][ar0][akc0] = *(const uint4*)Ap0;
    *(uint4*)&As[0][ar1][akc1] = *(const uint4*)Ap1;
    *(uint4*)&Bs[0][bk0][bnc0] = *(const uint4*)Wp0;
    *(uint4*)&Bs[0][bk1][bnc1] = *(const uint4*)Wp1;
    __syncthreads();

    float acc[4][4][4];
#pragma unroll
    for (int mt = 0; mt < 4; mt++)
#pragma unroll
        for (int nt = 0; nt < 4; nt++)
#pragma unroll
            for (int i = 0; i < 4; i++) acc[mt][nt][i] = 0.f;

    int buf = 0;
    for (int k0 = GBK; k0 <= K; k0 += GBK) {
        uint4 na0, na1, nb0, nb1;
        const bool more = (k0 < K);
        if (more) {
            na0 = *(const uint4*)(Ap0 + k0);
            na1 = *(const uint4*)(Ap1 + k0);
            nb0 = *(const uint4*)(Wp0 + (size_t)k0 * ldw);
            nb1 = *(const uint4*)(Wp1 + (size_t)k0 * ldw);
        }

#pragma unroll
        for (int ks = 0; ks < 2; ks++) {
            const int k8 = ks * 8;
            unsigned a[4][4], b[4][2];
#pragma unroll
            for (int mt = 0; mt < 4; mt++) {
                int r = warp_m*64 + mt*16 + g;
                a[mt][0] = As[buf][r    ][k8 + q];
                a[mt][1] = As[buf][r + 8][k8 + q];
                a[mt][2] = As[buf][r    ][k8 + q + 4];
                a[mt][3] = As[buf][r + 8][k8 + q + 4];
            }
#pragma unroll
            for (int nt = 0; nt < 4; nt++) {
                int c = warp_n*32 + nt*8 + g;
                b[nt][0] = Bs[buf][k8 + q    ][c];
                b[nt][1] = Bs[buf][k8 + q + 4][c];
            }
#pragma unroll
            for (int mt = 0; mt < 4; mt++)
#pragma unroll
                for (int nt = 0; nt < 4; nt++)
                    mma_tf32(acc[mt][nt],
                             a[mt][0], a[mt][1], a[mt][2], a[mt][3],
                             b[nt][0], b[nt][1]);
        }

        if (more) {
            buf ^= 1;
            *(uint4*)&As[buf][ar0][akc0] = na0;
            *(uint4*)&As[buf][ar1][akc1] = na1;
            *(uint4*)&Bs[buf][bk0][bnc0] = nb0;
            *(uint4*)&Bs[buf][bk1][bnc1] = nb1;
            __syncthreads();
        }
    }

#pragma unroll
    for (int mt = 0; mt < 4; mt++) {
        int r0 = bm + warp_m*64 + mt*16 + g;
#pragma unroll
        for (int nt = 0; nt < 4; nt++) {
            int col = bn + warp_n*32 + nt*8 + 2*q;
            float2 bb = *(const float2*)&bias[col];
            float v00 = acc[mt][nt][0] + bb.x, v01 = acc[mt][nt][1] + bb.y;
            float v10 = acc[mt][nt][2] + bb.x, v11 = acc[mt][nt][3] + bb.y;
            if (OUT_TF32) {
                unsigned* C = (unsigned*)Cv;
                *(uint2*)&C[(size_t)r0     * ldw + col] = make_uint2(f2tf32(v00), f2tf32(v01));
                *(uint2*)&C[(size_t)(r0+8) * ldw + col] = make_uint2(f2tf32(v10), f2tf32(v11));
            } else {
                float* C = (float*)Cv;
                *(float2*)&C[(size_t)r0     * ldw + col] = make_float2(v00, v01);
                *(float2*)&C[(size_t)(r0+8) * ldw + col] = make_float2(v10, v11);
            }
        }
    }
}

// Fused Q/K/V projection: N-space = [Q 768 | K 768 | V 1024], grid.x = 20
__global__ __launch_bounds__(256) void qkv_gemm(
    const unsigned* __restrict__ x,
    const unsigned* __restrict__ Wq, const float* __restrict__ bq,
    const unsigned* __restrict__ Wk, const float* __restrict__ bk_,
    const unsigned* __restrict__ Wv, const float* __restrict__ bv_,
    unsigned* __restrict__ gQ, unsigned* __restrict__ gK, unsigned* __restrict__ gV)
{
    const int bn_g = blockIdx.x * 128;
    const int bm   = blockIdx.y * 128;
    const unsigned* W; const float* bias; unsigned* C; int ldw, bn;
    if (bn_g < 768)       { W = Wq; bias = bq;  C = gQ; ldw = 768;  bn = bn_g; }
    else if (bn_g < 1536) { W = Wk; bias = bk_; C = gK; ldw = 768;  bn = bn_g - 768; }
    else                  { W = Wv; bias = bv_; C = gV; ldw = 1024; bn = bn_g - 1536; }
    tf32gemm128_core<true>(x, W, bias, C, D_MODEL, ldw, bm, bn);
}

// O projection (fp32 output to d_out)
__global__ __launch_bounds__(256) void o_gemm(
    const unsigned* __restrict__ A, const unsigned* __restrict__ W,
    const float* __restrict__ bias, float* __restrict__ C)
{
    tf32gemm128_core<false>(A, W, bias, C, D_MODEL, D_MODEL, blockIdx.y*128, blockIdx.x*128);
}

// ---------------------------------------------------------------------------
// Tensor-core causal flash attention. Block = 128 q rows x one (head,batch);
// 8 warps, warp w owns rows w*16..w*16+15. 32-key tiles.
// Scores: per warp 1x4 m16n8k8 frags over d (8 k-steps std / 1 wave).
// Softmax on mma C-layout (quad shuffles). P -> per-warp smem -> A-frags.
// PV: 4 k-steps x 8 n-frags, O accumulates in registers (C-layout).
// ---------------------------------------------------------------------------
__global__ __launch_bounds__(256, 2) void attn_kernel(
    const unsigned* __restrict__ Qb, const unsigned* __restrict__ Kb,
    const unsigned* __restrict__ Vb, const float* __restrict__ wav,
    unsigned* __restrict__ Ab)
{
    extern __shared__ unsigned sm_u[];
    unsigned* Qs = sm_u;               // [128][QS2]
    unsigned* Ks = Qs + 128*QS2;       // [64][KS2]  (k-dim major)
    unsigned* Vs = Ks + 64*KS2;        // [32][VS2]  (key major)
    unsigned* Ps = Vs + 32*VS2;        // 8 x [16][PS2]

    const int b = blockIdx.z, h = blockIdx.y;
    const int q0 = (gridDim.x - 1 - blockIdx.x) * BQ;   // heavy blocks first
    const int tid = threadIdx.x;
    const int warp = tid >> 5, lane = tid & 31;
    const int g = lane >> 2, q = lane & 3;
    const bool is_wave = (h < N_WAVE);
    const float scale = is_wave ? 0.4082482904638631f : 0.125f;
    const int hh = h - N_WAVE;
    const int wr0 = warp * 16;

    // ---- stage Q (once) ----
    if (is_wave) {
        if (tid < 128) {
            const float* wr = wav + (size_t)(b*SEQ + q0 + tid)*24 + h*6;
            unsigned* qrow = Qs + tid*QS2;
#pragma unroll
            for (int c = 0; c < 6; c++) qrow[c] = f2tf32(wr[c]);
            qrow[6] = 0u; qrow[7] = 0u;
        }
    } else {
        const unsigned* Qg = Qb + (size_t)(b*SEQ + q0)*STD_DIM + hh*D_K;
#pragma unroll
        for (int p = 0; p < 8; p++) {
            int idx = tid + p*256;
            int row = idx >> 4, c4 = (idx & 15)*4;
            *(uint4*)(Qs + row*QS2 + c4) = *(const uint4*)(Qg + (size_t)row*STD_DIM + c4);
        }
    }

    float m0 = -1e30f, m1 = -1e30f, l0 = 0.f, l1 = 0.f;
    float o[8][4];
#pragma unroll
    for (int nt = 0; nt < 8; nt++)
#pragma unroll
        for (int i = 0; i < 4; i++) o[nt][i] = 0.f;

    const int ntiles = q0/BK + 4;
    for (int jt = 0; jt < ntiles; jt++) {
        const int j0 = jt * BK;
        __syncthreads();                       // Ks/Vs reuse barrier

        // ---- stage K tile (k-major, transposed) ----
        if (is_wave) {
            if (tid < 32) {
                const float* wr = wav + (size_t)(b*SEQ + j0 + tid)*24 + h*6;
#pragma unroll
                for (int c = 0; c < 6; c++) Ks[c*KS2 + tid] = f2tf32(wr[c]);
                Ks[6*KS2 + tid] = 0u; Ks[7*KS2 + tid] = 0u;
            }
        } else {
#pragma unroll
            for (int p = 0; p < 2; p++) {
                int idx = tid + p*256;
                int key = idx & 31, c4 = (idx >> 5)*4;   // warp-uniform c4: conflict-free STS
                uint4 v = *(const uint4*)(Kb + (size_t)(b*SEQ + j0 + key)*STD_DIM + hh*D_K + c4);
                Ks[(c4+0)*KS2 + key] = v.x;
                Ks[(c4+1)*KS2 + key] = v.y;
                Ks[(c4+2)*KS2 + key] = v.z;
                Ks[(c4+3)*KS2 + key] = v.w;
            }
        }
        // ---- stage V tile ----
#pragma unroll
        for (int p = 0; p < 2; p++) {
            int idx = tid + p*256;
            int key = idx >> 4, c4 = (idx & 15)*4;
            *(uint4*)(Vs + key*VS2 + c4) =
                *(const uint4*)(Vb + (size_t)(b*SEQ + j0 + key)*D_MODEL + h*D_K + c4);
        }
        __syncthreads();

        if (j0 <= q0 + wr0 + 15) {            // warp-uniform causal tile skip
            // ---- scores ----
            float sacc[4][4];
#pragma unroll
            for (int nt = 0; nt < 4; nt++)
#pragma unroll
                for (int i = 0; i < 4; i++) sacc[nt][i] = 0.f;

            const int nd8 = is_wave ? 1 : 8;
            for (int k8 = 0; k8 < nd8; k8++) {
                const int kc = k8*8;
                unsigned a0 = Qs[(wr0+g  )*QS2 + kc + q];
                unsigned a1 = Qs[(wr0+g+8)*QS2 + kc + q];
                unsigned a2 = Qs[(wr0+g  )*QS2 + kc + q + 4];
                unsigned a3 = Qs[(wr0+g+8)*QS2 + kc + q + 4];
#pragma unroll
                for (int nt = 0; nt < 4; nt++) {
                    unsigned b0 = Ks[(kc+q  )*KS2 + nt*8 + g];
                    unsigned b1 = Ks[(kc+q+4)*KS2 + nt*8 + g];
                    mma_tf32(sacc[nt], a0, a1, a2, a3, b0, b1);
                }
            }

            // ---- mask + scale (C-layout: rows g,g+8; cols 2q,2q+1 per nfrag) ----
            const int r0 = q0 + wr0 + g, r1 = r0 + 8;
#pragma unroll
            for (int nt = 0; nt < 4; nt++) {
                int c0 = j0 + nt*8 + 2*q, c1 = c0 + 1;
                sacc[nt][0] = (c0 > r0) ? -1e30f : sacc[nt][0]*scale;
                sacc[nt][1] = (c1 > r0) ? -1e30f : sacc[nt][1]*scale;
                sacc[nt][2] = (c0 > r1) ? -1e30f : sacc[nt][2]*scale;
                sacc[nt][3] = (c1 > r1) ? -1e30f : sacc[nt][3]*scale;
            }

            // ---- online softmax (row stats across the 4-lane quad) ----
            float mx0 = fmaxf(fmaxf(sacc[0][0], sacc[0][1]), fmaxf(sacc[1][0], sacc[1][1]));
            mx0 = fmaxf(mx0, fmaxf(fmaxf(sacc[2][0], sacc[2][1]), fmaxf(sacc[3][0], sacc[3][1])));
            float mx1 = fmaxf(fmaxf(sacc[0][2], sacc[0][3]), fmaxf(sacc[1][2], sacc[1][3]));
            mx1 = fmaxf(mx1, fmaxf(fmaxf(sacc[2][2], sacc[2][3]), fmaxf(sacc[3][2], sacc[3][3])));
            mx0 = fmaxf(mx0, __shfl_xor_sync(0xffffffffu, mx0, 1));
            mx0 = fmaxf(mx0, __shfl_xor_sync(0xffffffffu, mx0, 2));
            mx1 = fmaxf(mx1, __shfl_xor_sync(0xffffffffu, mx1, 1));
            mx1 = fmaxf(mx1, __shfl_xor_sync(0xffffffffu, mx1, 2));

            float mn0 = fmaxf(m0, mx0), mn1 = fmaxf(m1, mx1);
            float fac0 = __expf(m0 - mn0), fac1 = __expf(m1 - mn1);

            unsigned* Pw = Ps + warp*16*PS2;
            float ps0 = 0.f, ps1 = 0.f;
#pragma unroll
            for (int nt = 0; nt < 4; nt++) {
                float p00 = __expf(sacc[nt][0] - mn0);
                float p01 = __expf(sacc[nt][1] - mn0);
                float p10 = __expf(sacc[nt][2] - mn1);
                float p11 = __expf(sacc[nt][3] - mn1);
                ps0 += p00 + p01; ps1 += p10 + p11;
                int cc = nt*8 + 2*q;
                *(uint2*)(Pw + g*PS2 + cc)     = make_uint2(f2tf32(p00), f2tf32(p01));
                *(uint2*)(Pw + (g+8)*PS2 + cc) = make_uint2(f2tf32(p10), f2tf32(p11));
            }
            ps0 += __shfl_xor_sync(0xffffffffu, ps0, 1);
            ps0 += __shfl_xor_sync(0xffffffffu, ps0, 2);
            ps1 += __shfl_xor_sync(0xffffffffu, ps1, 1);
            ps1 += __shfl_xor_sync(0xffffffffu, ps1, 2);

            l0 = l0*fac0 + ps0;  l1 = l1*fac1 + ps1;
            m0 = mn0;            m1 = mn1;
#pragma unroll
            for (int nt = 0; nt < 8; nt++) {
                o[nt][0] *= fac0; o[nt][1] *= fac0;
                o[nt][2] *= fac1; o[nt][3] *= fac1;
            }
            __syncwarp();

            // ---- PV: O += P(16x32) @ V(32x64) ----
#pragma unroll
            for (int k8 = 0; k8 < 4; k8++) {
                const int kc = k8*8;
                unsigned a0 = Pw[(g  )*PS2 + kc + q];
                unsigned a1 = Pw[(g+8)*PS2 + kc + q];
                unsigned a2 = Pw[(g  )*PS2 + kc + q + 4];
                unsigned a3 = Pw[(g+8)*PS2 + kc + q + 4];
#pragma unroll
                for (int nt = 0; nt < 8; nt++) {
                    unsigned b0 = Vs[(kc+q  )*VS2 + nt*8 + g];
                    unsigned b1 = Vs[(kc+q+4)*VS2 + nt*8 + g];
                    mma_tf32(o[nt], a0, a1, a2, a3, b0, b1);
                }
            }
            __syncwarp();                      // Ps reuse within warp next iter
        }
    }

    // ---- epilogue: write tf32 bits for the O-projection mma ----
    float inv0 = 1.f / l0, inv1 = 1.f / l1;
    unsigned* A0 = Ab + (size_t)(b*SEQ + q0 + wr0 + g)*D_MODEL + h*D_K;
    unsigned* A1 = A0 + 8*D_MODEL;
#pragma unroll
    for (int nt = 0; nt < 8; nt++) {
        int cc = nt*8 + 2*q;
        *(uint2*)(A0 + cc) = make_uint2(f2tf32(o[nt][0]*inv0), f2tf32(o[nt][1]*inv0));
        *(uint2*)(A1 + cc) = make_uint2(f2tf32(o[nt][2]*inv1), f2tf32(o[nt][3]*inv1));
    }
}

// ---------------------------------------------------------------------------
extern "C" void kernel_launch(void* const* d_in, const int* in_sizes, int n_in,
                              void* d_out, int out_size)
{
    const float* x   = (const float*)d_in[0];
    const float* wav = (const float*)d_in[1];
    // d_in[2] = causal_mask (implicit lower-triangular; unused)
    const float* Wq  = (const float*)d_in[3];
    const float* bq  = (const float*)d_in[4];
    const float* Wk  = (const float*)d_in[5];
    const float* bk  = (const float*)d_in[6];
    const float* Wv  = (const float*)d_in[7];
    const float* bv  = (const float*)d_in[8];
    const float* Wo  = (const float*)d_in[9];
    const float* bo  = (const float*)d_in[10];
    float* out = (float*)d_out;

    unsigned *gXt, *gWqt, *gWkt, *gWvt, *gWot, *gQ, *gK, *gV, *gA;
    cudaGetSymbolAddress((void**)&gXt,  g_Xt);
    cudaGetSymbolAddress((void**)&gWqt, g_Wqt);
    cudaGetSymbolAddress((void**)&gWkt, g_Wkt);
    cudaGetSymbolAddress((void**)&gWvt, g_Wvt);
    cudaGetSymbolAddress((void**)&gWot, g_Wot);
    cudaGetSymbolAddress((void**)&gQ,   g_Q);
    cudaGetSymbolAddress((void**)&gK,   g_K);
    cudaGetSymbolAddress((void**)&gV,   g_V);
    cudaGetSymbolAddress((void**)&gA,   g_A);

    cudaFuncSetAttribute(attn_kernel,
        cudaFuncAttributeMaxDynamicSharedMemorySize, ATTN_SMEM_BYTES);

    // Pre-convert activations + weights to tf32 bit patterns (hot loops stay cvt-free)
    {
        int n4;
        n4 = M_ROWS*D_MODEL/4;  cvt_tf32<<<n4/256, 256>>>((const float4*)x,  (uint4*)gXt,  n4);
        n4 = D_MODEL*STD_DIM/4; cvt_tf32<<<n4/256, 256>>>((const float4*)Wq, (uint4*)gWqt, n4);
        n4 = D_MODEL*STD_DIM/4; cvt_tf32<<<n4/256, 256>>>((const float4*)Wk, (uint4*)gWkt, n4);
        n4 = D_MODEL*D_MODEL/4; cvt_tf32<<<n4/256, 256>>>((const float4*)Wv, (uint4*)gWvt, n4);
        n4 = D_MODEL*D_MODEL/4; cvt_tf32<<<n4/256, 256>>>((const float4*)Wo, (uint4*)gWot, n4);
    }

    // Fused Q/K/V projections (tensor cores, tf32 in/out)
    qkv_gemm<<<dim3(20, M_ROWS/128), 256>>>(gXt, gWqt, bq, gWkt, bk, gWvt, bv, gQ, gK, gV);

    // Tensor-core causal attention (wave + std heads) -> gA (tf32 bits)
    attn_kernel<<<dim3(SEQ/BQ, N_WAVE + N_STD, BATCH), 256, ATTN_SMEM_BYTES>>>(gQ, gK, gV, wav, gA);

    // Output projection -> d_out (fp32)
    o_gemm<<<dim3(D_MODEL/128, M_ROWS/128), 256>>>(gA, gWot, bo, out);
}

// round 8
// speedup vs baseline: 4.1944x; 1.0364x over previous
#include <cuda_runtime.h>
#include <math.h>

#define D_MODEL 1024
#define N_STD   12
#define N_WAVE  4
#define D_K     64
#define STD_DIM 768
#define SEQ     1024
#define BATCH   4
#define M_ROWS  (BATCH*SEQ)   // 4096

#define BQ 128
#define BK 32

// attn smem strides (uints)
#define QS2 68
#define KS2 40
#define VS2 72
#define PS2 36
#define ATTN_SMEM_BYTES ((128*QS2 + 64*KS2 + 32*VS2 + 8*16*PS2)*4)  // 72704

// tf32 GEMM tiling
#define GBK  16
#define AS_S 20
#define BS_S 136
#define GSTG 3
#define AS_STAGE (128*AS_S)   // 2560 uints
#define BS_STAGE (GBK*BS_S)   // 2176 uints
#define GEMM_SMEM_BYTES ((GSTG*(AS_STAGE + BS_STAGE))*4)   // 56832

// Scratch (allocation-free rule: __device__ globals). tf32 bit patterns.
__device__ unsigned g_Xt [M_ROWS*D_MODEL];
__device__ unsigned g_Wqt[D_MODEL*STD_DIM];
__device__ unsigned g_Wkt[D_MODEL*STD_DIM];
__device__ unsigned g_Wvt[D_MODEL*D_MODEL];
__device__ unsigned g_Wot[D_MODEL*D_MODEL];
__device__ unsigned g_Q  [M_ROWS*STD_DIM];
__device__ unsigned g_K  [M_ROWS*STD_DIM];
__device__ unsigned g_V  [M_ROWS*D_MODEL];
__device__ unsigned g_A  [M_ROWS*D_MODEL];

__device__ __forceinline__ unsigned f2tf32(float f) {
    unsigned r;
    asm("cvt.rna.tf32.f32 %0, %1;" : "=r"(r) : "f"(f));
    return r;
}

__device__ __forceinline__ void mma_tf32(float c[4],
    unsigned a0, unsigned a1, unsigned a2, unsigned a3,
    unsigned b0, unsigned b1)
{
    asm volatile(
        "mma.sync.aligned.m16n8k8.row.col.f32.tf32.tf32.f32 "
        "{%0,%1,%2,%3}, {%4,%5,%6,%7}, {%8,%9}, {%0,%1,%2,%3};"
        : "+f"(c[0]), "+f"(c[1]), "+f"(c[2]), "+f"(c[3])
        : "r"(a0), "r"(a1), "r"(a2), "r"(a3), "r"(b0), "r"(b1));
}

__device__ __forceinline__ void cp16(unsigned* smem_dst, const void* gsrc) {
    unsigned s = (unsigned)__cvta_generic_to_shared(smem_dst);
    asm volatile("cp.async.cg.shared.global [%0], [%1], 16;\n" :: "r"(s), "l"(gsrc));
}
#define CP_COMMIT() asm volatile("cp.async.commit_group;\n")
#define CP_WAIT1()  asm volatile("cp.async.wait_group 1;\n")
#define CP_WAIT0()  asm volatile("cp.async.wait_group 0;\n")

// ---------------------------------------------------------------------------
// Fused fp32 -> tf32-bits bulk convert for all 5 tensors (one launch).
// grid.y selects the segment; excess blocks exit on the bounds check.
// ---------------------------------------------------------------------------
__global__ __launch_bounds__(256) void cvt_all(
    const float4* __restrict__ x,  uint4* __restrict__ xt,
    const float4* __restrict__ wq, uint4* __restrict__ wqt,
    const float4* __restrict__ wk, uint4* __restrict__ wkt,
    const float4* __restrict__ wv, uint4* __restrict__ wvt,
    const float4* __restrict__ wo, uint4* __restrict__ wot)
{
    const float4* s; uint4* d; int n4;
    switch (blockIdx.y) {
        case 0: s = x;  d = xt;  n4 = M_ROWS*D_MODEL/4;  break;
        case 1: s = wq; d = wqt; n4 = D_MODEL*STD_DIM/4; break;
        case 2: s = wk; d = wkt; n4 = D_MODEL*STD_DIM/4; break;
        case 3: s = wv; d = wvt; n4 = D_MODEL*D_MODEL/4; break;
        default:s = wo; d = wot; n4 = D_MODEL*D_MODEL/4; break;
    }
    int i = blockIdx.x * 256 + threadIdx.x;
    if (i < n4) {
        float4 v = s[i];
        d[i] = make_uint4(f2tf32(v.x), f2tf32(v.y), f2tf32(v.z), f2tf32(v.w));
    }
}

// ---------------------------------------------------------------------------
// TF32 GEMM core, cp.async 3-stage pipeline: 128x128 tile, BK=16,
// 256 threads = 2(m) x 4(n) warps; warp tile 64x32 = 4x4 m16n8k8 fragments.
// ---------------------------------------------------------------------------
template<bool OUT_TF32>
__device__ __forceinline__ void tf32gemm128_core(
    const unsigned* __restrict__ A, const unsigned* __restrict__ W,
    const float* __restrict__ bias, void* __restrict__ Cv,
    int K, int ldw, int bm, int bn)
{
    extern __shared__ unsigned gsm[];
    unsigned* AsB = gsm;                    // 3 stages of [128][AS_S]
    unsigned* BsB = gsm + GSTG*AS_STAGE;    // 3 stages of [GBK][BS_S]

    const int tid  = threadIdx.x;
    const int lane = tid & 31;
    const int wid  = tid >> 5;
    const int warp_m = wid >> 2;
    const int warp_n = wid & 3;
    const int g = lane >> 2;
    const int q = lane & 3;

    const int ar0 = tid >> 2,          akc0 = (tid & 3) * 4;
    const int ar1 = (tid + 256) >> 2,  akc1 = ((tid + 256) & 3) * 4;
    const int bk0 = tid >> 5,          bnc0 = (tid & 31) * 4;
    const int bk1 = (tid + 256) >> 5,  bnc1 = ((tid + 256) & 31) * 4;

    const unsigned* Ap0 = A + (size_t)(bm + ar0) * K + akc0;
    const unsigned* Ap1 = A + (size_t)(bm + ar1) * K + akc1;
    const unsigned* Wp0 = W + (size_t)bk0 * ldw + bn + bnc0;
    const unsigned* Wp1 = W + (size_t)bk1 * ldw + bn + bnc1;

    // issue one stage's 4 cp.async per thread
    auto issue = [&](int s, int k0) {
        unsigned* As = AsB + s*AS_STAGE;
        unsigned* Bs = BsB + s*BS_STAGE;
        cp16(As + ar0*AS_S + akc0, Ap0 + k0);
        cp16(As + ar1*AS_S + akc1, Ap1 + k0);
        cp16(Bs + bk0*BS_S + bnc0, Wp0 + (size_t)k0 * ldw);
        cp16(Bs + bk1*BS_S + bnc1, Wp1 + (size_t)k0 * ldw);
    };

    issue(0, 0);  CP_COMMIT();
    issue(1, GBK); CP_COMMIT();
    CP_WAIT1();                 // stage 0 resident
    __syncthreads();

    float acc[4][4][4];
#pragma unroll
    for (int mt = 0; mt < 4; mt++)
#pragma unroll
        for (int nt = 0; nt < 4; nt++)
#pragma unroll
            for (int i = 0; i < 4; i++) acc[mt][nt][i] = 0.f;

    for (int k0 = 0; k0 < K; k0 += GBK) {
        const int nxt = k0 + 2*GBK;
        if (nxt < K) issue((nxt >> 4) % GSTG, nxt);
        CP_COMMIT();            // (possibly empty) group keeps the ring count

        const unsigned* As = AsB + ((k0 >> 4) % GSTG)*AS_STAGE;
        const unsigned* Bs = BsB + ((k0 >> 4) % GSTG)*BS_STAGE;

#pragma unroll
        for (int ks = 0; ks < 2; ks++) {
            const int k8 = ks * 8;
            unsigned a[4][4], b[4][2];
#pragma unroll
            for (int mt = 0; mt < 4; mt++) {
                int r = warp_m*64 + mt*16 + g;
                a[mt][0] = As[(r    )*AS_S + k8 + q];
                a[mt][1] = As[(r + 8)*AS_S + k8 + q];
                a[mt][2] = As[(r    )*AS_S + k8 + q + 4];
                a[mt][3] = As[(r + 8)*AS_S + k8 + q + 4];
            }
#pragma unroll
            for (int nt = 0; nt < 4; nt++) {
                int c = warp_n*32 + nt*8 + g;
                b[nt][0] = Bs[(k8 + q    )*BS_S + c];
                b[nt][1] = Bs[(k8 + q + 4)*BS_S + c];
            }
#pragma unroll
            for (int mt = 0; mt < 4; mt++)
#pragma unroll
                for (int nt = 0; nt < 4; nt++)
                    mma_tf32(acc[mt][nt],
                             a[mt][0], a[mt][1], a[mt][2], a[mt][3],
                             b[nt][0], b[nt][1]);
        }

        if (k0 + GBK < K) {
            CP_WAIT1();         // next stage resident
            __syncthreads();
        }
    }

#pragma unroll
    for (int mt = 0; mt < 4; mt++) {
        int r0 = bm + warp_m*64 + mt*16 + g;
#pragma unroll
        for (int nt = 0; nt < 4; nt++) {
            int col = bn + warp_n*32 + nt*8 + 2*q;
            float2 bb = *(const float2*)&bias[col];
            float v00 = acc[mt][nt][0] + bb.x, v01 = acc[mt][nt][1] + bb.y;
            float v10 = acc[mt][nt][2] + bb.x, v11 = acc[mt][nt][3] + bb.y;
            if (OUT_TF32) {
                unsigned* C = (unsigned*)Cv;
                *(uint2*)&C[(size_t)r0     * ldw + col] = make_uint2(f2tf32(v00), f2tf32(v01));
                *(uint2*)&C[(size_t)(r0+8) * ldw + col] = make_uint2(f2tf32(v10), f2tf32(v11));
            } else {
                float* C = (float*)Cv;
                *(float2*)&C[(size_t)r0     * ldw + col] = make_float2(v00, v01);
                *(float2*)&C[(size_t)(r0+8) * ldw + col] = make_float2(v10, v11);
            }
        }
    }
}

// Fused Q/K/V projection: N-space = [Q 768 | K 768 | V 1024], grid.x = 20
__global__ __launch_bounds__(256) void qkv_gemm(
    const unsigned* __restrict__ x,
    const unsigned* __restrict__ Wq, const float* __restrict__ bq,
    const unsigned* __restrict__ Wk, const float* __restrict__ bk_,
    const unsigned* __restrict__ Wv, const float* __restrict__ bv_,
    unsigned* __restrict__ gQ, unsigned* __restrict__ gK, unsigned* __restrict__ gV)
{
    const int bn_g = blockIdx.x * 128;
    const int bm   = blockIdx.y * 128;
    const unsigned* W; const float* bias; unsigned* C; int ldw, bn;
    if (bn_g < 768)       { W = Wq; bias = bq;  C = gQ; ldw = 768;  bn = bn_g; }
    else if (bn_g < 1536) { W = Wk; bias = bk_; C = gK; ldw = 768;  bn = bn_g - 768; }
    else                  { W = Wv; bias = bv_; C = gV; ldw = 1024; bn = bn_g - 1536; }
    tf32gemm128_core<true>(x, W, bias, C, D_MODEL, ldw, bm, bn);
}

// O projection (fp32 output to d_out)
__global__ __launch_bounds__(256) void o_gemm(
    const unsigned* __restrict__ A, const unsigned* __restrict__ W,
    const float* __restrict__ bias, float* __restrict__ C)
{
    tf32gemm128_core<false>(A, W, bias, C, D_MODEL, D_MODEL, blockIdx.y*128, blockIdx.x*128);
}

// ---------------------------------------------------------------------------
// Tensor-core causal flash attention (structure as R7; V tile via cp.async).
// ---------------------------------------------------------------------------
__global__ __launch_bounds__(256, 2) void attn_kernel(
    const unsigned* __restrict__ Qb, const unsigned* __restrict__ Kb,
    const unsigned* __restrict__ Vb, const float* __restrict__ wav,
    unsigned* __restrict__ Ab)
{
    extern __shared__ unsigned sm_u[];
    unsigned* Qs = sm_u;               // [128][QS2]
    unsigned* Ks = Qs + 128*QS2;       // [64][KS2]  (k-dim major)
    unsigned* Vs = Ks + 64*KS2;        // [32][VS2]  (key major)
    unsigned* Ps = Vs + 32*VS2;        // 8 x [16][PS2]

    const int b = blockIdx.z, h = blockIdx.y;
    const int q0 = (gridDim.x - 1 - blockIdx.x) * BQ;
    const int tid = threadIdx.x;
    const int warp = tid >> 5, lane = tid & 31;
    const int g = lane >> 2, q = lane & 3;
    const bool is_wave = (h < N_WAVE);
    const float scale = is_wave ? 0.4082482904638631f : 0.125f;
    const int hh = h - N_WAVE;
    const int wr0 = warp * 16;

    // ---- stage Q (once) ----
    if (is_wave) {
        if (tid < 128) {
            const float* wr = wav + (size_t)(b*SEQ + q0 + tid)*24 + h*6;
            unsigned* qrow = Qs + tid*QS2;
#pragma unroll
            for (int c = 0; c < 6; c++) qrow[c] = f2tf32(wr[c]);
            qrow[6] = 0u; qrow[7] = 0u;
        }
    } else {
        const unsigned* Qg = Qb + (size_t)(b*SEQ + q0)*STD_DIM + hh*D_K;
#pragma unroll
        for (int p = 0; p < 8; p++) {
            int idx = tid + p*256;
            int row = idx >> 4, c4 = (idx & 15)*4;
            *(uint4*)(Qs + row*QS2 + c4) = *(const uint4*)(Qg + (size_t)row*STD_DIM + c4);
        }
    }

    float m0 = -1e30f, m1 = -1e30f, l0 = 0.f, l1 = 0.f;
    float o[8][4];
#pragma unroll
    for (int nt = 0; nt < 8; nt++)
#pragma unroll
        for (int i = 0; i < 4; i++) o[nt][i] = 0.f;

    const int ntiles = q0/BK + 4;
    for (int jt = 0; jt < ntiles; jt++) {
        const int j0 = jt * BK;
        __syncthreads();

        // ---- stage V tile via cp.async (overlaps with K staging below) ----
#pragma unroll
        for (int p = 0; p < 2; p++) {
            int idx = tid + p*256;
            int key = idx >> 4, c4 = (idx & 15)*4;
            cp16(Vs + key*VS2 + c4,
                 Vb + (size_t)(b*SEQ + j0 + key)*D_MODEL + h*D_K + c4);
        }
        CP_COMMIT();

        // ---- stage K tile (k-major, transposed scatter) ----
        if (is_wave) {
            if (tid < 32) {
                const float* wr = wav + (size_t)(b*SEQ + j0 + tid)*24 + h*6;
#pragma unroll
                for (int c = 0; c < 6; c++) Ks[c*KS2 + tid] = f2tf32(wr[c]);
                Ks[6*KS2 + tid] = 0u; Ks[7*KS2 + tid] = 0u;
            }
        } else {
#pragma unroll
            for (int p = 0; p < 2; p++) {
                int idx = tid + p*256;
                int key = idx & 31, c4 = (idx >> 5)*4;
                uint4 v = *(const uint4*)(Kb + (size_t)(b*SEQ + j0 + key)*STD_DIM + hh*D_K + c4);
                Ks[(c4+0)*KS2 + key] = v.x;
                Ks[(c4+1)*KS2 + key] = v.y;
                Ks[(c4+2)*KS2 + key] = v.z;
                Ks[(c4+3)*KS2 + key] = v.w;
            }
        }
        CP_WAIT0();
        __syncthreads();

        if (j0 <= q0 + wr0 + 15) {
            // ---- scores ----
            float sacc[4][4];
#pragma unroll
            for (int nt = 0; nt < 4; nt++)
#pragma unroll
                for (int i = 0; i < 4; i++) sacc[nt][i] = 0.f;

            const int nd8 = is_wave ? 1 : 8;
            for (int k8 = 0; k8 < nd8; k8++) {
                const int kc = k8*8;
                unsigned a0 = Qs[(wr0+g  )*QS2 + kc + q];
                unsigned a1 = Qs[(wr0+g+8)*QS2 + kc + q];
                unsigned a2 = Qs[(wr0+g  )*QS2 + kc + q + 4];
                unsigned a3 = Qs[(wr0+g+8)*QS2 + kc + q + 4];
#pragma unroll
                for (int nt = 0; nt < 4; nt++) {
                    unsigned b0 = Ks[(kc+q  )*KS2 + nt*8 + g];
                    unsigned b1 = Ks[(kc+q+4)*KS2 + nt*8 + g];
                    mma_tf32(sacc[nt], a0, a1, a2, a3, b0, b1);
                }
            }

            // ---- mask + scale ----
            const int r0 = q0 + wr0 + g, r1 = r0 + 8;
#pragma unroll
            for (int nt = 0; nt < 4; nt++) {
                int c0 = j0 + nt*8 + 2*q, c1 = c0 + 1;
                sacc[nt][0] = (c0 > r0) ? -1e30f : sacc[nt][0]*scale;
                sacc[nt][1] = (c1 > r0) ? -1e30f : sacc[nt][1]*scale;
                sacc[nt][2] = (c0 > r1) ? -1e30f : sacc[nt][2]*scale;
                sacc[nt][3] = (c1 > r1) ? -1e30f : sacc[nt][3]*scale;
            }

            // ---- online softmax (quad reductions) ----
            float mx0 = fmaxf(fmaxf(sacc[0][0], sacc[0][1]), fmaxf(sacc[1][0], sacc[1][1]));
            mx0 = fmaxf(mx0, fmaxf(fmaxf(sacc[2][0], sacc[2][1]), fmaxf(sacc[3][0], sacc[3][1])));
            float mx1 = fmaxf(fmaxf(sacc[0][2], sacc[0][3]), fmaxf(sacc[1][2], sacc[1][3]));
            mx1 = fmaxf(mx1, fmaxf(fmaxf(sacc[2][2], sacc[2][3]), fmaxf(sacc[3][2], sacc[3][3])));
            mx0 = fmaxf(mx0, __shfl_xor_sync(0xffffffffu, mx0, 1));
            mx0 = fmaxf(mx0, __shfl_xor_sync(0xffffffffu, mx0, 2));
            mx1 = fmaxf(mx1, __shfl_xor_sync(0xffffffffu, mx1, 1));
            mx1 = fmaxf(mx1, __shfl_xor_sync(0xffffffffu, mx1, 2));

            float mn0 = fmaxf(m0, mx0), mn1 = fmaxf(m1, mx1);
            float fac0 = __expf(m0 - mn0), fac1 = __expf(m1 - mn1);

            unsigned* Pw = Ps + warp*16*PS2;
            float ps0 = 0.f, ps1 = 0.f;
#pragma unroll
            for (int nt = 0; nt < 4; nt++) {
                float p00 = __expf(sacc[nt][0] - mn0);
                float p01 = __expf(sacc[nt][1] - mn0);
                float p10 = __expf(sacc[nt][2] - mn1);
                float p11 = __expf(sacc[nt][3] - mn1);
                ps0 += p00 + p01; ps1 += p10 + p11;
                int cc = nt*8 + 2*q;
                *(uint2*)(Pw + g*PS2 + cc)     = make_uint2(f2tf32(p00), f2tf32(p01));
                *(uint2*)(Pw + (g+8)*PS2 + cc) = make_uint2(f2tf32(p10), f2tf32(p11));
            }
            ps0 += __shfl_xor_sync(0xffffffffu, ps0, 1);
            ps0 += __shfl_xor_sync(0xffffffffu, ps0, 2);
            ps1 += __shfl_xor_sync(0xffffffffu, ps1, 1);
            ps1 += __shfl_xor_sync(0xffffffffu, ps1, 2);

            l0 = l0*fac0 + ps0;  l1 = l1*fac1 + ps1;
            m0 = mn0;            m1 = mn1;
#pragma unroll
            for (int nt = 0; nt < 8; nt++) {
                o[nt][0] *= fac0; o[nt][1] *= fac0;
                o[nt][2] *= fac1; o[nt][3] *= fac1;
            }
            __syncwarp();

            // ---- PV: O += P(16x32) @ V(32x64) ----
#pragma unroll
            for (int k8 = 0; k8 < 4; k8++) {
                const int kc = k8*8;
                unsigned a0 = Pw[(g  )*PS2 + kc + q];
                unsigned a1 = Pw[(g+8)*PS2 + kc + q];
                unsigned a2 = Pw[(g  )*PS2 + kc + q + 4];
                unsigned a3 = Pw[(g+8)*PS2 + kc + q + 4];
#pragma unroll
                for (int nt = 0; nt < 8; nt++) {
                    unsigned b0 = Vs[(kc+q  )*VS2 + nt*8 + g];
                    unsigned b1 = Vs[(kc+q+4)*VS2 + nt*8 + g];
                    mma_tf32(o[nt], a0, a1, a2, a3, b0, b1);
                }
            }
            __syncwarp();
        }
    }

    // ---- epilogue: tf32 bits for the O-projection mma ----
    float inv0 = 1.f / l0, inv1 = 1.f / l1;
    unsigned* A0 = Ab + (size_t)(b*SEQ + q0 + wr0 + g)*D_MODEL + h*D_K;
    unsigned* A1 = A0 + 8*D_MODEL;
#pragma unroll
    for (int nt = 0; nt < 8; nt++) {
        int cc = nt*8 + 2*q;
        *(uint2*)(A0 + cc) = make_uint2(f2tf32(o[nt][0]*inv0), f2tf32(o[nt][1]*inv0));
        *(uint2*)(A1 + cc) = make_uint2(f2tf32(o[nt][2]*inv1), f2tf32(o[nt][3]*inv1));
    }
}

// ---------------------------------------------------------------------------
extern "C" void kernel_launch(void* const* d_in, const int* in_sizes, int n_in,
                              void* d_out, int out_size)
{
    const float* x   = (const float*)d_in[0];
    const float* wav = (const float*)d_in[1];
    const float* Wq  = (const float*)d_in[3];
    const float* bq  = (const float*)d_in[4];
    const float* Wk  = (const float*)d_in[5];
    const float* bk  = (const float*)d_in[6];
    const float* Wv  = (const float*)d_in[7];
    const float* bv  = (const float*)d_in[8];
    const float* Wo  = (const float*)d_in[9];
    const float* bo  = (const float*)d_in[10];
    float* out = (float*)d_out;

    unsigned *gXt, *gWqt, *gWkt, *gWvt, *gWot, *gQ, *gK, *gV, *gA;
    cudaGetSymbolAddress((void**)&gXt,  g_Xt);
    cudaGetSymbolAddress((void**)&gWqt, g_Wqt);
    cudaGetSymbolAddress((void**)&gWkt, g_Wkt);
    cudaGetSymbolAddress((void**)&gWvt, g_Wvt);
    cudaGetSymbolAddress((void**)&gWot, g_Wot);
    cudaGetSymbolAddress((void**)&gQ,   g_Q);
    cudaGetSymbolAddress((void**)&gK,   g_K);
    cudaGetSymbolAddress((void**)&gV,   g_V);
    cudaGetSymbolAddress((void**)&gA,   g_A);

    cudaFuncSetAttribute(attn_kernel,
        cudaFuncAttributeMaxDynamicSharedMemorySize, ATTN_SMEM_BYTES);
    cudaFuncSetAttribute(qkv_gemm,
        cudaFuncAttributeMaxDynamicSharedMemorySize, GEMM_SMEM_BYTES);
    cudaFuncSetAttribute(o_gemm,
        cudaFuncAttributeMaxDynamicSharedMemorySize, GEMM_SMEM_BYTES);

    // One fused conversion launch (x + 4 weight matrices)
    cvt_all<<<dim3(M_ROWS*D_MODEL/4/256, 5), 256>>>(
        (const float4*)x,  (uint4*)gXt,
        (const float4*)Wq, (uint4*)gWqt,
        (const float4*)Wk, (uint4*)gWkt,
        (const float4*)Wv, (uint4*)gWvt,
        (const float4*)Wo, (uint4*)gWot);

    // Fused Q/K/V projections (tensor cores, cp.async pipeline)
    qkv_gemm<<<dim3(20, M_ROWS/128), 256, GEMM_SMEM_BYTES>>>(
        gXt, gWqt, bq, gWkt, bk, gWvt, bv, gQ, gK, gV);

    // Tensor-core causal attention -> gA (tf32 bits)
    attn_kernel<<<dim3(SEQ/BQ, N_WAVE + N_STD, BATCH), 256, ATTN_SMEM_BYTES>>>(gQ, gK, gV, wav, gA);

    // Output projection -> d_out (fp32)
    o_gemm<<<dim3(D_MODEL/128, M_ROWS/128), 256, GEMM_SMEM_BYTES>>>(gA, gWot, bo, out);
}

// round 9
// speedup vs baseline: 6.5034x; 1.5505x over previous
#include <cuda_runtime.h>
#include <cuda_fp16.h>
#include <math.h>

#define D_MODEL 1024
#define N_STD   12
#define N_WAVE  4
#define D_K     64
#define STD_DIM 768
#define SEQ     1024
#define BATCH   4
#define M_ROWS  (BATCH*SEQ)   // 4096

#define BQ 128
#define BK 32

// attn smem strides (u32 = f16x2)
#define QS2 36     // Qs [128 rows][32 d2 + pad]  : frag bank 4g+q
#define KS2 40     // Ks [32 d2][32 keys + pad]   : frag bank 8q+g
#define VS2 72     // Vs [16 k2][64 dims + pad]   : frag bank 8q+g
#define ATTN_SMEM_BYTES ((128*QS2 + 32*KS2 + 16*VS2)*4)   // 28160

// f16 GEMM tiling (k2 = k-pair units; GBK2=16 u32 = k32 per stage)
#define GBK2 16
#define AS2  20
#define BS2  136
#define GSTG 3
#define AS_STAGE (128*AS2)    // 2560 u32
#define BS_STAGE (GBK2*BS2)   // 2176 u32
#define GEMM_SMEM_BYTES ((GSTG*(AS_STAGE + BS_STAGE))*4)  // 56832

// Scratch (allocation-free rule). All f16x2 packed in u32.
__device__ unsigned g_Xt [M_ROWS*(D_MODEL/2)];
__device__ unsigned g_Wqt[(D_MODEL/2)*STD_DIM];
__device__ unsigned g_Wkt[(D_MODEL/2)*STD_DIM];
__device__ unsigned g_Wvt[(D_MODEL/2)*D_MODEL];
__device__ unsigned g_Wot[(D_MODEL/2)*D_MODEL];
__device__ unsigned g_Q  [M_ROWS*(STD_DIM/2)];
__device__ unsigned g_K  [M_ROWS*(STD_DIM/2)];
__device__ unsigned g_V  [M_ROWS*(D_MODEL/2)];
__device__ unsigned g_A  [M_ROWS*(D_MODEL/2)];

__device__ __forceinline__ unsigned packh2(float a, float b) {
    __half2 h = __floats2half2_rn(a, b);
    return *reinterpret_cast<unsigned*>(&h);
}

__device__ __forceinline__ void mma_f16(float c[4],
    unsigned a0, unsigned a1, unsigned a2, unsigned a3,
    unsigned b0, unsigned b1)
{
    asm volatile(
        "mma.sync.aligned.m16n8k16.row.col.f32.f16.f16.f32 "
        "{%0,%1,%2,%3}, {%4,%5,%6,%7}, {%8,%9}, {%0,%1,%2,%3};"
        : "+f"(c[0]), "+f"(c[1]), "+f"(c[2]), "+f"(c[3])
        : "r"(a0), "r"(a1), "r"(a2), "r"(a3), "r"(b0), "r"(b1));
}

__device__ __forceinline__ void cp16(unsigned* smem_dst, const void* gsrc) {
    unsigned s = (unsigned)__cvta_generic_to_shared(smem_dst);
    asm volatile("cp.async.cg.shared.global [%0], [%1], 16;\n" :: "r"(s), "l"(gsrc));
}
#define CP_COMMIT() asm volatile("cp.async.commit_group;\n")
#define CP_WAIT1()  asm volatile("cp.async.wait_group 1;\n")

// ---------------------------------------------------------------------------
// x [M,1024] f32 -> Xt [M][512] u32 (d-pairs packed within row)
// ---------------------------------------------------------------------------
__global__ __launch_bounds__(256) void cvt_x(
    const float4* __restrict__ src, uint2* __restrict__ dst, int n4)
{
    int i = blockIdx.x * 256 + threadIdx.x;
    if (i < n4) {
        float4 v = src[i];
        dst[i] = make_uint2(packh2(v.x, v.y), packh2(v.z, v.w));
    }
}

// ---------------------------------------------------------------------------
// W [1024][N] f32 -> Wt [512][N] u32, packing (W[2k2][n], W[2k2+1][n]).
// grid.y selects which weight matrix.
// ---------------------------------------------------------------------------
__global__ __launch_bounds__(256) void cvt_w(
    const float* __restrict__ wq, unsigned* __restrict__ wqt,
    const float* __restrict__ wk, unsigned* __restrict__ wkt,
    const float* __restrict__ wv, unsigned* __restrict__ wvt,
    const float* __restrict__ wo, unsigned* __restrict__ wot)
{
    const float* W; unsigned* Wt; int N;
    switch (blockIdx.y) {
        case 0: W = wq; Wt = wqt; N = STD_DIM; break;
        case 1: W = wk; Wt = wkt; N = STD_DIM; break;
        case 2: W = wv; Wt = wvt; N = D_MODEL; break;
        default:W = wo; Wt = wot; N = D_MODEL; break;
    }
    int i = blockIdx.x * 256 + threadIdx.x;
    int total = (D_MODEL/2) * (N/4);
    if (i < total) {
        int k2 = i / (N/4), n4 = (i % (N/4)) * 4;
        float4 r0 = *(const float4*)(W + (size_t)(2*k2  ) * N + n4);
        float4 r1 = *(const float4*)(W + (size_t)(2*k2+1) * N + n4);
        *(uint4*)(Wt + (size_t)k2 * N + n4) = make_uint4(
            packh2(r0.x, r1.x), packh2(r0.y, r1.y),
            packh2(r0.z, r1.z), packh2(r0.w, r1.w));
    }
}

// ---------------------------------------------------------------------------
// FP16 GEMM core: 128x128 tile, 32-k per stage (16 u32), cp.async 3-stage,
// 256 threads = 2(m) x 4(n) warps; warp tile 64x32 = 4x4 m16n8k16 frags.
// A: [m][K2] u32 (k-pairs). W: [K2][ldw] u32 (k-pairs per u32, n across).
// ---------------------------------------------------------------------------
template<bool OUT_F16>
__device__ __forceinline__ void h16gemm_core(
    const unsigned* __restrict__ A, const unsigned* __restrict__ W,
    const float* __restrict__ bias, void* __restrict__ Cv,
    int K2, int ldw, int ldc, int bm, int bn)
{
    extern __shared__ unsigned gsm[];
    unsigned* AsB = gsm;
    unsigned* BsB = gsm + GSTG*AS_STAGE;

    const int tid  = threadIdx.x;
    const int lane = tid & 31;
    const int wid  = tid >> 5;
    const int warp_m = wid >> 2;
    const int warp_n = wid & 3;
    const int g = lane >> 2;
    const int q = lane & 3;

    const int ar0 = tid >> 1,  akc0 = (tid & 1) * 8;
    const int bk0 = tid >> 4,  bc0  = (tid & 15) * 8;

    const unsigned* Ap = A + (size_t)(bm + ar0) * K2 + akc0;
    const unsigned* Wp = W + (size_t)bk0 * ldw + bn + bc0;

    auto issue = [&](int s, int k20) {
        unsigned* As = AsB + s*AS_STAGE;
        unsigned* Bs = BsB + s*BS_STAGE;
        cp16(As + ar0*AS2 + akc0,     Ap + k20);
        cp16(As + ar0*AS2 + akc0 + 4, Ap + k20 + 4);
        cp16(Bs + bk0*BS2 + bc0,      Wp + (size_t)k20 * ldw);
        cp16(Bs + bk0*BS2 + bc0 + 4,  Wp + (size_t)k20 * ldw + 4);
    };

    issue(0, 0);      CP_COMMIT();
    issue(1, GBK2);   CP_COMMIT();
    CP_WAIT1();
    __syncthreads();

    float acc[4][4][4];
#pragma unroll
    for (int mt = 0; mt < 4; mt++)
#pragma unroll
        for (int nt = 0; nt < 4; nt++)
#pragma unroll
            for (int i = 0; i < 4; i++) acc[mt][nt][i] = 0.f;

    for (int k20 = 0; k20 < K2; k20 += GBK2) {
        const int nxt = k20 + 2*GBK2;
        if (nxt < K2) issue((nxt >> 4) % GSTG, nxt);
        CP_COMMIT();

        const unsigned* As = AsB + ((k20 >> 4) % GSTG)*AS_STAGE;
        const unsigned* Bs = BsB + ((k20 >> 4) % GSTG)*BS_STAGE;

#pragma unroll
        for (int kb = 0; kb < 2; kb++) {      // two k16 blocks per stage
            const int kc = kb*8;
            unsigned a[4][4], b[4][2];
#pragma unroll
            for (int mt = 0; mt < 4; mt++) {
                int r = warp_m*64 + mt*16 + g;
                a[mt][0] = As[(r    )*AS2 + kc + q];
                a[mt][1] = As[(r + 8)*AS2 + kc + q];
                a[mt][2] = As[(r    )*AS2 + kc + q + 4];
                a[mt][3] = As[(r + 8)*AS2 + kc + q + 4];
            }
#pragma unroll
            for (int nt = 0; nt < 4; nt++) {
                int c = warp_n*32 + nt*8 + g;
                b[nt][0] = Bs[(kc + q    )*BS2 + c];
                b[nt][1] = Bs[(kc + q + 4)*BS2 + c];
            }
#pragma unroll
            for (int mt = 0; mt < 4; mt++)
#pragma unroll
                for (int nt = 0; nt < 4; nt++)
                    mma_f16(acc[mt][nt],
                            a[mt][0], a[mt][1], a[mt][2], a[mt][3],
                            b[nt][0], b[nt][1]);
        }

        if (k20 + GBK2 < K2) {
            CP_WAIT1();
            __syncthreads();
        }
    }

#pragma unroll
    for (int mt = 0; mt < 4; mt++) {
        int r0 = bm + warp_m*64 + mt*16 + g;
#pragma unroll
        for (int nt = 0; nt < 4; nt++) {
            int col = bn + warp_n*32 + nt*8 + 2*q;
            float2 bb = *(const float2*)&bias[col];
            float v00 = acc[mt][nt][0] + bb.x, v01 = acc[mt][nt][1] + bb.y;
            float v10 = acc[mt][nt][2] + bb.x, v11 = acc[mt][nt][3] + bb.y;
            if (OUT_F16) {
                unsigned* C = (unsigned*)Cv;
                C[(size_t)r0     * ldc + col/2] = packh2(v00, v01);
                C[(size_t)(r0+8) * ldc + col/2] = packh2(v10, v11);
            } else {
                float* C = (float*)Cv;
                *(float2*)&C[(size_t)r0     * ldc + col] = make_float2(v00, v01);
                *(float2*)&C[(size_t)(r0+8) * ldc + col] = make_float2(v10, v11);
            }
        }
    }
}

// Fused Q/K/V projection: N-space = [Q 768 | K 768 | V 1024], grid.x = 20
__global__ __launch_bounds__(256) void qkv_gemm(
    const unsigned* __restrict__ x,
    const unsigned* __restrict__ Wq, const float* __restrict__ bq,
    const unsigned* __restrict__ Wk, const float* __restrict__ bk_,
    const unsigned* __restrict__ Wv, const float* __restrict__ bv_,
    unsigned* __restrict__ gQ, unsigned* __restrict__ gK, unsigned* __restrict__ gV)
{
    const int bn_g = blockIdx.x * 128;
    const int bm   = blockIdx.y * 128;
    const unsigned* W; const float* bias; unsigned* C; int ldw, ldc, bn;
    if (bn_g < 768)       { W = Wq; bias = bq;  C = gQ; ldw = 768;  ldc = 384; bn = bn_g; }
    else if (bn_g < 1536) { W = Wk; bias = bk_; C = gK; ldw = 768;  ldc = 384; bn = bn_g - 768; }
    else                  { W = Wv; bias = bv_; C = gV; ldw = 1024; ldc = 512; bn = bn_g - 1536; }
    h16gemm_core<true>(x, W, bias, C, D_MODEL/2, ldw, ldc, bm, bn);
}

// O projection (fp32 output to d_out)
__global__ __launch_bounds__(256) void o_gemm(
    const unsigned* __restrict__ A, const unsigned* __restrict__ W,
    const float* __restrict__ bias, float* __restrict__ C)
{
    h16gemm_core<false>(A, W, bias, C, D_MODEL/2, D_MODEL, D_MODEL,
                        blockIdx.y*128, blockIdx.x*128);
}

// ---------------------------------------------------------------------------
// FP16 tensor-core causal flash attention. Block = 128 q x (head,batch);
// 8 warps, warp w owns rows w*16..+15. 32-key tiles.
// Scores: m16n8k16 over d (4 k-steps std / 1 wave). Softmax on C-layout.
// P stays in registers: score C-frags repack directly into PV A-frags.
// ---------------------------------------------------------------------------
__global__ __launch_bounds__(256, 2) void attn_kernel(
    const unsigned* __restrict__ Qb, const unsigned* __restrict__ Kb,
    const unsigned* __restrict__ Vb, const float* __restrict__ wav,
    unsigned* __restrict__ Ab)
{
    extern __shared__ unsigned sm_u[];
    unsigned* Qs = sm_u;             // [128][QS2]  (d2-major rows)
    unsigned* Ks = Qs + 128*QS2;     // [32 d2][KS2] keys across
    unsigned* Vs = Ks + 32*KS2;      // [16 k2][VS2] dims across

    const int b = blockIdx.z, h = blockIdx.y;
    const int q0 = (gridDim.x - 1 - blockIdx.x) * BQ;   // heavy blocks first
    const int tid = threadIdx.x;
    const int warp = tid >> 5, lane = tid & 31;
    const int g = lane >> 2, q = lane & 3;
    const bool is_wave = (h < N_WAVE);
    const float scale = is_wave ? 0.4082482904638631f : 0.125f;
    const int hh = h - N_WAVE;
    const int wr0 = warp * 16;

    // ---- stage Q (once) ----
    if (is_wave) {
        if (tid < 128) {
            const float* wr = wav + (size_t)(b*SEQ + q0 + tid)*24 + h*6;
            unsigned* qrow = Qs + tid*QS2;
            qrow[0] = packh2(wr[0], wr[1]);
            qrow[1] = packh2(wr[2], wr[3]);
            qrow[2] = packh2(wr[4], wr[5]);
            qrow[3] = 0u; qrow[4] = 0u; qrow[5] = 0u; qrow[6] = 0u; qrow[7] = 0u;
        }
    } else {
        const unsigned* Qg = Qb + (size_t)(b*SEQ + q0)*384 + hh*32;
#pragma unroll
        for (int p = 0; p < 4; p++) {
            int idx = tid + p*256;
            int row = idx >> 3, c4 = (idx & 7)*4;
            *(uint4*)(Qs + row*QS2 + c4) = *(const uint4*)(Qg + (size_t)row*384 + c4);
        }
    }

    float m0 = -1e30f, m1 = -1e30f, l0 = 0.f, l1 = 0.f;
    float o[8][4];
#pragma unroll
    for (int nt = 0; nt < 8; nt++)
#pragma unroll
        for (int i = 0; i < 4; i++) o[nt][i] = 0.f;

    const int ntiles = q0/BK + 4;
    for (int jt = 0; jt < ntiles; jt++) {
        const int j0 = jt * BK;
        __syncthreads();

        // ---- stage V tile: [key][d] f16x2 -> [k2(key-pair)][d] (half scatter) ----
        {
            int key = tid >> 3, d8 = (tid & 7)*8;
            uint4 v = *(const uint4*)(Vb + (size_t)(b*SEQ + j0 + key)*512 + h*32 + d8/2);
            __half* vh = (__half*)Vs;
            int k2 = key >> 1, par = key & 1;
            unsigned vv[4] = {v.x, v.y, v.z, v.w};
#pragma unroll
            for (int u = 0; u < 4; u++) {
                __half2 hp = *(__half2*)&vv[u];
                vh[(k2*VS2 + d8 + 2*u    )*2 + par] = __low2half(hp);
                vh[(k2*VS2 + d8 + 2*u + 1)*2 + par] = __high2half(hp);
            }
        }

        // ---- stage K tile: [key][d2] -> Ks[d2][key] (u32 scatter) ----
        if (is_wave) {
            if (tid < 32) {
                const float* wr = wav + (size_t)(b*SEQ + j0 + tid)*24 + h*6;
                Ks[0*KS2 + tid] = packh2(wr[0], wr[1]);
                Ks[1*KS2 + tid] = packh2(wr[2], wr[3]);
                Ks[2*KS2 + tid] = packh2(wr[4], wr[5]);
#pragma unroll
                for (int c = 3; c < 8; c++) Ks[c*KS2 + tid] = 0u;
            }
        } else {
            int key = tid & 31, c4 = (tid >> 5)*4;
            uint4 v = *(const uint4*)(Kb + (size_t)(b*SEQ + j0 + key)*384 + hh*32 + c4);
            Ks[(c4+0)*KS2 + key] = v.x;
            Ks[(c4+1)*KS2 + key] = v.y;
            Ks[(c4+2)*KS2 + key] = v.z;
            Ks[(c4+3)*KS2 + key] = v.w;
        }
        __syncthreads();

        if (j0 <= q0 + wr0 + 15) {
            // ---- scores: 16x32 per warp ----
            float sacc[4][4];
#pragma unroll
            for (int nt = 0; nt < 4; nt++)
#pragma unroll
                for (int i = 0; i < 4; i++) sacc[nt][i] = 0.f;

            const int nkb = is_wave ? 1 : 4;
            for (int kb = 0; kb < nkb; kb++) {
                const int kc = kb*8;
                unsigned a0 = Qs[(wr0+g  )*QS2 + kc + q];
                unsigned a1 = Qs[(wr0+g+8)*QS2 + kc + q];
                unsigned a2 = Qs[(wr0+g  )*QS2 + kc + q + 4];
                unsigned a3 = Qs[(wr0+g+8)*QS2 + kc + q + 4];
#pragma unroll
                for (int nt = 0; nt < 4; nt++) {
                    unsigned b0 = Ks[(kc + q    )*KS2 + nt*8 + g];
                    unsigned b1 = Ks[(kc + q + 4)*KS2 + nt*8 + g];
                    mma_f16(sacc[nt], a0, a1, a2, a3, b0, b1);
                }
            }

            // ---- mask + scale (C-layout: rows g,g+8; cols 2q,2q+1) ----
            const int r0 = q0 + wr0 + g, r1 = r0 + 8;
#pragma unroll
            for (int nt = 0; nt < 4; nt++) {
                int c0 = j0 + nt*8 + 2*q, c1 = c0 + 1;
                sacc[nt][0] = (c0 > r0) ? -1e30f : sacc[nt][0]*scale;
                sacc[nt][1] = (c1 > r0) ? -1e30f : sacc[nt][1]*scale;
                sacc[nt][2] = (c0 > r1) ? -1e30f : sacc[nt][2]*scale;
                sacc[nt][3] = (c1 > r1) ? -1e30f : sacc[nt][3]*scale;
            }

            // ---- online softmax (quad reductions) ----
            float mx0 = fmaxf(fmaxf(sacc[0][0], sacc[0][1]), fmaxf(sacc[1][0], sacc[1][1]));
            mx0 = fmaxf(mx0, fmaxf(fmaxf(sacc[2][0], sacc[2][1]), fmaxf(sacc[3][0], sacc[3][1])));
            float mx1 = fmaxf(fmaxf(sacc[0][2], sacc[0][3]), fmaxf(sacc[1][2], sacc[1][3]));
            mx1 = fmaxf(mx1, fmaxf(fmaxf(sacc[2][2], sacc[2][3]), fmaxf(sacc[3][2], sacc[3][3])));
            mx0 = fmaxf(mx0, __shfl_xor_sync(0xffffffffu, mx0, 1));
            mx0 = fmaxf(mx0, __shfl_xor_sync(0xffffffffu, mx0, 2));
            mx1 = fmaxf(mx1, __shfl_xor_sync(0xffffffffu, mx1, 1));
            mx1 = fmaxf(mx1, __shfl_xor_sync(0xffffffffu, mx1, 2));

            float mn0 = fmaxf(m0, mx0), mn1 = fmaxf(m1, mx1);
            float fac0 = __expf(m0 - mn0), fac1 = __expf(m1 - mn1);

            float p[4][4];
            float ps0 = 0.f, ps1 = 0.f;
#pragma unroll
            for (int nt = 0; nt < 4; nt++) {
                p[nt][0] = __expf(sacc[nt][0] - mn0);
                p[nt][1] = __expf(sacc[nt][1] - mn0);
                p[nt][2] = __expf(sacc[nt][2] - mn1);
                p[nt][3] = __expf(sacc[nt][3] - mn1);
                ps0 += p[nt][0] + p[nt][1];
                ps1 += p[nt][2] + p[nt][3];
            }
            ps0 += __shfl_xor_sync(0xffffffffu, ps0, 1);
            ps0 += __shfl_xor_sync(0xffffffffu, ps0, 2);
            ps1 += __shfl_xor_sync(0xffffffffu, ps1, 1);
            ps1 += __shfl_xor_sync(0xffffffffu, ps1, 2);

            l0 = l0*fac0 + ps0;  l1 = l1*fac1 + ps1;
            m0 = mn0;            m1 = mn1;
#pragma unroll
            for (int nt = 0; nt < 8; nt++) {
                o[nt][0] *= fac0; o[nt][1] *= fac0;
                o[nt][2] *= fac1; o[nt][3] *= fac1;
            }

            // ---- P: score C-frags -> PV A-frags, all in registers ----
            unsigned pa[2][4];
#pragma unroll
            for (int kb2 = 0; kb2 < 2; kb2++) {
                pa[kb2][0] = packh2(p[2*kb2  ][0], p[2*kb2  ][1]);  // (g,   2q..)
                pa[kb2][1] = packh2(p[2*kb2  ][2], p[2*kb2  ][3]);  // (g+8, 2q..)
                pa[kb2][2] = packh2(p[2*kb2+1][0], p[2*kb2+1][1]);  // (g,   2q+8..)
                pa[kb2][3] = packh2(p[2*kb2+1][2], p[2*kb2+1][3]);  // (g+8, 2q+8..)
            }

            // ---- PV: O += P(16x32) @ V(32x64) ----
#pragma unroll
            for (int kb2 = 0; kb2 < 2; kb2++) {
#pragma unroll
                for (int nt = 0; nt < 8; nt++) {
                    unsigned b0 = Vs[(kb2*8 + q    )*VS2 + nt*8 + g];
                    unsigned b1 = Vs[(kb2*8 + q + 4)*VS2 + nt*8 + g];
                    mma_f16(o[nt], pa[kb2][0], pa[kb2][1], pa[kb2][2], pa[kb2][3], b0, b1);
                }
            }
        }
    }

    // ---- epilogue: pack f16x2 for the O-projection ----
    float inv0 = 1.f / l0, inv1 = 1.f / l1;
    unsigned* A0 = Ab + (size_t)(b*SEQ + q0 + wr0 + g)*512 + h*32;
    unsigned* A1 = A0 + 8*512;
#pragma unroll
    for (int nt = 0; nt < 8; nt++) {
        A0[nt*4 + q] = packh2(o[nt][0]*inv0, o[nt][1]*inv0);
        A1[nt*4 + q] = packh2(o[nt][2]*inv1, o[nt][3]*inv1);
    }
}

// ---------------------------------------------------------------------------
extern "C" void kernel_launch(void* const* d_in, const int* in_sizes, int n_in,
                              void* d_out, int out_size)
{
    const float* x   = (const float*)d_in[0];
    const float* wav = (const float*)d_in[1];
    const float* Wq  = (const float*)d_in[3];
    const float* bq  = (const float*)d_in[4];
    const float* Wk  = (const float*)d_in[5];
    const float* bk  = (const float*)d_in[6];
    const float* Wv  = (const float*)d_in[7];
    const float* bv  = (const float*)d_in[8];
    const float* Wo  = (const float*)d_in[9];
    const float* bo  = (const float*)d_in[10];
    float* out = (float*)d_out;

    unsigned *gXt, *gWqt, *gWkt, *gWvt, *gWot, *gQ, *gK, *gV, *gA;
    cudaGetSymbolAddress((void**)&gXt,  g_Xt);
    cudaGetSymbolAddress((void**)&gWqt, g_Wqt);
    cudaGetSymbolAddress((void**)&gWkt, g_Wkt);
    cudaGetSymbolAddress((void**)&gWvt, g_Wvt);
    cudaGetSymbolAddress((void**)&gWot, g_Wot);
    cudaGetSymbolAddress((void**)&gQ,   g_Q);
    cudaGetSymbolAddress((void**)&gK,   g_K);
    cudaGetSymbolAddress((void**)&gV,   g_V);
    cudaGetSymbolAddress((void**)&gA,   g_A);

    cudaFuncSetAttribute(attn_kernel,
        cudaFuncAttributeMaxDynamicSharedMemorySize, ATTN_SMEM_BYTES);
    cudaFuncSetAttribute(qkv_gemm,
        cudaFuncAttributeMaxDynamicSharedMemorySize, GEMM_SMEM_BYTES);
    cudaFuncSetAttribute(o_gemm,
        cudaFuncAttributeMaxDynamicSharedMemorySize, GEMM_SMEM_BYTES);

    // fp32 -> f16x2 conversions
    cvt_x<<<M_ROWS*D_MODEL/4/256, 256>>>((const float4*)x, (uint2*)gXt, M_ROWS*D_MODEL/4);
    cvt_w<<<dim3((D_MODEL/2)*(D_MODEL/4)/256, 4), 256>>>(
        Wq, gWqt, Wk, gWkt, Wv, gWvt, Wo, gWot);

    // Fused Q/K/V projections (f16 tensor cores, cp.async)
    qkv_gemm<<<dim3(20, M_ROWS/128), 256, GEMM_SMEM_BYTES>>>(
        gXt, gWqt, bq, gWkt, bk, gWvt, bv, gQ, gK, gV);

    // f16 tensor-core causal attention -> gA
    attn_kernel<<<dim3(SEQ/BQ, N_WAVE + N_STD, BATCH), 256, ATTN_SMEM_BYTES>>>(
        gQ, gK, gV, wav, gA);

    // Output projection -> d_out (fp32)
    o_gemm<<<dim3(D_MODEL/128, M_ROWS/128), 256, GEMM_SMEM_BYTES>>>(gA, gWot, bo, out);
}

// round 10
// speedup vs baseline: 7.1197x; 1.0948x over previous
#include <cuda_runtime.h>
#include <cuda_fp16.h>
#include <math.h>

#define D_MODEL 1024
#define N_STD   12
#define N_WAVE  4
#define D_K     64
#define STD_DIM 768
#define SEQ     1024
#define BATCH   4
#define M_ROWS  (BATCH*SEQ)   // 4096

#define BQ 128
#define BK 64

// attn smem strides (u32 = f16x2)
#define QS2 36     // Qs [128 q][32 d2 + pad]        : A-frag bank 4g+q
#define KS2 36     // Ks [64 key][32 d2 + pad]       : B-frag bank 4g+q
#define VS2 72     // Vs [32 k2][64 dims + pad]      : B-frag bank 8q+g
#define ATTN_SMEM_BYTES ((128*QS2 + 64*KS2 + 32*VS2)*4)   // 36864

// f16 GEMM tiling (k2 = k-pair units; GBK2=16 u32 = k32 per stage)
#define GBK2 16
#define AS2  20
#define BS2  136
#define GSTG 3
#define AS_STAGE (128*AS2)
#define BS_STAGE (GBK2*BS2)
#define GEMM_SMEM_BYTES ((GSTG*(AS_STAGE + BS_STAGE))*4)  // 56832

// Scratch (allocation-free rule). All f16x2 packed in u32.
__device__ unsigned g_Xt [M_ROWS*(D_MODEL/2)];
__device__ unsigned g_Wqt[(D_MODEL/2)*STD_DIM];
__device__ unsigned g_Wkt[(D_MODEL/2)*STD_DIM];
__device__ unsigned g_Wvt[(D_MODEL/2)*D_MODEL];
__device__ unsigned g_Wot[(D_MODEL/2)*D_MODEL];
__device__ unsigned g_Q  [M_ROWS*(STD_DIM/2)];
__device__ unsigned g_K  [M_ROWS*(STD_DIM/2)];
__device__ unsigned g_V  [M_ROWS*(D_MODEL/2)];
__device__ unsigned g_A  [M_ROWS*(D_MODEL/2)];

__device__ __forceinline__ unsigned packh2(float a, float b) {
    __half2 h = __floats2half2_rn(a, b);
    return *reinterpret_cast<unsigned*>(&h);
}

__device__ __forceinline__ void mma_f16(float c[4],
    unsigned a0, unsigned a1, unsigned a2, unsigned a3,
    unsigned b0, unsigned b1)
{
    asm volatile(
        "mma.sync.aligned.m16n8k16.row.col.f32.f16.f16.f32 "
        "{%0,%1,%2,%3}, {%4,%5,%6,%7}, {%8,%9}, {%0,%1,%2,%3};"
        : "+f"(c[0]), "+f"(c[1]), "+f"(c[2]), "+f"(c[3])
        : "r"(a0), "r"(a1), "r"(a2), "r"(a3), "r"(b0), "r"(b1));
}

__device__ __forceinline__ void cp16(unsigned* smem_dst, const void* gsrc) {
    unsigned s = (unsigned)__cvta_generic_to_shared(smem_dst);
    asm volatile("cp.async.cg.shared.global [%0], [%1], 16;\n" :: "r"(s), "l"(gsrc));
}
#define CP_COMMIT() asm volatile("cp.async.commit_group;\n")
#define CP_WAIT1()  asm volatile("cp.async.wait_group 1;\n")
#define CP_WAIT0()  asm volatile("cp.async.wait_group 0;\n")

// ---------------------------------------------------------------------------
// Fused fp32 -> f16x2 conversion: seg 0 = x (within-row pairs);
// segs 1-4 = weights (across-row pairs: (W[2k][n], W[2k+1][n])).
// ---------------------------------------------------------------------------
__global__ __launch_bounds__(256) void cvt_all(
    const float* __restrict__ x,  unsigned* __restrict__ xt,
    const float* __restrict__ wq, unsigned* __restrict__ wqt,
    const float* __restrict__ wk, unsigned* __restrict__ wkt,
    const float* __restrict__ wv, unsigned* __restrict__ wvt,
    const float* __restrict__ wo, unsigned* __restrict__ wot)
{
    int i = blockIdx.x * 256 + threadIdx.x;
    if (blockIdx.y == 0) {
        int n4 = M_ROWS*D_MODEL/4;
        if (i < n4) {
            float4 v = ((const float4*)x)[i];
            ((uint2*)xt)[i] = make_uint2(packh2(v.x, v.y), packh2(v.z, v.w));
        }
        return;
    }
    const float* W; unsigned* Wt; int N;
    switch (blockIdx.y) {
        case 1: W = wq; Wt = wqt; N = STD_DIM; break;
        case 2: W = wk; Wt = wkt; N = STD_DIM; break;
        case 3: W = wv; Wt = wvt; N = D_MODEL; break;
        default:W = wo; Wt = wot; N = D_MODEL; break;
    }
    int total = (D_MODEL/2) * (N/4);
    if (i < total) {
        int k2 = i / (N/4), n4 = (i % (N/4)) * 4;
        float4 r0 = *(const float4*)(W + (size_t)(2*k2  ) * N + n4);
        float4 r1 = *(const float4*)(W + (size_t)(2*k2+1) * N + n4);
        *(uint4*)(Wt + (size_t)k2 * N + n4) = make_uint4(
            packh2(r0.x, r1.x), packh2(r0.y, r1.y),
            packh2(r0.z, r1.z), packh2(r0.w, r1.w));
    }
}

// ---------------------------------------------------------------------------
// FP16 GEMM core (unchanged from R9): 128x128 tile, cp.async 3-stage.
// ---------------------------------------------------------------------------
template<bool OUT_F16>
__device__ __forceinline__ void h16gemm_core(
    const unsigned* __restrict__ A, const unsigned* __restrict__ W,
    const float* __restrict__ bias, void* __restrict__ Cv,
    int K2, int ldw, int ldc, int bm, int bn)
{
    extern __shared__ unsigned gsm[];
    unsigned* AsB = gsm;
    unsigned* BsB = gsm + GSTG*AS_STAGE;

    const int tid  = threadIdx.x;
    const int lane = tid & 31;
    const int wid  = tid >> 5;
    const int warp_m = wid >> 2;
    const int warp_n = wid & 3;
    const int g = lane >> 2;
    const int q = lane & 3;

    const int ar0 = tid >> 1,  akc0 = (tid & 1) * 8;
    const int bk0 = tid >> 4,  bc0  = (tid & 15) * 8;

    const unsigned* Ap = A + (size_t)(bm + ar0) * K2 + akc0;
    const unsigned* Wp = W + (size_t)bk0 * ldw + bn + bc0;

    auto issue = [&](int s, int k20) {
        unsigned* As = AsB + s*AS_STAGE;
        unsigned* Bs = BsB + s*BS_STAGE;
        cp16(As + ar0*AS2 + akc0,     Ap + k20);
        cp16(As + ar0*AS2 + akc0 + 4, Ap + k20 + 4);
        cp16(Bs + bk0*BS2 + bc0,      Wp + (size_t)k20 * ldw);
        cp16(Bs + bk0*BS2 + bc0 + 4,  Wp + (size_t)k20 * ldw + 4);
    };

    issue(0, 0);      CP_COMMIT();
    issue(1, GBK2);   CP_COMMIT();
    CP_WAIT1();
    __syncthreads();

    float acc[4][4][4];
#pragma unroll
    for (int mt = 0; mt < 4; mt++)
#pragma unroll
        for (int nt = 0; nt < 4; nt++)
#pragma unroll
            for (int i = 0; i < 4; i++) acc[mt][nt][i] = 0.f;

    for (int k20 = 0; k20 < K2; k20 += GBK2) {
        const int nxt = k20 + 2*GBK2;
        if (nxt < K2) issue((nxt >> 4) % GSTG, nxt);
        CP_COMMIT();

        const unsigned* As = AsB + ((k20 >> 4) % GSTG)*AS_STAGE;
        const unsigned* Bs = BsB + ((k20 >> 4) % GSTG)*BS_STAGE;

#pragma unroll
        for (int kb = 0; kb < 2; kb++) {
            const int kc = kb*8;
            unsigned a[4][4], b[4][2];
#pragma unroll
            for (int mt = 0; mt < 4; mt++) {
                int r = warp_m*64 + mt*16 + g;
                a[mt][0] = As[(r    )*AS2 + kc + q];
                a[mt][1] = As[(r + 8)*AS2 + kc + q];
                a[mt][2] = As[(r    )*AS2 + kc + q + 4];
                a[mt][3] = As[(r + 8)*AS2 + kc + q + 4];
            }
#pragma unroll
            for (int nt = 0; nt < 4; nt++) {
                int c = warp_n*32 + nt*8 + g;
                b[nt][0] = Bs[(kc + q    )*BS2 + c];
                b[nt][1] = Bs[(kc + q + 4)*BS2 + c];
            }
#pragma unroll
            for (int mt = 0; mt < 4; mt++)
#pragma unroll
                for (int nt = 0; nt < 4; nt++)
                    mma_f16(acc[mt][nt],
                            a[mt][0], a[mt][1], a[mt][2], a[mt][3],
                            b[nt][0], b[nt][1]);
        }

        if (k20 + GBK2 < K2) {
            CP_WAIT1();
            __syncthreads();
        }
    }

#pragma unroll
    for (int mt = 0; mt < 4; mt++) {
        int r0 = bm + warp_m*64 + mt*16 + g;
#pragma unroll
        for (int nt = 0; nt < 4; nt++) {
            int col = bn + warp_n*32 + nt*8 + 2*q;
            float2 bb = *(const float2*)&bias[col];
            float v00 = acc[mt][nt][0] + bb.x, v01 = acc[mt][nt][1] + bb.y;
            float v10 = acc[mt][nt][2] + bb.x, v11 = acc[mt][nt][3] + bb.y;
            if (OUT_F16) {
                unsigned* C = (unsigned*)Cv;
                C[(size_t)r0     * ldc + col/2] = packh2(v00, v01);
                C[(size_t)(r0+8) * ldc + col/2] = packh2(v10, v11);
            } else {
                float* C = (float*)Cv;
                *(float2*)&C[(size_t)r0     * ldc + col] = make_float2(v00, v01);
                *(float2*)&C[(size_t)(r0+8) * ldc + col] = make_float2(v10, v11);
            }
        }
    }
}

__global__ __launch_bounds__(256) void qkv_gemm(
    const unsigned* __restrict__ x,
    const unsigned* __restrict__ Wq, const float* __restrict__ bq,
    const unsigned* __restrict__ Wk, const float* __restrict__ bk_,
    const unsigned* __restrict__ Wv, const float* __restrict__ bv_,
    unsigned* __restrict__ gQ, unsigned* __restrict__ gK, unsigned* __restrict__ gV)
{
    const int bn_g = blockIdx.x * 128;
    const int bm   = blockIdx.y * 128;
    const unsigned* W; const float* bias; unsigned* C; int ldw, ldc, bn;
    if (bn_g < 768)       { W = Wq; bias = bq;  C = gQ; ldw = 768;  ldc = 384; bn = bn_g; }
    else if (bn_g < 1536) { W = Wk; bias = bk_; C = gK; ldw = 768;  ldc = 384; bn = bn_g - 768; }
    else                  { W = Wv; bias = bv_; C = gV; ldw = 1024; ldc = 512; bn = bn_g - 1536; }
    h16gemm_core<true>(x, W, bias, C, D_MODEL/2, ldw, ldc, bm, bn);
}

__global__ __launch_bounds__(256) void o_gemm(
    const unsigned* __restrict__ A, const unsigned* __restrict__ W,
    const float* __restrict__ bias, float* __restrict__ C)
{
    h16gemm_core<false>(A, W, bias, C, D_MODEL/2, D_MODEL, D_MODEL,
                        blockIdx.y*128, blockIdx.x*128);
}

// ---------------------------------------------------------------------------
// FP16 causal flash attention, BK=64. Block = 128 q x (head,batch); 8 warps,
// warp w owns rows w*16..+15. K staged row-major [key][d2] via cp.async
// (B-frag reads it directly); V half-scattered to [k2][dim].
// Scores 8 n-frags; P packed register->register per k16 block; PV 4 k-steps.
// ---------------------------------------------------------------------------
__global__ __launch_bounds__(256, 2) void attn_kernel(
    const unsigned* __restrict__ Qb, const unsigned* __restrict__ Kb,
    const unsigned* __restrict__ Vb, const float* __restrict__ wav,
    unsigned* __restrict__ Ab)
{
    extern __shared__ unsigned sm_u[];
    unsigned* Qs = sm_u;             // [128][QS2]
    unsigned* Ks = Qs + 128*QS2;     // [64][KS2]  row-major keys
    unsigned* Vs = Ks + 64*KS2;      // [32][VS2]

    const int b = blockIdx.z, h = blockIdx.y;
    const int q0 = (gridDim.x - 1 - blockIdx.x) * BQ;   // heavy blocks first
    const int tid = threadIdx.x;
    const int warp = tid >> 5, lane = tid & 31;
    const int g = lane >> 2, q = lane & 3;
    const bool is_wave = (h < N_WAVE);
    const float scale = is_wave ? 0.4082482904638631f : 0.125f;
    const int hh = h - N_WAVE;
    const int wr0 = warp * 16;

    // ---- stage Q (once) ----
    if (is_wave) {
        if (tid < 128) {
            const float* wr = wav + (size_t)(b*SEQ + q0 + tid)*24 + h*6;
            unsigned* qrow = Qs + tid*QS2;
            qrow[0] = packh2(wr[0], wr[1]);
            qrow[1] = packh2(wr[2], wr[3]);
            qrow[2] = packh2(wr[4], wr[5]);
            qrow[3] = 0u; qrow[4] = 0u; qrow[5] = 0u; qrow[6] = 0u; qrow[7] = 0u;
        }
    } else {
        const unsigned* Qg = Qb + (size_t)(b*SEQ + q0)*384 + hh*32;
#pragma unroll
        for (int p = 0; p < 4; p++) {
            int idx = tid + p*256;
            int row = idx >> 3, c4 = (idx & 7)*4;
            *(uint4*)(Qs + row*QS2 + c4) = *(const uint4*)(Qg + (size_t)row*384 + c4);
        }
    }

    float m0 = -1e30f, m1 = -1e30f, l0 = 0.f, l1 = 0.f;
    float o[8][4];
#pragma unroll
    for (int nt = 0; nt < 8; nt++)
#pragma unroll
        for (int i = 0; i < 4; i++) o[nt][i] = 0.f;

    const int ntiles = q0/BK + 2;    // keys up to q0+127
    for (int jt = 0; jt < ntiles; jt++) {
        const int j0 = jt * BK;
        __syncthreads();

        // ---- stage K tile: row-major, cp.async (std) / direct (wave) ----
        if (is_wave) {
            if (tid < 64) {
                const float* wr = wav + (size_t)(b*SEQ + j0 + tid)*24 + h*6;
                unsigned* kr = Ks + tid*KS2;
                kr[0] = packh2(wr[0], wr[1]);
                kr[1] = packh2(wr[2], wr[3]);
                kr[2] = packh2(wr[4], wr[5]);
                kr[3] = 0u; kr[4] = 0u; kr[5] = 0u; kr[6] = 0u; kr[7] = 0u;
            }
        } else {
#pragma unroll
            for (int p = 0; p < 2; p++) {
                int idx = tid + p*256;
                int row = idx >> 3, c4 = (idx & 7)*4;
                cp16(Ks + row*KS2 + c4,
                     Kb + (size_t)(b*SEQ + j0 + row)*384 + hh*32 + c4);
            }
            CP_COMMIT();
        }

        // ---- stage V tile: [key][d2] -> [k2][dim] half scatter ----
#pragma unroll
        for (int p = 0; p < 2; p++) {
            int idx = tid + p*256;
            int key = idx >> 3, d8 = (idx & 7)*8;
            uint4 v = *(const uint4*)(Vb + (size_t)(b*SEQ + j0 + key)*512 + h*32 + d8/2);
            __half* vh = (__half*)Vs;
            int k2 = key >> 1, par = key & 1;
            unsigned vv[4] = {v.x, v.y, v.z, v.w};
#pragma unroll
            for (int u = 0; u < 4; u++) {
                __half2 hp = *(__half2*)&vv[u];
                vh[(k2*VS2 + d8 + 2*u    )*2 + par] = __low2half(hp);
                vh[(k2*VS2 + d8 + 2*u + 1)*2 + par] = __high2half(hp);
            }
        }
        if (!is_wave) CP_WAIT0();
        __syncthreads();

        if (j0 <= q0 + wr0 + 15) {   // warp-uniform causal tile skip
            // ---- scores: 16x64 per warp ----
            float sacc[8][4];
#pragma unroll
            for (int nt = 0; nt < 8; nt++)
#pragma unroll
                for (int i = 0; i < 4; i++) sacc[nt][i] = 0.f;

            const int nkb = is_wave ? 1 : 4;
            for (int kb = 0; kb < nkb; kb++) {
                const int kc = kb*8;
                unsigned a0 = Qs[(wr0+g  )*QS2 + kc + q];
                unsigned a1 = Qs[(wr0+g+8)*QS2 + kc + q];
                unsigned a2 = Qs[(wr0+g  )*QS2 + kc + q + 4];
                unsigned a3 = Qs[(wr0+g+8)*QS2 + kc + q + 4];
#pragma unroll
                for (int nt = 0; nt < 8; nt++) {
                    unsigned b0 = Ks[(nt*8+g)*KS2 + kc + q];
                    unsigned b1 = Ks[(nt*8+g)*KS2 + kc + q + 4];
                    mma_f16(sacc[nt], a0, a1, a2, a3, b0, b1);
                }
            }

            // ---- mask + scale (C-layout: rows g,g+8; cols 2q,2q+1) ----
            const int r0 = q0 + wr0 + g, r1 = r0 + 8;
#pragma unroll
            for (int nt = 0; nt < 8; nt++) {
                int c0 = j0 + nt*8 + 2*q, c1 = c0 + 1;
                sacc[nt][0] = (c0 > r0) ? -1e30f : sacc[nt][0]*scale;
                sacc[nt][1] = (c1 > r0) ? -1e30f : sacc[nt][1]*scale;
                sacc[nt][2] = (c0 > r1) ? -1e30f : sacc[nt][2]*scale;
                sacc[nt][3] = (c1 > r1) ? -1e30f : sacc[nt][3]*scale;
            }

            // ---- online softmax (quad reductions) ----
            float mx0 = -1e30f, mx1 = -1e30f;
#pragma unroll
            for (int nt = 0; nt < 8; nt++) {
                mx0 = fmaxf(mx0, fmaxf(sacc[nt][0], sacc[nt][1]));
                mx1 = fmaxf(mx1, fmaxf(sacc[nt][2], sacc[nt][3]));
            }
            mx0 = fmaxf(mx0, __shfl_xor_sync(0xffffffffu, mx0, 1));
            mx0 = fmaxf(mx0, __shfl_xor_sync(0xffffffffu, mx0, 2));
            mx1 = fmaxf(mx1, __shfl_xor_sync(0xffffffffu, mx1, 1));
            mx1 = fmaxf(mx1, __shfl_xor_sync(0xffffffffu, mx1, 2));

            float mn0 = fmaxf(m0, mx0), mn1 = fmaxf(m1, mx1);
            float fac0 = __expf(m0 - mn0), fac1 = __expf(m1 - mn1);

            float ps0 = 0.f, ps1 = 0.f;
#pragma unroll
            for (int nt = 0; nt < 8; nt++) {
                sacc[nt][0] = __expf(sacc[nt][0] - mn0);
                sacc[nt][1] = __expf(sacc[nt][1] - mn0);
                sacc[nt][2] = __expf(sacc[nt][2] - mn1);
                sacc[nt][3] = __expf(sacc[nt][3] - mn1);
                ps0 += sacc[nt][0] + sacc[nt][1];
                ps1 += sacc[nt][2] + sacc[nt][3];
            }
            ps0 += __shfl_xor_sync(0xffffffffu, ps0, 1);
            ps0 += __shfl_xor_sync(0xffffffffu, ps0, 2);
            ps1 += __shfl_xor_sync(0xffffffffu, ps1, 1);
            ps1 += __shfl_xor_sync(0xffffffffu, ps1, 2);

            l0 = l0*fac0 + ps0;  l1 = l1*fac1 + ps1;
            m0 = mn0;            m1 = mn1;
#pragma unroll
            for (int nt = 0; nt < 8; nt++) {
                o[nt][0] *= fac0; o[nt][1] *= fac0;
                o[nt][2] *= fac1; o[nt][3] *= fac1;
            }

            // ---- PV: O += P(16x64) @ V(64x64); P packed just-in-time ----
#pragma unroll
            for (int kb2 = 0; kb2 < 4; kb2++) {
                unsigned pa0 = packh2(sacc[2*kb2  ][0], sacc[2*kb2  ][1]);
                unsigned pa1 = packh2(sacc[2*kb2  ][2], sacc[2*kb2  ][3]);
                unsigned pa2 = packh2(sacc[2*kb2+1][0], sacc[2*kb2+1][1]);
                unsigned pa3 = packh2(sacc[2*kb2+1][2], sacc[2*kb2+1][3]);
#pragma unroll
                for (int nt = 0; nt < 8; nt++) {
                    unsigned b0 = Vs[(kb2*8 + q    )*VS2 + nt*8 + g];
                    unsigned b1 = Vs[(kb2*8 + q + 4)*VS2 + nt*8 + g];
                    mma_f16(o[nt], pa0, pa1, pa2, pa3, b0, b1);
                }
            }
        }
    }

    // ---- epilogue: pack f16x2 for the O-projection ----
    float inv0 = 1.f / l0, inv1 = 1.f / l1;
    unsigned* A0 = Ab + (size_t)(b*SEQ + q0 + wr0 + g)*512 + h*32;
    unsigned* A1 = A0 + 8*512;
#pragma unroll
    for (int nt = 0; nt < 8; nt++) {
        A0[nt*4 + q] = packh2(o[nt][0]*inv0, o[nt][1]*inv0);
        A1[nt*4 + q] = packh2(o[nt][2]*inv1, o[nt][3]*inv1);
    }
}

// ---------------------------------------------------------------------------
extern "C" void kernel_launch(void* const* d_in, const int* in_sizes, int n_in,
                              void* d_out, int out_size)
{
    const float* x   = (const float*)d_in[0];
    const float* wav = (const float*)d_in[1];
    const float* Wq  = (const float*)d_in[3];
    const float* bq  = (const float*)d_in[4];
    const float* Wk  = (const float*)d_in[5];
    const float* bk  = (const float*)d_in[6];
    const float* Wv  = (const float*)d_in[7];
    const float* bv  = (const float*)d_in[8];
    const float* Wo  = (const float*)d_in[9];
    const float* bo  = (const float*)d_in[10];
    float* out = (float*)d_out;

    unsigned *gXt, *gWqt, *gWkt, *gWvt, *gWot, *gQ, *gK, *gV, *gA;
    cudaGetSymbolAddress((void**)&gXt,  g_Xt);
    cudaGetSymbolAddress((void**)&gWqt, g_Wqt);
    cudaGetSymbolAddress((void**)&gWkt, g_Wkt);
    cudaGetSymbolAddress((void**)&gWvt, g_Wvt);
    cudaGetSymbolAddress((void**)&gWot, g_Wot);
    cudaGetSymbolAddress((void**)&gQ,   g_Q);
    cudaGetSymbolAddress((void**)&gK,   g_K);
    cudaGetSymbolAddress((void**)&gV,   g_V);
    cudaGetSymbolAddress((void**)&gA,   g_A);

    cudaFuncSetAttribute(attn_kernel,
        cudaFuncAttributeMaxDynamicSharedMemorySize, ATTN_SMEM_BYTES);
    cudaFuncSetAttribute(qkv_gemm,
        cudaFuncAttributeMaxDynamicSharedMemorySize, GEMM_SMEM_BYTES);
    cudaFuncSetAttribute(o_gemm,
        cudaFuncAttributeMaxDynamicSharedMemorySize, GEMM_SMEM_BYTES);

    // One fused fp32 -> f16x2 conversion launch (x + 4 weight matrices)
    cvt_all<<<dim3(M_ROWS*D_MODEL/4/256, 5), 256>>>(
        x, gXt, Wq, gWqt, Wk, gWkt, Wv, gWvt, Wo, gWot);

    // Fused Q/K/V projections (f16 tensor cores, cp.async)
    qkv_gemm<<<dim3(20, M_ROWS/128), 256, GEMM_SMEM_BYTES>>>(
        gXt, gWqt, bq, gWkt, bk, gWvt, bv, gQ, gK, gV);

    // f16 tensor-core causal attention -> gA
    attn_kernel<<<dim3(SEQ/BQ, N_WAVE + N_STD, BATCH), 256, ATTN_SMEM_BYTES>>>(
        gQ, gK, gV, wav, gA);

    // Output projection -> d_out (fp32)
    o_gemm<<<dim3(D_MODEL/128, M_ROWS/128), 256, GEMM_SMEM_BYTES>>>(gA, gWot, bo, out);
}

// round 12
// speedup vs baseline: 7.3680x; 1.0349x over previous
#include <cuda_runtime.h>
#include <cuda_fp16.h>
#include <math.h>

#define D_MODEL 1024
#define N_STD   12
#define N_WAVE  4
#define D_K     64
#define STD_DIM 768
#define SEQ     1024
#define BATCH   4
#define M_ROWS  (BATCH*SEQ)   // 4096
#define K2DIM   (D_MODEL/2)   // 512 k-pairs

#define BQ 128
#define BK 64

// attn smem strides (u32 = f16x2)
#define QS2 36
#define KS2 36
#define VS2 72
#define ATTN_SMEM_BYTES ((128*QS2 + 64*KS2 + 32*VS2)*4)   // 36864

// f16 GEMM tiling: both A and B staged as 128 rows x 16 k2, stride 20
#define GBK2 16
#define AS2  20
#define GSTG 3
#define AS_STAGE (128*AS2)    // 2560 u32
#define GEMM_SMEM_BYTES ((GSTG*2*AS_STAGE)*4)   // 61440

// Scratch (allocation-free rule). All f16x2 packed in u32.
// Weights stored N-MAJOR: Wt[n][k2].
__device__ unsigned g_Xt [M_ROWS*K2DIM];
__device__ unsigned g_Wqt[STD_DIM*K2DIM];
__device__ unsigned g_Wkt[STD_DIM*K2DIM];
__device__ unsigned g_Wvt[D_MODEL*K2DIM];
__device__ unsigned g_Wot[D_MODEL*K2DIM];
__device__ unsigned g_Q  [M_ROWS*(STD_DIM/2)];
__device__ unsigned g_K  [M_ROWS*(STD_DIM/2)];
__device__ unsigned g_V  [M_ROWS*(D_MODEL/2)];
__device__ unsigned g_A  [M_ROWS*(D_MODEL/2)];

__device__ __forceinline__ unsigned packh2(float a, float b) {
    __half2 h = __floats2half2_rn(a, b);
    return *reinterpret_cast<unsigned*>(&h);
}

__device__ __forceinline__ void mma_f16(float c[4],
    unsigned a0, unsigned a1, unsigned a2, unsigned a3,
    unsigned b0, unsigned b1)
{
    asm volatile(
        "mma.sync.aligned.m16n8k16.row.col.f32.f16.f16.f32 "
        "{%0,%1,%2,%3}, {%4,%5,%6,%7}, {%8,%9}, {%0,%1,%2,%3};"
        : "+f"(c[0]), "+f"(c[1]), "+f"(c[2]), "+f"(c[3])
        : "r"(a0), "r"(a1), "r"(a2), "r"(a3), "r"(b0), "r"(b1));
}

__device__ __forceinline__ void ldsm_x4(
    unsigned& r0, unsigned& r1, unsigned& r2, unsigned& r3, unsigned addr)
{
    asm volatile(
        "ldmatrix.sync.aligned.m8n8.x4.shared.b16 {%0,%1,%2,%3}, [%4];"
        : "=r"(r0), "=r"(r1), "=r"(r2), "=r"(r3) : "r"(addr));
}

__device__ __forceinline__ void cp16(unsigned* smem_dst, const void* gsrc) {
    unsigned s = (unsigned)__cvta_generic_to_shared(smem_dst);
    asm volatile("cp.async.cg.shared.global [%0], [%1], 16;\n" :: "r"(s), "l"(gsrc));
}
#define CP_COMMIT() asm volatile("cp.async.commit_group;\n")
#define CP_WAIT1()  asm volatile("cp.async.wait_group 1;\n")
#define CP_WAIT0()  asm volatile("cp.async.wait_group 0;\n")

// ---------------------------------------------------------------------------
// x [M,1024] f32 -> Xt [M][512] u32 (within-row d-pairs)
// ---------------------------------------------------------------------------
__global__ __launch_bounds__(256) void cvt_x(
    const float4* __restrict__ src, uint2* __restrict__ dst, int n4)
{
    int i = blockIdx.x * 256 + threadIdx.x;
    if (i < n4) {
        float4 v = src[i];
        dst[i] = make_uint2(packh2(v.x, v.y), packh2(v.z, v.w));
    }
}

// ---------------------------------------------------------------------------
// W [1024][N] f32 -> Wt [N][512] u32 n-major, Wt[n][k2]=(W[2k2][n],W[2k2+1][n]).
// smem-transpose tiles of 64k x 32n. Stride 36 floats = 144B (16B-aligned
// float4 rows — 33 was the R11 misaligned-address bug).
// ---------------------------------------------------------------------------
__global__ __launch_bounds__(256) void cvt_wT(
    const float* __restrict__ wq, unsigned* __restrict__ wqt,
    const float* __restrict__ wk, unsigned* __restrict__ wkt,
    const float* __restrict__ wv, unsigned* __restrict__ wvt,
    const float* __restrict__ wo, unsigned* __restrict__ wot)
{
    const float* W; unsigned* Wt; int N;
    switch (blockIdx.y) {
        case 0: W = wq; Wt = wqt; N = STD_DIM; break;
        case 1: W = wk; Wt = wkt; N = STD_DIM; break;
        case 2: W = wv; Wt = wvt; N = D_MODEL; break;
        default:W = wo; Wt = wot; N = D_MODEL; break;
    }
    const int tiles_n = N / 32;
    const int bx = blockIdx.x;
    if (bx >= tiles_n * 16) return;
    const int n0 = (bx % tiles_n) * 32;
    const int k0 = (bx / tiles_n) * 64;

    __shared__ float sm[64][36];
    const int t = threadIdx.x;
    {
        int row = t >> 3, c4 = (t & 7) * 4;
        *(float4*)&sm[row][c4]      = *(const float4*)(W + (size_t)(k0+row)*N + n0 + c4);
        *(float4*)&sm[row+32][c4]   = *(const float4*)(W + (size_t)(k0+row+32)*N + n0 + c4);
    }
    __syncthreads();
    {
        int n = t >> 3, k2q = (t & 7) * 4;
        uint4 o;
        o.x = packh2(sm[2*(k2q+0)][n], sm[2*(k2q+0)+1][n]);
        o.y = packh2(sm[2*(k2q+1)][n], sm[2*(k2q+1)+1][n]);
        o.z = packh2(sm[2*(k2q+2)][n], sm[2*(k2q+2)+1][n]);
        o.w = packh2(sm[2*(k2q+3)][n], sm[2*(k2q+3)+1][n]);
        *(uint4*)(Wt + (size_t)(n0+n)*K2DIM + k0/2 + k2q) = o;
    }
}

// ---------------------------------------------------------------------------
// FP16 GEMM core with ldmatrix: 128x128 tile, cp.async 3-stage, k32/stage.
// A [m][K2] and Wt [n][K2] both k-major; staged identically (stride AS2).
// 256 threads = 2(m) x 4(n) warps; warp 64x32 = 4x4 m16n8k16 frags.
// ---------------------------------------------------------------------------
template<bool OUT_F16>
__device__ __forceinline__ void h16gemm_core(
    const unsigned* __restrict__ A, const unsigned* __restrict__ Wt,
    const float* __restrict__ bias, void* __restrict__ Cv,
    int ldc, int bm, int bn)
{
    extern __shared__ unsigned gsm[];
    const unsigned smem_base = (unsigned)__cvta_generic_to_shared(gsm);

    const int tid  = threadIdx.x;
    const int lane = tid & 31;
    const int wid  = tid >> 5;
    const int warp_m = wid >> 2;
    const int warp_n = wid & 3;
    const int g = lane >> 2;
    const int q = lane & 3;

    const int srow = tid >> 1, soff = (tid & 1) * 8;
    const unsigned* Ap = A  + (size_t)(bm + srow) * K2DIM + soff;
    const unsigned* Wp = Wt + (size_t)(bn + srow) * K2DIM + soff;

    auto issue = [&](int s, int k20) {
        unsigned* As = gsm + s*AS_STAGE;
        unsigned* Bs = gsm + (GSTG + s)*AS_STAGE;
        cp16(As + srow*AS2 + soff,     Ap + k20);
        cp16(As + srow*AS2 + soff + 4, Ap + k20 + 4);
        cp16(Bs + srow*AS2 + soff,     Wp + k20);
        cp16(Bs + srow*AS2 + soff + 4, Wp + k20 + 4);
    };

    issue(0, 0);      CP_COMMIT();
    issue(1, GBK2);   CP_COMMIT();
    CP_WAIT1();
    __syncthreads();

    // per-lane ldmatrix offsets (u32 units)
    const int a_off = (warp_m*64 + (lane & 15))*AS2 + (lane >> 4)*4;
    const int b_off = (warp_n*32 + (lane >> 4)*8 + (lane & 7))*AS2 + ((lane >> 3) & 1)*4;

    float acc[4][4][4];
#pragma unroll
    for (int mt = 0; mt < 4; mt++)
#pragma unroll
        for (int nt = 0; nt < 4; nt++)
#pragma unroll
            for (int i = 0; i < 4; i++) acc[mt][nt][i] = 0.f;

    for (int k20 = 0; k20 < K2DIM; k20 += GBK2) {
        const int nxt = k20 + 2*GBK2;
        if (nxt < K2DIM) issue((nxt >> 4) % GSTG, nxt);
        CP_COMMIT();

        const int s = (k20 >> 4) % GSTG;
        const unsigned abase = smem_base + (s*AS_STAGE)*4;
        const unsigned bbase = smem_base + ((GSTG + s)*AS_STAGE)*4;

#pragma unroll
        for (int kb = 0; kb < 2; kb++) {
            const int kc = kb*8;
            unsigned a[4][4], b[2][4];
#pragma unroll
            for (int mt = 0; mt < 4; mt++)
                ldsm_x4(a[mt][0], a[mt][1], a[mt][2], a[mt][3],
                        abase + (a_off + mt*16*AS2 + kc)*4);
#pragma unroll
            for (int np = 0; np < 2; np++)
                ldsm_x4(b[np][0], b[np][1], b[np][2], b[np][3],
                        bbase + (b_off + np*16*AS2 + kc)*4);
#pragma unroll
            for (int mt = 0; mt < 4; mt++)
#pragma unroll
                for (int nt = 0; nt < 4; nt++)
                    mma_f16(acc[mt][nt],
                            a[mt][0], a[mt][1], a[mt][2], a[mt][3],
                            b[nt>>1][(nt&1)*2], b[nt>>1][(nt&1)*2+1]);
        }

        if (k20 + GBK2 < K2DIM) {
            CP_WAIT1();
            __syncthreads();
        }
    }

#pragma unroll
    for (int mt = 0; mt < 4; mt++) {
        int r0 = bm + warp_m*64 + mt*16 + g;
#pragma unroll
        for (int nt = 0; nt < 4; nt++) {
            int col = bn + warp_n*32 + nt*8 + 2*q;
            float2 bb = *(const float2*)&bias[col];
            float v00 = acc[mt][nt][0] + bb.x, v01 = acc[mt][nt][1] + bb.y;
            float v10 = acc[mt][nt][2] + bb.x, v11 = acc[mt][nt][3] + bb.y;
            if (OUT_F16) {
                unsigned* C = (unsigned*)Cv;
                C[(size_t)r0     * ldc + col/2] = packh2(v00, v01);
                C[(size_t)(r0+8) * ldc + col/2] = packh2(v10, v11);
            } else {
                float* C = (float*)Cv;
                *(float2*)&C[(size_t)r0     * ldc + col] = make_float2(v00, v01);
                *(float2*)&C[(size_t)(r0+8) * ldc + col] = make_float2(v10, v11);
            }
        }
    }
}

__global__ __launch_bounds__(256) void qkv_gemm(
    const unsigned* __restrict__ x,
    const unsigned* __restrict__ Wq, const float* __restrict__ bq,
    const unsigned* __restrict__ Wk, const float* __restrict__ bk_,
    const unsigned* __restrict__ Wv, const float* __restrict__ bv_,
    unsigned* __restrict__ gQ, unsigned* __restrict__ gK, unsigned* __restrict__ gV)
{
    const int bn_g = blockIdx.x * 128;
    const int bm   = blockIdx.y * 128;
    const unsigned* W; const float* bias; unsigned* C; int ldc, bn;
    if (bn_g < 768)       { W = Wq; bias = bq;  C = gQ; ldc = 384; bn = bn_g; }
    else if (bn_g < 1536) { W = Wk; bias = bk_; C = gK; ldc = 384; bn = bn_g - 768; }
    else                  { W = Wv; bias = bv_; C = gV; ldc = 512; bn = bn_g - 1536; }
    h16gemm_core<true>(x, W, bias, C, ldc, bm, bn);
}

__global__ __launch_bounds__(256) void o_gemm(
    const unsigned* __restrict__ A, const unsigned* __restrict__ W,
    const float* __restrict__ bias, float* __restrict__ C)
{
    h16gemm_core<false>(A, W, bias, C, D_MODEL, blockIdx.y*128, blockIdx.x*128);
}

// ---------------------------------------------------------------------------
// FP16 causal flash attention, BK=64, ldmatrix Q/K fragment loads.
// ---------------------------------------------------------------------------
__global__ __launch_bounds__(256, 2) void attn_kernel(
    const unsigned* __restrict__ Qb, const unsigned* __restrict__ Kb,
    const unsigned* __restrict__ Vb, const float* __restrict__ wav,
    unsigned* __restrict__ Ab)
{
    extern __shared__ unsigned sm_u[];
    unsigned* Qs = sm_u;             // [128][QS2]
    unsigned* Ks = Qs + 128*QS2;     // [64][KS2]  row-major keys
    unsigned* Vs = Ks + 64*KS2;      // [32][VS2]
    const unsigned smem_base = (unsigned)__cvta_generic_to_shared(sm_u);
    const unsigned ks_base   = smem_base + 128*QS2*4;

    const int b = blockIdx.z, h = blockIdx.y;
    const int q0 = (gridDim.x - 1 - blockIdx.x) * BQ;
    const int tid = threadIdx.x;
    const int warp = tid >> 5, lane = tid & 31;
    const int g = lane >> 2, q = lane & 3;
    const bool is_wave = (h < N_WAVE);
    const float scale = is_wave ? 0.4082482904638631f : 0.125f;
    const int hh = h - N_WAVE;
    const int wr0 = warp * 16;

    // per-lane ldmatrix offsets
    const int qa_off = (wr0 + (lane & 15))*QS2 + (lane >> 4)*4;
    const int kb_off = ((lane >> 4)*8 + (lane & 7))*KS2 + ((lane >> 3) & 1)*4;

    // ---- stage Q (once) ----
    if (is_wave) {
        if (tid < 128) {
            const float* wr = wav + (size_t)(b*SEQ + q0 + tid)*24 + h*6;
            unsigned* qrow = Qs + tid*QS2;
            qrow[0] = packh2(wr[0], wr[1]);
            qrow[1] = packh2(wr[2], wr[3]);
            qrow[2] = packh2(wr[4], wr[5]);
            qrow[3] = 0u; qrow[4] = 0u; qrow[5] = 0u; qrow[6] = 0u; qrow[7] = 0u;
        }
    } else {
        const unsigned* Qg = Qb + (size_t)(b*SEQ + q0)*384 + hh*32;
#pragma unroll
        for (int p = 0; p < 4; p++) {
            int idx = tid + p*256;
            int row = idx >> 3, c4 = (idx & 7)*4;
            *(uint4*)(Qs + row*QS2 + c4) = *(const uint4*)(Qg + (size_t)row*384 + c4);
        }
    }

    float m0 = -1e30f, m1 = -1e30f, l0 = 0.f, l1 = 0.f;
    float o[8][4];
#pragma unroll
    for (int nt = 0; nt < 8; nt++)
#pragma unroll
        for (int i = 0; i < 4; i++) o[nt][i] = 0.f;

    const int ntiles = q0/BK + 2;
    for (int jt = 0; jt < ntiles; jt++) {
        const int j0 = jt * BK;
        __syncthreads();

        // ---- stage K tile row-major ----
        if (is_wave) {
            if (tid < 64) {
                const float* wr = wav + (size_t)(b*SEQ + j0 + tid)*24 + h*6;
                unsigned* kr = Ks + tid*KS2;
                kr[0] = packh2(wr[0], wr[1]);
                kr[1] = packh2(wr[2], wr[3]);
                kr[2] = packh2(wr[4], wr[5]);
                kr[3] = 0u; kr[4] = 0u; kr[5] = 0u; kr[6] = 0u; kr[7] = 0u;
            }
        } else {
#pragma unroll
            for (int p = 0; p < 2; p++) {
                int idx = tid + p*256;
                int row = idx >> 3, c4 = (idx & 7)*4;
                cp16(Ks + row*KS2 + c4,
                     Kb + (size_t)(b*SEQ + j0 + row)*384 + hh*32 + c4);
            }
            CP_COMMIT();
        }

        // ---- stage V tile: [key][d2] -> [k2][dim] half scatter ----
#pragma unroll
        for (int p = 0; p < 2; p++) {
            int idx = tid + p*256;
            int key = idx >> 3, d8 = (idx & 7)*8;
            uint4 v = *(const uint4*)(Vb + (size_t)(b*SEQ + j0 + key)*512 + h*32 + d8/2);
            __half* vh = (__half*)Vs;
            int k2 = key >> 1, par = key & 1;
            unsigned vv[4] = {v.x, v.y, v.z, v.w};
#pragma unroll
            for (int u = 0; u < 4; u++) {
                __half2 hp = *(__half2*)&vv[u];
                vh[(k2*VS2 + d8 + 2*u    )*2 + par] = __low2half(hp);
                vh[(k2*VS2 + d8 + 2*u + 1)*2 + par] = __high2half(hp);
            }
        }
        if (!is_wave) CP_WAIT0();
        __syncthreads();

        if (j0 <= q0 + wr0 + 15) {
            // ---- scores: 16x64 per warp ----
            float sacc[8][4];
#pragma unroll
            for (int nt = 0; nt < 8; nt++)
#pragma unroll
                for (int i = 0; i < 4; i++) sacc[nt][i] = 0.f;

            const int nkb = is_wave ? 1 : 4;
            for (int kb = 0; kb < nkb; kb++) {
                const int kc = kb*8;
                unsigned a0, a1, a2, a3;
                ldsm_x4(a0, a1, a2, a3, smem_base + (qa_off + kc)*4);
#pragma unroll
                for (int np = 0; np < 4; np++) {
                    unsigned b0, b1, b2, b3;
                    ldsm_x4(b0, b1, b2, b3, ks_base + (kb_off + np*16*KS2 + kc)*4);
                    mma_f16(sacc[np*2  ], a0, a1, a2, a3, b0, b1);
                    mma_f16(sacc[np*2+1], a0, a1, a2, a3, b2, b3);
                }
            }

            // ---- mask + scale ----
            const int r0 = q0 + wr0 + g, r1 = r0 + 8;
#pragma unroll
            for (int nt = 0; nt < 8; nt++) {
                int c0 = j0 + nt*8 + 2*q, c1 = c0 + 1;
                sacc[nt][0] = (c0 > r0) ? -1e30f : sacc[nt][0]*scale;
                sacc[nt][1] = (c1 > r0) ? -1e30f : sacc[nt][1]*scale;
                sacc[nt][2] = (c0 > r1) ? -1e30f : sacc[nt][2]*scale;
                sacc[nt][3] = (c1 > r1) ? -1e30f : sacc[nt][3]*scale;
            }

            // ---- online softmax (quad reductions) ----
            float mx0 = -1e30f, mx1 = -1e30f;
#pragma unroll
            for (int nt = 0; nt < 8; nt++) {
                mx0 = fmaxf(mx0, fmaxf(sacc[nt][0], sacc[nt][1]));
                mx1 = fmaxf(mx1, fmaxf(sacc[nt][2], sacc[nt][3]));
            }
            mx0 = fmaxf(mx0, __shfl_xor_sync(0xffffffffu, mx0, 1));
            mx0 = fmaxf(mx0, __shfl_xor_sync(0xffffffffu, mx0, 2));
            mx1 = fmaxf(mx1, __shfl_xor_sync(0xffffffffu, mx1, 1));
            mx1 = fmaxf(mx1, __shfl_xor_sync(0xffffffffu, mx1, 2));

            float mn0 = fmaxf(m0, mx0), mn1 = fmaxf(m1, mx1);
            float fac0 = __expf(m0 - mn0), fac1 = __expf(m1 - mn1);

            float ps0 = 0.f, ps1 = 0.f;
#pragma unroll
            for (int nt = 0; nt < 8; nt++) {
                sacc[nt][0] = __expf(sacc[nt][0] - mn0);
                sacc[nt][1] = __expf(sacc[nt][1] - mn0);
                sacc[nt][2] = __expf(sacc[nt][2] - mn1);
                sacc[nt][3] = __expf(sacc[nt][3] - mn1);
                ps0 += sacc[nt][0] + sacc[nt][1];
                ps1 += sacc[nt][2] + sacc[nt][3];
            }
            ps0 += __shfl_xor_sync(0xffffffffu, ps0, 1);
            ps0 += __shfl_xor_sync(0xffffffffu, ps0, 2);
            ps1 += __shfl_xor_sync(0xffffffffu, ps1, 1);
            ps1 += __shfl_xor_sync(0xffffffffu, ps1, 2);

            l0 = l0*fac0 + ps0;  l1 = l1*fac1 + ps1;
            m0 = mn0;            m1 = mn1;
#pragma unroll
            for (int nt = 0; nt < 8; nt++) {
                o[nt][0] *= fac0; o[nt][1] *= fac0;
                o[nt][2] *= fac1; o[nt][3] *= fac1;
            }

            // ---- PV: O += P(16x64) @ V(64x64); P packed just-in-time ----
#pragma unroll
            for (int kb2 = 0; kb2 < 4; kb2++) {
                unsigned pa0 = packh2(sacc[2*kb2  ][0], sacc[2*kb2  ][1]);
                unsigned pa1 = packh2(sacc[2*kb2  ][2], sacc[2*kb2  ][3]);
                unsigned pa2 = packh2(sacc[2*kb2+1][0], sacc[2*kb2+1][1]);
                unsigned pa3 = packh2(sacc[2*kb2+1][2], sacc[2*kb2+1][3]);
#pragma unroll
                for (int nt = 0; nt < 8; nt++) {
                    unsigned b0 = Vs[(kb2*8 + q    )*VS2 + nt*8 + g];
                    unsigned b1 = Vs[(kb2*8 + q + 4)*VS2 + nt*8 + g];
                    mma_f16(o[nt], pa0, pa1, pa2, pa3, b0, b1);
                }
            }
        }
    }

    // ---- epilogue: pack f16x2 for the O-projection ----
    float inv0 = 1.f / l0, inv1 = 1.f / l1;
    unsigned* A0 = Ab + (size_t)(b*SEQ + q0 + wr0 + g)*512 + h*32;
    unsigned* A1 = A0 + 8*512;
#pragma unroll
    for (int nt = 0; nt < 8; nt++) {
        A0[nt*4 + q] = packh2(o[nt][0]*inv0, o[nt][1]*inv0);
        A1[nt*4 + q] = packh2(o[nt][2]*inv1, o[nt][3]*inv1);
    }
}

// ---------------------------------------------------------------------------
extern "C" void kernel_launch(void* const* d_in, const int* in_sizes, int n_in,
                              void* d_out, int out_size)
{
    const float* x   = (const float*)d_in[0];
    const float* wav = (const float*)d_in[1];
    const float* Wq  = (const float*)d_in[3];
    const float* bq  = (const float*)d_in[4];
    const float* Wk  = (const float*)d_in[5];
    const float* bk  = (const float*)d_in[6];
    const float* Wv  = (const float*)d_in[7];
    const float* bv  = (const float*)d_in[8];
    const float* Wo  = (const float*)d_in[9];
    const float* bo  = (const float*)d_in[10];
    float* out = (float*)d_out;

    unsigned *gXt, *gWqt, *gWkt, *gWvt, *gWot, *gQ, *gK, *gV, *gA;
    cudaGetSymbolAddress((void**)&gXt,  g_Xt);
    cudaGetSymbolAddress((void**)&gWqt, g_Wqt);
    cudaGetSymbolAddress((void**)&gWkt, g_Wkt);
    cudaGetSymbolAddress((void**)&gWvt, g_Wvt);
    cudaGetSymbolAddress((void**)&gWot, g_Wot);
    cudaGetSymbolAddress((void**)&gQ,   g_Q);
    cudaGetSymbolAddress((void**)&gK,   g_K);
    cudaGetSymbolAddress((void**)&gV,   g_V);
    cudaGetSymbolAddress((void**)&gA,   g_A);

    cudaFuncSetAttribute(attn_kernel,
        cudaFuncAttributeMaxDynamicSharedMemorySize, ATTN_SMEM_BYTES);
    cudaFuncSetAttribute(qkv_gemm,
        cudaFuncAttributeMaxDynamicSharedMemorySize, GEMM_SMEM_BYTES);
    cudaFuncSetAttribute(o_gemm,
        cudaFuncAttributeMaxDynamicSharedMemorySize, GEMM_SMEM_BYTES);

    // fp32 -> f16x2 conversions (weights transposed to n-major)
    cvt_x<<<M_ROWS*D_MODEL/4/256, 256>>>((const float4*)x, (uint2*)gXt, M_ROWS*D_MODEL/4);
    cvt_wT<<<dim3(512, 4), 256>>>(Wq, gWqt, Wk, gWkt, Wv, gWvt, Wo, gWot);

    // Fused Q/K/V projections (f16 tensor cores, cp.async + ldmatrix)
    qkv_gemm<<<dim3(20, M_ROWS/128), 256, GEMM_SMEM_BYTES>>>(
        gXt, gWqt, bq, gWkt, bk, gWvt, bv, gQ, gK, gV);

    // f16 tensor-core causal attention -> gA
    attn_kernel<<<dim3(SEQ/BQ, N_WAVE + N_STD, BATCH), 256, ATTN_SMEM_BYTES>>>(
        gQ, gK, gV, wav, gA);

    // Output projection -> d_out (fp32)
    o_gemm<<<dim3(D_MODEL/128, M_ROWS/128), 256, GEMM_SMEM_BYTES>>>(gA, gWot, bo, out);
}

// round 13
// speedup vs baseline: 7.7034x; 1.0455x over previous
#include <cuda_runtime.h>
#include <cuda_fp16.h>
#include <math.h>

#define D_MODEL 1024
#define N_STD   12
#define N_WAVE  4
#define D_K     64
#define STD_DIM 768
#define SEQ     1024
#define BATCH   4
#define M_ROWS  (BATCH*SEQ)   // 4096
#define K2DIM   (D_MODEL/2)   // 512 k-pairs

#define BQ 128
#define BK 64

// attn smem strides (u32 = f16x2)
#define QS2 36
#define KS2 36
#define VS2 36     // V row-major [64 keys][32 u32 + pad] — ldmatrix.trans reads
#define ATTN_SMEM_BYTES ((128*QS2 + 64*KS2 + 64*VS2)*4)   // 36864

// f16 GEMM tiling: both A and B staged as 128 rows x 16 k2, stride 20
#define GBK2 16
#define AS2  20
#define GSTG 3
#define AS_STAGE (128*AS2)    // 2560 u32
#define GEMM_SMEM_BYTES ((GSTG*2*AS_STAGE)*4)   // 61440

// Scratch (allocation-free rule). All f16x2 packed in u32.
// Weights stored N-MAJOR: Wt[n][k2].
__device__ unsigned g_Xt [M_ROWS*K2DIM];
__device__ unsigned g_Wqt[STD_DIM*K2DIM];
__device__ unsigned g_Wkt[STD_DIM*K2DIM];
__device__ unsigned g_Wvt[D_MODEL*K2DIM];
__device__ unsigned g_Wot[D_MODEL*K2DIM];
__device__ unsigned g_Q  [M_ROWS*(STD_DIM/2)];
__device__ unsigned g_K  [M_ROWS*(STD_DIM/2)];
__device__ unsigned g_V  [M_ROWS*(D_MODEL/2)];
__device__ unsigned g_A  [M_ROWS*(D_MODEL/2)];

__device__ __forceinline__ unsigned packh2(float a, float b) {
    __half2 h = __floats2half2_rn(a, b);
    return *reinterpret_cast<unsigned*>(&h);
}

__device__ __forceinline__ void mma_f16(float c[4],
    unsigned a0, unsigned a1, unsigned a2, unsigned a3,
    unsigned b0, unsigned b1)
{
    asm volatile(
        "mma.sync.aligned.m16n8k16.row.col.f32.f16.f16.f32 "
        "{%0,%1,%2,%3}, {%4,%5,%6,%7}, {%8,%9}, {%0,%1,%2,%3};"
        : "+f"(c[0]), "+f"(c[1]), "+f"(c[2]), "+f"(c[3])
        : "r"(a0), "r"(a1), "r"(a2), "r"(a3), "r"(b0), "r"(b1));
}

__device__ __forceinline__ void ldsm_x4(
    unsigned& r0, unsigned& r1, unsigned& r2, unsigned& r3, unsigned addr)
{
    asm volatile(
        "ldmatrix.sync.aligned.m8n8.x4.shared.b16 {%0,%1,%2,%3}, [%4];"
        : "=r"(r0), "=r"(r1), "=r"(r2), "=r"(r3) : "r"(addr));
}

__device__ __forceinline__ void ldsm_x4_trans(
    unsigned& r0, unsigned& r1, unsigned& r2, unsigned& r3, unsigned addr)
{
    asm volatile(
        "ldmatrix.sync.aligned.m8n8.x4.trans.shared.b16 {%0,%1,%2,%3}, [%4];"
        : "=r"(r0), "=r"(r1), "=r"(r2), "=r"(r3) : "r"(addr));
}

__device__ __forceinline__ void cp16(unsigned* smem_dst, const void* gsrc) {
    unsigned s = (unsigned)__cvta_generic_to_shared(smem_dst);
    asm volatile("cp.async.cg.shared.global [%0], [%1], 16;\n" :: "r"(s), "l"(gsrc));
}
#define CP_COMMIT() asm volatile("cp.async.commit_group;\n")
#define CP_WAIT1()  asm volatile("cp.async.wait_group 1;\n")
#define CP_WAIT0()  asm volatile("cp.async.wait_group 0;\n")

// ---------------------------------------------------------------------------
// x [M,1024] f32 -> Xt [M][512] u32 (within-row d-pairs)
// ---------------------------------------------------------------------------
__global__ __launch_bounds__(256) void cvt_x(
    const float4* __restrict__ src, uint2* __restrict__ dst, int n4)
{
    int i = blockIdx.x * 256 + threadIdx.x;
    if (i < n4) {
        float4 v = src[i];
        dst[i] = make_uint2(packh2(v.x, v.y), packh2(v.z, v.w));
    }
}

// ---------------------------------------------------------------------------
// W [1024][N] f32 -> Wt [N][512] u32 n-major (smem transpose, stride 36 = 16B ok)
// ---------------------------------------------------------------------------
__global__ __launch_bounds__(256) void cvt_wT(
    const float* __restrict__ wq, unsigned* __restrict__ wqt,
    const float* __restrict__ wk, unsigned* __restrict__ wkt,
    const float* __restrict__ wv, unsigned* __restrict__ wvt,
    const float* __restrict__ wo, unsigned* __restrict__ wot)
{
    const float* W; unsigned* Wt; int N;
    switch (blockIdx.y) {
        case 0: W = wq; Wt = wqt; N = STD_DIM; break;
        case 1: W = wk; Wt = wkt; N = STD_DIM; break;
        case 2: W = wv; Wt = wvt; N = D_MODEL; break;
        default:W = wo; Wt = wot; N = D_MODEL; break;
    }
    const int tiles_n = N / 32;
    const int bx = blockIdx.x;
    if (bx >= tiles_n * 16) return;
    const int n0 = (bx % tiles_n) * 32;
    const int k0 = (bx / tiles_n) * 64;

    __shared__ float sm[64][36];
    const int t = threadIdx.x;
    {
        int row = t >> 3, c4 = (t & 7) * 4;
        *(float4*)&sm[row][c4]      = *(const float4*)(W + (size_t)(k0+row)*N + n0 + c4);
        *(float4*)&sm[row+32][c4]   = *(const float4*)(W + (size_t)(k0+row+32)*N + n0 + c4);
    }
    __syncthreads();
    {
        int n = t >> 3, k2q = (t & 7) * 4;
        uint4 o;
        o.x = packh2(sm[2*(k2q+0)][n], sm[2*(k2q+0)+1][n]);
        o.y = packh2(sm[2*(k2q+1)][n], sm[2*(k2q+1)+1][n]);
        o.z = packh2(sm[2*(k2q+2)][n], sm[2*(k2q+2)+1][n]);
        o.w = packh2(sm[2*(k2q+3)][n], sm[2*(k2q+3)+1][n]);
        *(uint4*)(Wt + (size_t)(n0+n)*K2DIM + k0/2 + k2q) = o;
    }
}

// ---------------------------------------------------------------------------
// FP16 GEMM core with ldmatrix: 128x128 tile, cp.async 3-stage, k32/stage.
// ---------------------------------------------------------------------------
template<bool OUT_F16>
__device__ __forceinline__ void h16gemm_core(
    const unsigned* __restrict__ A, const unsigned* __restrict__ Wt,
    const float* __restrict__ bias, void* __restrict__ Cv,
    int ldc, int bm, int bn)
{
    extern __shared__ unsigned gsm[];
    const unsigned smem_base = (unsigned)__cvta_generic_to_shared(gsm);

    const int tid  = threadIdx.x;
    const int lane = tid & 31;
    const int wid  = tid >> 5;
    const int warp_m = wid >> 2;
    const int warp_n = wid & 3;
    const int g = lane >> 2;
    const int q = lane & 3;

    const int srow = tid >> 1, soff = (tid & 1) * 8;
    const unsigned* Ap = A  + (size_t)(bm + srow) * K2DIM + soff;
    const unsigned* Wp = Wt + (size_t)(bn + srow) * K2DIM + soff;

    auto issue = [&](int s, int k20) {
        unsigned* As = gsm + s*AS_STAGE;
        unsigned* Bs = gsm + (GSTG + s)*AS_STAGE;
        cp16(As + srow*AS2 + soff,     Ap + k20);
        cp16(As + srow*AS2 + soff + 4, Ap + k20 + 4);
        cp16(Bs + srow*AS2 + soff,     Wp + k20);
        cp16(Bs + srow*AS2 + soff + 4, Wp + k20 + 4);
    };

    issue(0, 0);      CP_COMMIT();
    issue(1, GBK2);   CP_COMMIT();
    CP_WAIT1();
    __syncthreads();

    const int a_off = (warp_m*64 + (lane & 15))*AS2 + (lane >> 4)*4;
    const int b_off = (warp_n*32 + (lane >> 4)*8 + (lane & 7))*AS2 + ((lane >> 3) & 1)*4;

    float acc[4][4][4];
#pragma unroll
    for (int mt = 0; mt < 4; mt++)
#pragma unroll
        for (int nt = 0; nt < 4; nt++)
#pragma unroll
            for (int i = 0; i < 4; i++) acc[mt][nt][i] = 0.f;

    for (int k20 = 0; k20 < K2DIM; k20 += GBK2) {
        const int nxt = k20 + 2*GBK2;
        if (nxt < K2DIM) issue((nxt >> 4) % GSTG, nxt);
        CP_COMMIT();

        const int s = (k20 >> 4) % GSTG;
        const unsigned abase = smem_base + (s*AS_STAGE)*4;
        const unsigned bbase = smem_base + ((GSTG + s)*AS_STAGE)*4;

#pragma unroll
        for (int kb = 0; kb < 2; kb++) {
            const int kc = kb*8;
            unsigned a[4][4], b[2][4];
#pragma unroll
            for (int mt = 0; mt < 4; mt++)
                ldsm_x4(a[mt][0], a[mt][1], a[mt][2], a[mt][3],
                        abase + (a_off + mt*16*AS2 + kc)*4);
#pragma unroll
            for (int np = 0; np < 2; np++)
                ldsm_x4(b[np][0], b[np][1], b[np][2], b[np][3],
                        bbase + (b_off + np*16*AS2 + kc)*4);
#pragma unroll
            for (int mt = 0; mt < 4; mt++)
#pragma unroll
                for (int nt = 0; nt < 4; nt++)
                    mma_f16(acc[mt][nt],
                            a[mt][0], a[mt][1], a[mt][2], a[mt][3],
                            b[nt>>1][(nt&1)*2], b[nt>>1][(nt&1)*2+1]);
        }

        if (k20 + GBK2 < K2DIM) {
            CP_WAIT1();
            __syncthreads();
        }
    }

#pragma unroll
    for (int mt = 0; mt < 4; mt++) {
        int r0 = bm + warp_m*64 + mt*16 + g;
#pragma unroll
        for (int nt = 0; nt < 4; nt++) {
            int col = bn + warp_n*32 + nt*8 + 2*q;
            float2 bb = *(const float2*)&bias[col];
            float v00 = acc[mt][nt][0] + bb.x, v01 = acc[mt][nt][1] + bb.y;
            float v10 = acc[mt][nt][2] + bb.x, v11 = acc[mt][nt][3] + bb.y;
            if (OUT_F16) {
                unsigned* C = (unsigned*)Cv;
                C[(size_t)r0     * ldc + col/2] = packh2(v00, v01);
                C[(size_t)(r0+8) * ldc + col/2] = packh2(v10, v11);
            } else {
                float* C = (float*)Cv;
                *(float2*)&C[(size_t)r0     * ldc + col] = make_float2(v00, v01);
                *(float2*)&C[(size_t)(r0+8) * ldc + col] = make_float2(v10, v11);
            }
        }
    }
}

__global__ __launch_bounds__(256) void qkv_gemm(
    const unsigned* __restrict__ x,
    const unsigned* __restrict__ Wq, const float* __restrict__ bq,
    const unsigned* __restrict__ Wk, const float* __restrict__ bk_,
    const unsigned* __restrict__ Wv, const float* __restrict__ bv_,
    unsigned* __restrict__ gQ, unsigned* __restrict__ gK, unsigned* __restrict__ gV)
{
    const int bn_g = blockIdx.x * 128;
    const int bm   = blockIdx.y * 128;
    const unsigned* W; const float* bias; unsigned* C; int ldc, bn;
    if (bn_g < 768)       { W = Wq; bias = bq;  C = gQ; ldc = 384; bn = bn_g; }
    else if (bn_g < 1536) { W = Wk; bias = bk_; C = gK; ldc = 384; bn = bn_g - 768; }
    else                  { W = Wv; bias = bv_; C = gV; ldc = 512; bn = bn_g - 1536; }
    h16gemm_core<true>(x, W, bias, C, ldc, bm, bn);
}

__global__ __launch_bounds__(256) void o_gemm(
    const unsigned* __restrict__ A, const unsigned* __restrict__ W,
    const float* __restrict__ bias, float* __restrict__ C)
{
    h16gemm_core<false>(A, W, bias, C, D_MODEL, blockIdx.y*128, blockIdx.x*128);
}

// ---------------------------------------------------------------------------
// FP16 causal flash attention, BK=64; Q/K frags via ldmatrix, V frags via
// ldmatrix.trans on row-major V (scatter eliminated; all staging cp.async).
// ---------------------------------------------------------------------------
__global__ __launch_bounds__(256, 2) void attn_kernel(
    const unsigned* __restrict__ Qb, const unsigned* __restrict__ Kb,
    const unsigned* __restrict__ Vb, const float* __restrict__ wav,
    unsigned* __restrict__ Ab)
{
    extern __shared__ unsigned sm_u[];
    unsigned* Qs = sm_u;             // [128][QS2]
    unsigned* Ks = Qs + 128*QS2;     // [64][KS2]  row-major keys
    unsigned* Vs = Ks + 64*KS2;      // [64][VS2]  row-major keys
    const unsigned smem_base = (unsigned)__cvta_generic_to_shared(sm_u);
    const unsigned ks_base   = smem_base + 128*QS2*4;
    const unsigned vs_base   = ks_base + 64*KS2*4;

    const int b = blockIdx.z, h = blockIdx.y;
    const int q0 = (gridDim.x - 1 - blockIdx.x) * BQ;
    const int tid = threadIdx.x;
    const int warp = tid >> 5, lane = tid & 31;
    const int g = lane >> 2, q = lane & 3;
    const bool is_wave = (h < N_WAVE);
    const float scale = is_wave ? 0.4082482904638631f : 0.125f;
    const int hh = h - N_WAVE;
    const int wr0 = warp * 16;

    // per-lane ldmatrix offsets (u32 units)
    const int qa_off = (wr0 + (lane & 15))*QS2 + (lane >> 4)*4;
    const int kb_off = ((lane >> 4)*8 + (lane & 7))*KS2 + ((lane >> 3) & 1)*4;
    // V trans: groups 0/1 -> keys 0-7/8-15 (same dim blk), groups 2/3 -> next dim blk
    const int vt_off = (((lane >> 3) & 1)*8 + (lane & 7))*VS2 + (lane >> 4)*4;

    // ---- stage Q (once) ----
    if (is_wave) {
        if (tid < 128) {
            const float* wr = wav + (size_t)(b*SEQ + q0 + tid)*24 + h*6;
            unsigned* qrow = Qs + tid*QS2;
            qrow[0] = packh2(wr[0], wr[1]);
            qrow[1] = packh2(wr[2], wr[3]);
            qrow[2] = packh2(wr[4], wr[5]);
            qrow[3] = 0u; qrow[4] = 0u; qrow[5] = 0u; qrow[6] = 0u; qrow[7] = 0u;
        }
    } else {
        const unsigned* Qg = Qb + (size_t)(b*SEQ + q0)*384 + hh*32;
#pragma unroll
        for (int p = 0; p < 4; p++) {
            int idx = tid + p*256;
            int row = idx >> 3, c4 = (idx & 7)*4;
            *(uint4*)(Qs + row*QS2 + c4) = *(const uint4*)(Qg + (size_t)row*384 + c4);
        }
    }

    float m0 = -1e30f, m1 = -1e30f, l0 = 0.f, l1 = 0.f;
    float o[8][4];
#pragma unroll
    for (int nt = 0; nt < 8; nt++)
#pragma unroll
        for (int i = 0; i < 4; i++) o[nt][i] = 0.f;

    const int ntiles = q0/BK + 2;
    for (int jt = 0; jt < ntiles; jt++) {
        const int j0 = jt * BK;
        __syncthreads();

        // ---- stage K tile row-major ----
        if (is_wave) {
            if (tid < 64) {
                const float* wr = wav + (size_t)(b*SEQ + j0 + tid)*24 + h*6;
                unsigned* kr = Ks + tid*KS2;
                kr[0] = packh2(wr[0], wr[1]);
                kr[1] = packh2(wr[2], wr[3]);
                kr[2] = packh2(wr[4], wr[5]);
                kr[3] = 0u; kr[4] = 0u; kr[5] = 0u; kr[6] = 0u; kr[7] = 0u;
            }
        } else {
#pragma unroll
            for (int p = 0; p < 2; p++) {
                int idx = tid + p*256;
                int row = idx >> 3, c4 = (idx & 7)*4;
                cp16(Ks + row*KS2 + c4,
                     Kb + (size_t)(b*SEQ + j0 + row)*384 + hh*32 + c4);
            }
        }

        // ---- stage V tile row-major (straight copy, ldmatrix.trans reads) ----
#pragma unroll
        for (int p = 0; p < 2; p++) {
            int idx = tid + p*256;
            int row = idx >> 3, c4 = (idx & 7)*4;
            cp16(Vs + row*VS2 + c4,
                 Vb + (size_t)(b*SEQ + j0 + row)*512 + h*32 + c4);
        }
        CP_COMMIT();
        CP_WAIT0();
        __syncthreads();

        if (j0 <= q0 + wr0 + 15) {
            // ---- scores: 16x64 per warp ----
            float sacc[8][4];
#pragma unroll
            for (int nt = 0; nt < 8; nt++)
#pragma unroll
                for (int i = 0; i < 4; i++) sacc[nt][i] = 0.f;

            const int nkb = is_wave ? 1 : 4;
            for (int kb = 0; kb < nkb; kb++) {
                const int kc = kb*8;
                unsigned a0, a1, a2, a3;
                ldsm_x4(a0, a1, a2, a3, smem_base + (qa_off + kc)*4);
#pragma unroll
                for (int np = 0; np < 4; np++) {
                    unsigned b0, b1, b2, b3;
                    ldsm_x4(b0, b1, b2, b3, ks_base + (kb_off + np*16*KS2 + kc)*4);
                    mma_f16(sacc[np*2  ], a0, a1, a2, a3, b0, b1);
                    mma_f16(sacc[np*2+1], a0, a1, a2, a3, b2, b3);
                }
            }

            // ---- mask + scale (C-layout: rows g,g+8; cols 2q,2q+1) ----
            const int r0 = q0 + wr0 + g, r1 = r0 + 8;
#pragma unroll
            for (int nt = 0; nt < 8; nt++) {
                int c0 = j0 + nt*8 + 2*q, c1 = c0 + 1;
                sacc[nt][0] = (c0 > r0) ? -1e30f : sacc[nt][0]*scale;
                sacc[nt][1] = (c1 > r0) ? -1e30f : sacc[nt][1]*scale;
                sacc[nt][2] = (c0 > r1) ? -1e30f : sacc[nt][2]*scale;
                sacc[nt][3] = (c1 > r1) ? -1e30f : sacc[nt][3]*scale;
            }

            // ---- online softmax (quad reductions) ----
            float mx0 = -1e30f, mx1 = -1e30f;
#pragma unroll
            for (int nt = 0; nt < 8; nt++) {
                mx0 = fmaxf(mx0, fmaxf(sacc[nt][0], sacc[nt][1]));
                mx1 = fmaxf(mx1, fmaxf(sacc[nt][2], sacc[nt][3]));
            }
            mx0 = fmaxf(mx0, __shfl_xor_sync(0xffffffffu, mx0, 1));
            mx0 = fmaxf(mx0, __shfl_xor_sync(0xffffffffu, mx0, 2));
            mx1 = fmaxf(mx1, __shfl_xor_sync(0xffffffffu, mx1, 1));
            mx1 = fmaxf(mx1, __shfl_xor_sync(0xffffffffu, mx1, 2));

            float mn0 = fmaxf(m0, mx0), mn1 = fmaxf(m1, mx1);
            float fac0 = __expf(m0 - mn0), fac1 = __expf(m1 - mn1);

            float ps0 = 0.f, ps1 = 0.f;
#pragma unroll
            for (int nt = 0; nt < 8; nt++) {
                sacc[nt][0] = __expf(sacc[nt][0] - mn0);
                sacc[nt][1] = __expf(sacc[nt][1] - mn0);
                sacc[nt][2] = __expf(sacc[nt][2] - mn1);
                sacc[nt][3] = __expf(sacc[nt][3] - mn1);
                ps0 += sacc[nt][0] + sacc[nt][1];
                ps1 += sacc[nt][2] + sacc[nt][3];
            }
            ps0 += __shfl_xor_sync(0xffffffffu, ps0, 1);
            ps0 += __shfl_xor_sync(0xffffffffu, ps0, 2);
            ps1 += __shfl_xor_sync(0xffffffffu, ps1, 1);
            ps1 += __shfl_xor_sync(0xffffffffu, ps1, 2);

            l0 = l0*fac0 + ps0;  l1 = l1*fac1 + ps1;
            m0 = mn0;            m1 = mn1;
#pragma unroll
            for (int nt = 0; nt < 8; nt++) {
                o[nt][0] *= fac0; o[nt][1] *= fac0;
                o[nt][2] *= fac1; o[nt][3] *= fac1;
            }

            // ---- PV: O += P(16x64) @ V(64x64); V frags via ldmatrix.trans ----
#pragma unroll
            for (int kb2 = 0; kb2 < 4; kb2++) {
                unsigned pa0 = packh2(sacc[2*kb2  ][0], sacc[2*kb2  ][1]);
                unsigned pa1 = packh2(sacc[2*kb2  ][2], sacc[2*kb2  ][3]);
                unsigned pa2 = packh2(sacc[2*kb2+1][0], sacc[2*kb2+1][1]);
                unsigned pa3 = packh2(sacc[2*kb2+1][2], sacc[2*kb2+1][3]);
#pragma unroll
                for (int ntp = 0; ntp < 4; ntp++) {
                    unsigned b0, b1, b2, b3;
                    ldsm_x4_trans(b0, b1, b2, b3,
                        vs_base + (vt_off + kb2*16*VS2 + ntp*8)*4);
                    mma_f16(o[2*ntp  ], pa0, pa1, pa2, pa3, b0, b1);
                    mma_f16(o[2*ntp+1], pa0, pa1, pa2, pa3, b2, b3);
                }
            }
        }
    }

    // ---- epilogue: pack f16x2 for the O-projection ----
    float inv0 = 1.f / l0, inv1 = 1.f / l1;
    unsigned* A0 = Ab + (size_t)(b*SEQ + q0 + wr0 + g)*512 + h*32;
    unsigned* A1 = A0 + 8*512;
#pragma unroll
    for (int nt = 0; nt < 8; nt++) {
        A0[nt*4 + q] = packh2(o[nt][0]*inv0, o[nt][1]*inv0);
        A1[nt*4 + q] = packh2(o[nt][2]*inv1, o[nt][3]*inv1);
    }
}

// ---------------------------------------------------------------------------
extern "C" void kernel_launch(void* const* d_in, const int* in_sizes, int n_in,
                              void* d_out, int out_size)
{
    const float* x   = (const float*)d_in[0];
    const float* wav = (const float*)d_in[1];
    const float* Wq  = (const float*)d_in[3];
    const float* bq  = (const float*)d_in[4];
    const float* Wk  = (const float*)d_in[5];
    const float* bk  = (const float*)d_in[6];
    const float* Wv  = (const float*)d_in[7];
    const float* bv  = (const float*)d_in[8];
    const float* Wo  = (const float*)d_in[9];
    const float* bo  = (const float*)d_in[10];
    float* out = (float*)d_out;

    unsigned *gXt, *gWqt, *gWkt, *gWvt, *gWot, *gQ, *gK, *gV, *gA;
    cudaGetSymbolAddress((void**)&gXt,  g_Xt);
    cudaGetSymbolAddress((void**)&gWqt, g_Wqt);
    cudaGetSymbolAddress((void**)&gWkt, g_Wkt);
    cudaGetSymbolAddress((void**)&gWvt, g_Wvt);
    cudaGetSymbolAddress((void**)&gWot, g_Wot);
    cudaGetSymbolAddress((void**)&gQ,   g_Q);
    cudaGetSymbolAddress((void**)&gK,   g_K);
    cudaGetSymbolAddress((void**)&gV,   g_V);
    cudaGetSymbolAddress((void**)&gA,   g_A);

    cudaFuncSetAttribute(attn_kernel,
        cudaFuncAttributeMaxDynamicSharedMemorySize, ATTN_SMEM_BYTES);
    cudaFuncSetAttribute(qkv_gemm,
        cudaFuncAttributeMaxDynamicSharedMemorySize, GEMM_SMEM_BYTES);
    cudaFuncSetAttribute(o_gemm,
        cudaFuncAttributeMaxDynamicSharedMemorySize, GEMM_SMEM_BYTES);

    // fp32 -> f16x2 conversions (weights transposed to n-major)
    cvt_x<<<M_ROWS*D_MODEL/4/256, 256>>>((const float4*)x, (uint2*)gXt, M_ROWS*D_MODEL/4);
    cvt_wT<<<dim3(512, 4), 256>>>(Wq, gWqt, Wk, gWkt, Wv, gWvt, Wo, gWot);

    // Fused Q/K/V projections (f16 tensor cores, cp.async + ldmatrix)
    qkv_gemm<<<dim3(20, M_ROWS/128), 256, GEMM_SMEM_BYTES>>>(
        gXt, gWqt, bq, gWkt, bk, gWvt, bv, gQ, gK, gV);

    // f16 tensor-core causal attention -> gA
    attn_kernel<<<dim3(SEQ/BQ, N_WAVE + N_STD, BATCH), 256, ATTN_SMEM_BYTES>>>(
        gQ, gK, gV, wav, gA);

    // Output projection -> d_out (fp32)
    o_gemm<<<dim3(D_MODEL/128, M_ROWS/128), 256, GEMM_SMEM_BYTES>>>(gA, gWot, bo, out);
}

// round 14
// speedup vs baseline: 8.0464x; 1.0445x over previous
#include <cuda_runtime.h>
#include <cuda_fp16.h>
#include <math.h>

#define D_MODEL 1024
#define N_STD   12
#define N_WAVE  4
#define D_K     64
#define STD_DIM 768
#define SEQ     1024
#define BATCH   4
#define M_ROWS  (BATCH*SEQ)   // 4096
#define K2DIM   (D_MODEL/2)   // 512 k-pairs

#define BQ 128
#define BK 64

// attn smem (u32 = f16x2): Qs[128][36], then 2x { K[64][36], V[64][36] }
#define QS2 36
#define KVS 36
#define KVBUF (64*KVS)
#define ATTN_SMEM_BYTES ((128*QS2 + 4*KVBUF)*4)   // 55296

// f16 GEMM tiling: both A and B staged as 128 rows x 16 k2, stride 20
#define GBK2 16
#define AS2  20
#define GSTG 3
#define AS_STAGE (128*AS2)    // 2560 u32
#define GEMM_SMEM_BYTES ((GSTG*2*AS_STAGE)*4)   // 61440

// Scratch (allocation-free rule). All f16x2 packed in u32.
// Weights stored N-MAJOR: Wt[n][k2]. Wq pre-scaled by 1/8 (softmax scale fold).
__device__ unsigned g_Xt [M_ROWS*K2DIM];
__device__ unsigned g_Wqt[STD_DIM*K2DIM];
__device__ unsigned g_Wkt[STD_DIM*K2DIM];
__device__ unsigned g_Wvt[D_MODEL*K2DIM];
__device__ unsigned g_Wot[D_MODEL*K2DIM];
__device__ unsigned g_Q  [M_ROWS*(STD_DIM/2)];
__device__ unsigned g_K  [M_ROWS*(STD_DIM/2)];
__device__ unsigned g_V  [M_ROWS*(D_MODEL/2)];
__device__ unsigned g_A  [M_ROWS*(D_MODEL/2)];

__device__ __forceinline__ unsigned packh2(float a, float b) {
    __half2 h = __floats2half2_rn(a, b);
    return *reinterpret_cast<unsigned*>(&h);
}

__device__ __forceinline__ void mma_f16(float c[4],
    unsigned a0, unsigned a1, unsigned a2, unsigned a3,
    unsigned b0, unsigned b1)
{
    asm volatile(
        "mma.sync.aligned.m16n8k16.row.col.f32.f16.f16.f32 "
        "{%0,%1,%2,%3}, {%4,%5,%6,%7}, {%8,%9}, {%0,%1,%2,%3};"
        : "+f"(c[0]), "+f"(c[1]), "+f"(c[2]), "+f"(c[3])
        : "r"(a0), "r"(a1), "r"(a2), "r"(a3), "r"(b0), "r"(b1));
}

__device__ __forceinline__ void ldsm_x4(
    unsigned& r0, unsigned& r1, unsigned& r2, unsigned& r3, unsigned addr)
{
    asm volatile(
        "ldmatrix.sync.aligned.m8n8.x4.shared.b16 {%0,%1,%2,%3}, [%4];"
        : "=r"(r0), "=r"(r1), "=r"(r2), "=r"(r3) : "r"(addr));
}

__device__ __forceinline__ void ldsm_x4_trans(
    unsigned& r0, unsigned& r1, unsigned& r2, unsigned& r3, unsigned addr)
{
    asm volatile(
        "ldmatrix.sync.aligned.m8n8.x4.trans.shared.b16 {%0,%1,%2,%3}, [%4];"
        : "=r"(r0), "=r"(r1), "=r"(r2), "=r"(r3) : "r"(addr));
}

__device__ __forceinline__ void cp16(unsigned* smem_dst, const void* gsrc) {
    unsigned s = (unsigned)__cvta_generic_to_shared(smem_dst);
    asm volatile("cp.async.cg.shared.global [%0], [%1], 16;\n" :: "r"(s), "l"(gsrc));
}
#define CP_COMMIT() asm volatile("cp.async.commit_group;\n")
#define CP_WAIT1()  asm volatile("cp.async.wait_group 1;\n")
#define CP_WAIT0()  asm volatile("cp.async.wait_group 0;\n")

// ---------------------------------------------------------------------------
// x [M,1024] f32 -> Xt [M][512] u32 (within-row d-pairs)
// ---------------------------------------------------------------------------
__global__ __launch_bounds__(256) void cvt_x(
    const float4* __restrict__ src, uint2* __restrict__ dst, int n4)
{
    int i = blockIdx.x * 256 + threadIdx.x;
    if (i < n4) {
        float4 v = src[i];
        dst[i] = make_uint2(packh2(v.x, v.y), packh2(v.z, v.w));
    }
}

// ---------------------------------------------------------------------------
// W [1024][N] f32 -> Wt [N][512] u32 n-major (smem transpose).
// Wq scaled by 0.125 (softmax scale folded into Q).
// ---------------------------------------------------------------------------
__global__ __launch_bounds__(256) void cvt_wT(
    const float* __restrict__ wq, unsigned* __restrict__ wqt,
    const float* __restrict__ wk, unsigned* __restrict__ wkt,
    const float* __restrict__ wv, unsigned* __restrict__ wvt,
    const float* __restrict__ wo, unsigned* __restrict__ wot)
{
    const float* W; unsigned* Wt; int N; float sc = 1.f;
    switch (blockIdx.y) {
        case 0: W = wq; Wt = wqt; N = STD_DIM; sc = 0.125f; break;
        case 1: W = wk; Wt = wkt; N = STD_DIM; break;
        case 2: W = wv; Wt = wvt; N = D_MODEL; break;
        default:W = wo; Wt = wot; N = D_MODEL; break;
    }
    const int tiles_n = N / 32;
    const int bx = blockIdx.x;
    if (bx >= tiles_n * 16) return;
    const int n0 = (bx % tiles_n) * 32;
    const int k0 = (bx / tiles_n) * 64;

    __shared__ float sm[64][36];
    const int t = threadIdx.x;
    {
        int row = t >> 3, c4 = (t & 7) * 4;
        *(float4*)&sm[row][c4]      = *(const float4*)(W + (size_t)(k0+row)*N + n0 + c4);
        *(float4*)&sm[row+32][c4]   = *(const float4*)(W + (size_t)(k0+row+32)*N + n0 + c4);
    }
    __syncthreads();
    {
        int n = t >> 3, k2q = (t & 7) * 4;
        uint4 o;
        o.x = packh2(sm[2*(k2q+0)][n]*sc, sm[2*(k2q+0)+1][n]*sc);
        o.y = packh2(sm[2*(k2q+1)][n]*sc, sm[2*(k2q+1)+1][n]*sc);
        o.z = packh2(sm[2*(k2q+2)][n]*sc, sm[2*(k2q+2)+1][n]*sc);
        o.w = packh2(sm[2*(k2q+3)][n]*sc, sm[2*(k2q+3)+1][n]*sc);
        *(uint4*)(Wt + (size_t)(n0+n)*K2DIM + k0/2 + k2q) = o;
    }
}

// ---------------------------------------------------------------------------
// FP16 GEMM core with ldmatrix (unchanged from R13).
// bscale: bias multiplier (0.125 for the Q segment — scale fold).
// ---------------------------------------------------------------------------
template<bool OUT_F16>
__device__ __forceinline__ void h16gemm_core(
    const unsigned* __restrict__ A, const unsigned* __restrict__ Wt,
    const float* __restrict__ bias, float bscale, void* __restrict__ Cv,
    int ldc, int bm, int bn)
{
    extern __shared__ unsigned gsm[];
    const unsigned smem_base = (unsigned)__cvta_generic_to_shared(gsm);

    const int tid  = threadIdx.x;
    const int lane = tid & 31;
    const int wid  = tid >> 5;
    const int warp_m = wid >> 2;
    const int warp_n = wid & 3;
    const int g = lane >> 2;
    const int q = lane & 3;

    const int srow = tid >> 1, soff = (tid & 1) * 8;
    const unsigned* Ap = A  + (size_t)(bm + srow) * K2DIM + soff;
    const unsigned* Wp = Wt + (size_t)(bn + srow) * K2DIM + soff;

    auto issue = [&](int s, int k20) {
        unsigned* As = gsm + s*AS_STAGE;
        unsigned* Bs = gsm + (GSTG + s)*AS_STAGE;
        cp16(As + srow*AS2 + soff,     Ap + k20);
        cp16(As + srow*AS2 + soff + 4, Ap + k20 + 4);
        cp16(Bs + srow*AS2 + soff,     Wp + k20);
        cp16(Bs + srow*AS2 + soff + 4, Wp + k20 + 4);
    };

    issue(0, 0);      CP_COMMIT();
    issue(1, GBK2);   CP_COMMIT();
    CP_WAIT1();
    __syncthreads();

    const int a_off = (warp_m*64 + (lane & 15))*AS2 + (lane >> 4)*4;
    const int b_off = (warp_n*32 + (lane >> 4)*8 + (lane & 7))*AS2 + ((lane >> 3) & 1)*4;

    float acc[4][4][4];
#pragma unroll
    for (int mt = 0; mt < 4; mt++)
#pragma unroll
        for (int nt = 0; nt < 4; nt++)
#pragma unroll
            for (int i = 0; i < 4; i++) acc[mt][nt][i] = 0.f;

    for (int k20 = 0; k20 < K2DIM; k20 += GBK2) {
        const int nxt = k20 + 2*GBK2;
        if (nxt < K2DIM) issue((nxt >> 4) % GSTG, nxt);
        CP_COMMIT();

        const int s = (k20 >> 4) % GSTG;
        const unsigned abase = smem_base + (s*AS_STAGE)*4;
        const unsigned bbase = smem_base + ((GSTG + s)*AS_STAGE)*4;

#pragma unroll
        for (int kb = 0; kb < 2; kb++) {
            const int kc = kb*8;
            unsigned a[4][4], b[2][4];
#pragma unroll
            for (int mt = 0; mt < 4; mt++)
                ldsm_x4(a[mt][0], a[mt][1], a[mt][2], a[mt][3],
                        abase + (a_off + mt*16*AS2 + kc)*4);
#pragma unroll
            for (int np = 0; np < 2; np++)
                ldsm_x4(b[np][0], b[np][1], b[np][2], b[np][3],
                        bbase + (b_off + np*16*AS2 + kc)*4);
#pragma unroll
            for (int mt = 0; mt < 4; mt++)
#pragma unroll
                for (int nt = 0; nt < 4; nt++)
                    mma_f16(acc[mt][nt],
                            a[mt][0], a[mt][1], a[mt][2], a[mt][3],
                            b[nt>>1][(nt&1)*2], b[nt>>1][(nt&1)*2+1]);
        }

        if (k20 + GBK2 < K2DIM) {
            CP_WAIT1();
            __syncthreads();
        }
    }

#pragma unroll
    for (int mt = 0; mt < 4; mt++) {
        int r0 = bm + warp_m*64 + mt*16 + g;
#pragma unroll
        for (int nt = 0; nt < 4; nt++) {
            int col = bn + warp_n*32 + nt*8 + 2*q;
            float2 bb = *(const float2*)&bias[col];
            bb.x *= bscale; bb.y *= bscale;
            float v00 = acc[mt][nt][0] + bb.x, v01 = acc[mt][nt][1] + bb.y;
            float v10 = acc[mt][nt][2] + bb.x, v11 = acc[mt][nt][3] + bb.y;
            if (OUT_F16) {
                unsigned* C = (unsigned*)Cv;
                C[(size_t)r0     * ldc + col/2] = packh2(v00, v01);
                C[(size_t)(r0+8) * ldc + col/2] = packh2(v10, v11);
            } else {
                float* C = (float*)Cv;
                *(float2*)&C[(size_t)r0     * ldc + col] = make_float2(v00, v01);
                *(float2*)&C[(size_t)(r0+8) * ldc + col] = make_float2(v10, v11);
            }
        }
    }
}

__global__ __launch_bounds__(256) void qkv_gemm(
    const unsigned* __restrict__ x,
    const unsigned* __restrict__ Wq, const float* __restrict__ bq,
    const unsigned* __restrict__ Wk, const float* __restrict__ bk_,
    const unsigned* __restrict__ Wv, const float* __restrict__ bv_,
    unsigned* __restrict__ gQ, unsigned* __restrict__ gK, unsigned* __restrict__ gV)
{
    const int bn_g = blockIdx.x * 128;
    const int bm   = blockIdx.y * 128;
    const unsigned* W; const float* bias; unsigned* C; int ldc, bn; float bs = 1.f;
    if (bn_g < 768)       { W = Wq; bias = bq;  C = gQ; ldc = 384; bn = bn_g; bs = 0.125f; }
    else if (bn_g < 1536) { W = Wk; bias = bk_; C = gK; ldc = 384; bn = bn_g - 768; }
    else                  { W = Wv; bias = bv_; C = gV; ldc = 512; bn = bn_g - 1536; }
    h16gemm_core<true>(x, W, bias, bs, C, ldc, bm, bn);
}

__global__ __launch_bounds__(256) void o_gemm(
    const unsigned* __restrict__ A, const unsigned* __restrict__ W,
    const float* __restrict__ bias, float* __restrict__ C)
{
    h16gemm_core<false>(A, W, bias, 1.f, C, D_MODEL, blockIdx.y*128, blockIdx.x*128);
}

// ---------------------------------------------------------------------------
// FP16 causal flash attention, BK=64, double-buffered K/V cp.async pipeline,
// Q pre-scaled (no per-tile scale FMUL), warp-uniform unmasked fast path.
// ---------------------------------------------------------------------------
__global__ __launch_bounds__(256, 2) void attn_kernel(
    const unsigned* __restrict__ Qb, const unsigned* __restrict__ Kb,
    const unsigned* __restrict__ Vb, const float* __restrict__ wav,
    unsigned* __restrict__ Ab)
{
    extern __shared__ unsigned sm_u[];
    unsigned* Qs = sm_u;                       // [128][QS2]
    unsigned* KV = sm_u + 128*QS2;             // buf s: K at (2s)*KVBUF, V at (2s+1)*KVBUF
    const unsigned smem_base = (unsigned)__cvta_generic_to_shared(sm_u);
    const unsigned kv_base   = smem_base + 128*QS2*4;

    const int b = blockIdx.z, h = blockIdx.y;
    const int q0 = (gridDim.x - 1 - blockIdx.x) * BQ;   // heavy blocks first
    const int tid = threadIdx.x;
    const int warp = tid >> 5, lane = tid & 31;
    const int g = lane >> 2, q = lane & 3;
    const bool is_wave = (h < N_WAVE);
    const int hh = h - N_WAVE;
    const int wr0 = warp * 16;

    // per-lane ldmatrix offsets (u32 units)
    const int qa_off = (wr0 + (lane & 15))*QS2 + (lane >> 4)*4;
    const int kb_off = ((lane >> 4)*8 + (lane & 7))*KVS + ((lane >> 3) & 1)*4;
    const int vt_off = (((lane >> 3) & 1)*8 + (lane & 7))*KVS + (lane >> 4)*4;

    // ---- stage Q (once; wave q pre-scaled by 1/sqrt(6)) ----
    if (is_wave) {
        if (tid < 128) {
            const float* wr = wav + (size_t)(b*SEQ + q0 + tid)*24 + h*6;
            const float ws = 0.4082482904638631f;
            unsigned* qrow = Qs + tid*QS2;
            qrow[0] = packh2(wr[0]*ws, wr[1]*ws);
            qrow[1] = packh2(wr[2]*ws, wr[3]*ws);
            qrow[2] = packh2(wr[4]*ws, wr[5]*ws);
            qrow[3] = 0u; qrow[4] = 0u; qrow[5] = 0u; qrow[6] = 0u; qrow[7] = 0u;
        }
    } else {
        const unsigned* Qg = Qb + (size_t)(b*SEQ + q0)*384 + hh*32;
#pragma unroll
        for (int p = 0; p < 4; p++) {
            int idx = tid + p*256;
            int row = idx >> 3, c4 = (idx & 7)*4;
            *(uint4*)(Qs + row*QS2 + c4) = *(const uint4*)(Qg + (size_t)row*384 + c4);
        }
    }

    // stage K/V for tile jj into buffer s
    auto stage_kv = [&](int jj, int s) {
        const int j0s = jj * BK;
        unsigned* Kd = KV + (2*s  )*KVBUF;
        unsigned* Vd = KV + (2*s+1)*KVBUF;
        if (is_wave) {
            if (tid < 64) {
                const float* wr = wav + (size_t)(b*SEQ + j0s + tid)*24 + h*6;
                unsigned* kr = Kd + tid*KVS;
                kr[0] = packh2(wr[0], wr[1]);
                kr[1] = packh2(wr[2], wr[3]);
                kr[2] = packh2(wr[4], wr[5]);
                kr[3] = 0u; kr[4] = 0u; kr[5] = 0u; kr[6] = 0u; kr[7] = 0u;
            }
        } else {
#pragma unroll
            for (int p = 0; p < 2; p++) {
                int idx = tid + p*256;
                int row = idx >> 3, c4 = (idx & 7)*4;
                cp16(Kd + row*KVS + c4,
                     Kb + (size_t)(b*SEQ + j0s + row)*384 + hh*32 + c4);
            }
        }
#pragma unroll
        for (int p = 0; p < 2; p++) {
            int idx = tid + p*256;
            int row = idx >> 3, c4 = (idx & 7)*4;
            cp16(Vd + row*KVS + c4,
                 Vb + (size_t)(b*SEQ + j0s + row)*512 + h*32 + c4);
        }
    };

    float m0 = -1e30f, m1 = -1e30f, l0 = 0.f, l1 = 0.f;
    float o[8][4];
#pragma unroll
    for (int nt = 0; nt < 8; nt++)
#pragma unroll
        for (int i = 0; i < 4; i++) o[nt][i] = 0.f;

    const int ntiles = q0/BK + 2;

    // prologue: stage tile 0
    stage_kv(0, 0);
    CP_COMMIT();

    for (int jt = 0; jt < ntiles; jt++) {
        const int j0 = jt * BK;
        const int cur = jt & 1;

        if (jt + 1 < ntiles) stage_kv(jt + 1, 1 - cur);
        CP_COMMIT();
        CP_WAIT1();           // current tile's group complete
        __syncthreads();      // staging visible to all warps

        if (j0 <= q0 + wr0 + 15) {     // warp-uniform causal tile skip
            const unsigned ks_b = kv_base + (2*cur  )*KVBUF*4;
            const unsigned vs_b = kv_base + (2*cur+1)*KVBUF*4;

            // ---- scores: 16x64 per warp (Q pre-scaled) ----
            float sacc[8][4];
#pragma unroll
            for (int nt = 0; nt < 8; nt++)
#pragma unroll
                for (int i = 0; i < 4; i++) sacc[nt][i] = 0.f;

            const int nkb = is_wave ? 1 : 4;
            for (int kb = 0; kb < nkb; kb++) {
                const int kc = kb*8;
                unsigned a0, a1, a2, a3;
                ldsm_x4(a0, a1, a2, a3, smem_base + (qa_off + kc)*4);
#pragma unroll
                for (int np = 0; np < 4; np++) {
                    unsigned b0, b1, b2, b3;
                    ldsm_x4(b0, b1, b2, b3, ks_b + (kb_off + np*16*KVS + kc)*4);
                    mma_f16(sacc[np*2  ], a0, a1, a2, a3, b0, b1);
                    mma_f16(sacc[np*2+1], a0, a1, a2, a3, b2, b3);
                }
            }

            // ---- mask only when the tile crosses this warp's diagonal ----
            if (j0 + 63 > q0 + wr0) {
                const int r0 = q0 + wr0 + g, r1 = r0 + 8;
#pragma unroll
                for (int nt = 0; nt < 8; nt++) {
                    int c0 = j0 + nt*8 + 2*q, c1 = c0 + 1;
                    if (c0 > r0) sacc[nt][0] = -1e30f;
                    if (c1 > r0) sacc[nt][1] = -1e30f;
                    if (c0 > r1) sacc[nt][2] = -1e30f;
                    if (c1 > r1) sacc[nt][3] = -1e30f;
                }
            }

            // ---- online softmax (quad reductions) ----
            float mx0 = -1e30f, mx1 = -1e30f;
#pragma unroll
            for (int nt = 0; nt < 8; nt++) {
                mx0 = fmaxf(mx0, fmaxf(sacc[nt][0], sacc[nt][1]));
                mx1 = fmaxf(mx1, fmaxf(sacc[nt][2], sacc[nt][3]));
            }
            mx0 = fmaxf(mx0, __shfl_xor_sync(0xffffffffu, mx0, 1));
            mx0 = fmaxf(mx0, __shfl_xor_sync(0xffffffffu, mx0, 2));
            mx1 = fmaxf(mx1, __shfl_xor_sync(0xffffffffu, mx1, 1));
            mx1 = fmaxf(mx1, __shfl_xor_sync(0xffffffffu, mx1, 2));

            float mn0 = fmaxf(m0, mx0), mn1 = fmaxf(m1, mx1);
            float fac0 = __expf(m0 - mn0), fac1 = __expf(m1 - mn1);

            float ps0 = 0.f, ps1 = 0.f;
#pragma unroll
            for (int nt = 0; nt < 8; nt++) {
                sacc[nt][0] = __expf(sacc[nt][0] - mn0);
                sacc[nt][1] = __expf(sacc[nt][1] - mn0);
                sacc[nt][2] = __expf(sacc[nt][2] - mn1);
                sacc[nt][3] = __expf(sacc[nt][3] - mn1);
                ps0 += sacc[nt][0] + sacc[nt][1];
                ps1 += sacc[nt][2] + sacc[nt][3];
            }
            ps0 += __shfl_xor_sync(0xffffffffu, ps0, 1);
            ps0 += __shfl_xor_sync(0xffffffffu, ps0, 2);
            ps1 += __shfl_xor_sync(0xffffffffu, ps1, 1);
            ps1 += __shfl_xor_sync(0xffffffffu, ps1, 2);

            l0 = l0*fac0 + ps0;  l1 = l1*fac1 + ps1;
            m0 = mn0;            m1 = mn1;
#pragma unroll
            for (int nt = 0; nt < 8; nt++) {
                o[nt][0] *= fac0; o[nt][1] *= fac0;
                o[nt][2] *= fac1; o[nt][3] *= fac1;
            }

            // ---- PV: O += P(16x64) @ V(64x64); V frags via ldmatrix.trans ----
#pragma unroll
            for (int kb2 = 0; kb2 < 4; kb2++) {
                unsigned pa0 = packh2(sacc[2*kb2  ][0], sacc[2*kb2  ][1]);
                unsigned pa1 = packh2(sacc[2*kb2  ][2], sacc[2*kb2  ][3]);
                unsigned pa2 = packh2(sacc[2*kb2+1][0], sacc[2*kb2+1][1]);
                unsigned pa3 = packh2(sacc[2*kb2+1][2], sacc[2*kb2+1][3]);
#pragma unroll
                for (int ntp = 0; ntp < 4; ntp++) {
                    unsigned b0, b1, b2, b3;
                    ldsm_x4_trans(b0, b1, b2, b3,
                        vs_b + (vt_off + kb2*16*KVS + ntp*8)*4);
                    mma_f16(o[2*ntp  ], pa0, pa1, pa2, pa3, b0, b1);
                    mma_f16(o[2*ntp+1], pa0, pa1, pa2, pa3, b2, b3);
                }
            }
        }
        __syncthreads();      // compute done before buffer `cur` is restaged
    }

    // ---- epilogue: pack f16x2 for the O-projection ----
    float inv0 = 1.f / l0, inv1 = 1.f / l1;
    unsigned* A0 = Ab + (size_t)(b*SEQ + q0 + wr0 + g)*512 + h*32;
    unsigned* A1 = A0 + 8*512;
#pragma unroll
    for (int nt = 0; nt < 8; nt++) {
        A0[nt*4 + q] = packh2(o[nt][0]*inv0, o[nt][1]*inv0);
        A1[nt*4 + q] = packh2(o[nt][2]*inv1, o[nt][3]*inv1);
    }
}

// ---------------------------------------------------------------------------
extern "C" void kernel_launch(void* const* d_in, const int* in_sizes, int n_in,
                              void* d_out, int out_size)
{
    const float* x   = (const float*)d_in[0];
    const float* wav = (const float*)d_in[1];
    const float* Wq  = (const float*)d_in[3];
    const float* bq  = (const float*)d_in[4];
    const float* Wk  = (const float*)d_in[5];
    const float* bk  = (const float*)d_in[6];
    const float* Wv  = (const float*)d_in[7];
    const float* bv  = (const float*)d_in[8];
    const float* Wo  = (const float*)d_in[9];
    const float* bo  = (const float*)d_in[10];
    float* out = (float*)d_out;

    unsigned *gXt, *gWqt, *gWkt, *gWvt, *gWot, *gQ, *gK, *gV, *gA;
    cudaGetSymbolAddress((void**)&gXt,  g_Xt);
    cudaGetSymbolAddress((void**)&gWqt, g_Wqt);
    cudaGetSymbolAddress((void**)&gWkt, g_Wkt);
    cudaGetSymbolAddress((void**)&gWvt, g_Wvt);
    cudaGetSymbolAddress((void**)&gWot, g_Wot);
    cudaGetSymbolAddress((void**)&gQ,   g_Q);
    cudaGetSymbolAddress((void**)&gK,   g_K);
    cudaGetSymbolAddress((void**)&gV,   g_V);
    cudaGetSymbolAddress((void**)&gA,   g_A);

    cudaFuncSetAttribute(attn_kernel,
        cudaFuncAttributeMaxDynamicSharedMemorySize, ATTN_SMEM_BYTES);
    cudaFuncSetAttribute(qkv_gemm,
        cudaFuncAttributeMaxDynamicSharedMemorySize, GEMM_SMEM_BYTES);
    cudaFuncSetAttribute(o_gemm,
        cudaFuncAttributeMaxDynamicSharedMemorySize, GEMM_SMEM_BYTES);

    // fp32 -> f16x2 conversions (weights transposed to n-major; Wq pre-scaled)
    cvt_x<<<M_ROWS*D_MODEL/4/256, 256>>>((const float4*)x, (uint2*)gXt, M_ROWS*D_MODEL/4);
    cvt_wT<<<dim3(512, 4), 256>>>(Wq, gWqt, Wk, gWkt, Wv, gWvt, Wo, gWot);

    // Fused Q/K/V projections (f16 tensor cores, cp.async + ldmatrix)
    qkv_gemm<<<dim3(20, M_ROWS/128), 256, GEMM_SMEM_BYTES>>>(
        gXt, gWqt, bq, gWkt, bk, gWvt, bv, gQ, gK, gV);

    // f16 tensor-core causal attention -> gA
    attn_kernel<<<dim3(SEQ/BQ, N_WAVE + N_STD, BATCH), 256, ATTN_SMEM_BYTES>>>(
        gQ, gK, gV, wav, gA);

    // Output projection -> d_out (fp32)
    o_gemm<<<dim3(D_MODEL/128, M_ROWS/128), 256, GEMM_SMEM_BYTES>>>(gA, gWot, bo, out);
}

// round 16
// speedup vs baseline: 8.0522x; 1.0007x over previous
#include <cuda_runtime.h>
#include <cuda_fp16.h>
#include <math.h>

#define D_MODEL 1024
#define N_STD   12
#define N_WAVE  4
#define D_K     64
#define STD_DIM 768
#define SEQ     1024
#define BATCH   4
#define M_ROWS  (BATCH*SEQ)   // 4096
#define K2DIM   (D_MODEL/2)   // 512 k-pairs

#define BQ 128
#define BK 64

// attn smem (u32 = f16x2): Qs[128][36], then 4x { K[64][36], V[64][36] }
#define QS2 36
#define KVS 36
#define KVBUF (64*KVS)
#define NKV 4
#define ATTN_SMEM_BYTES ((128*QS2 + 2*NKV*KVBUF)*4)   // 92160

// f16 GEMM tiling: both A and B staged as 128 rows x 16 k2, stride 20
#define GBK2 16
#define AS2  20
#define GSTG 3
#define AS_STAGE (128*AS2)    // 2560 u32
#define GEMM_SMEM_BYTES ((GSTG*2*AS_STAGE)*4)   // 61440

// Scratch (allocation-free rule). All f16x2 packed in u32.
// Weights stored N-MAJOR: Wt[n][k2]. Wq pre-scaled by 1/8 (softmax scale fold).
__device__ unsigned g_Xt [M_ROWS*K2DIM];
__device__ unsigned g_Wqt[STD_DIM*K2DIM];
__device__ unsigned g_Wkt[STD_DIM*K2DIM];
__device__ unsigned g_Wvt[D_MODEL*K2DIM];
__device__ unsigned g_Wot[D_MODEL*K2DIM];
__device__ unsigned g_Q  [M_ROWS*(STD_DIM/2)];
__device__ unsigned g_K  [M_ROWS*(STD_DIM/2)];
__device__ unsigned g_V  [M_ROWS*(D_MODEL/2)];
__device__ unsigned g_A  [M_ROWS*(D_MODEL/2)];

__device__ __forceinline__ unsigned packh2(float a, float b) {
    __half2 h = __floats2half2_rn(a, b);
    return *reinterpret_cast<unsigned*>(&h);
}

__device__ __forceinline__ void mma_f16(float c[4],
    unsigned a0, unsigned a1, unsigned a2, unsigned a3,
    unsigned b0, unsigned b1)
{
    asm volatile(
        "mma.sync.aligned.m16n8k16.row.col.f32.f16.f16.f32 "
        "{%0,%1,%2,%3}, {%4,%5,%6,%7}, {%8,%9}, {%0,%1,%2,%3};"
        : "+f"(c[0]), "+f"(c[1]), "+f"(c[2]), "+f"(c[3])
        : "r"(a0), "r"(a1), "r"(a2), "r"(a3), "r"(b0), "r"(b1));
}

__device__ __forceinline__ void ldsm_x4(
    unsigned& r0, unsigned& r1, unsigned& r2, unsigned& r3, unsigned addr)
{
    asm volatile(
        "ldmatrix.sync.aligned.m8n8.x4.shared.b16 {%0,%1,%2,%3}, [%4];"
        : "=r"(r0), "=r"(r1), "=r"(r2), "=r"(r3) : "r"(addr));
}

__device__ __forceinline__ void ldsm_x4_trans(
    unsigned& r0, unsigned& r1, unsigned& r2, unsigned& r3, unsigned addr)
{
    asm volatile(
        "ldmatrix.sync.aligned.m8n8.x4.trans.shared.b16 {%0,%1,%2,%3}, [%4];"
        : "=r"(r0), "=r"(r1), "=r"(r2), "=r"(r3) : "r"(addr));
}

__device__ __forceinline__ void cp16(unsigned* smem_dst, const void* gsrc) {
    unsigned s = (unsigned)__cvta_generic_to_shared(smem_dst);
    asm volatile("cp.async.cg.shared.global [%0], [%1], 16;\n" :: "r"(s), "l"(gsrc));
}
#define CP_COMMIT() asm volatile("cp.async.commit_group;\n")
#define CP_WAIT1()  asm volatile("cp.async.wait_group 1;\n")
#define CP_WAIT2()  asm volatile("cp.async.wait_group 2;\n")

// ---------------------------------------------------------------------------
// x [M,1024] f32 -> Xt [M][512] u32 (within-row d-pairs)
// ---------------------------------------------------------------------------
__global__ __launch_bounds__(256) void cvt_x(
    const float4* __restrict__ src, uint2* __restrict__ dst, int n4)
{
    int i = blockIdx.x * 256 + threadIdx.x;
    if (i < n4) {
        float4 v = src[i];
        dst[i] = make_uint2(packh2(v.x, v.y), packh2(v.z, v.w));
    }
}

// ---------------------------------------------------------------------------
// W [1024][N] f32 -> Wt [N][512] u32 n-major (smem transpose).
// Wq scaled by 0.125 (softmax scale folded into Q).
// ---------------------------------------------------------------------------
__global__ __launch_bounds__(256) void cvt_wT(
    const float* __restrict__ wq, unsigned* __restrict__ wqt,
    const float* __restrict__ wk, unsigned* __restrict__ wkt,
    const float* __restrict__ wv, unsigned* __restrict__ wvt,
    const float* __restrict__ wo, unsigned* __restrict__ wot)
{
    const float* W; unsigned* Wt; int N; float sc = 1.f;
    switch (blockIdx.y) {
        case 0: W = wq; Wt = wqt; N = STD_DIM; sc = 0.125f; break;
        case 1: W = wk; Wt = wkt; N = STD_DIM; break;
        case 2: W = wv; Wt = wvt; N = D_MODEL; break;
        default:W = wo; Wt = wot; N = D_MODEL; break;
    }
    const int tiles_n = N / 32;
    const int bx = blockIdx.x;
    if (bx >= tiles_n * 16) return;
    const int n0 = (bx % tiles_n) * 32;
    const int k0 = (bx / tiles_n) * 64;

    __shared__ float sm[64][36];
    const int t = threadIdx.x;
    {
        int row = t >> 3, c4 = (t & 7) * 4;
        *(float4*)&sm[row][c4]      = *(const float4*)(W + (size_t)(k0+row)*N + n0 + c4);
        *(float4*)&sm[row+32][c4]   = *(const float4*)(W + (size_t)(k0+row+32)*N + n0 + c4);
    }
    __syncthreads();
    {
        int n = t >> 3, k2q = (t & 7) * 4;
        uint4 o;
        o.x = packh2(sm[2*(k2q+0)][n]*sc, sm[2*(k2q+0)+1][n]*sc);
        o.y = packh2(sm[2*(k2q+1)][n]*sc, sm[2*(k2q+1)+1][n]*sc);
        o.z = packh2(sm[2*(k2q+2)][n]*sc, sm[2*(k2q+2)+1][n]*sc);
        o.w = packh2(sm[2*(k2q+3)][n]*sc, sm[2*(k2q+3)+1][n]*sc);
        *(uint4*)(Wt + (size_t)(n0+n)*K2DIM + k0/2 + k2q) = o;
    }
}

// ---------------------------------------------------------------------------
// FP16 GEMM core with ldmatrix (unchanged).
// ---------------------------------------------------------------------------
template<bool OUT_F16>
__device__ __forceinline__ void h16gemm_core(
    const unsigned* __restrict__ A, const unsigned* __restrict__ Wt,
    const float* __restrict__ bias, float bscale, void* __restrict__ Cv,
    int ldc, int bm, int bn)
{
    extern __shared__ unsigned gsm[];
    const unsigned smem_base = (unsigned)__cvta_generic_to_shared(gsm);

    const int tid  = threadIdx.x;
    const int lane = tid & 31;
    const int wid  = tid >> 5;
    const int warp_m = wid >> 2;
    const int warp_n = wid & 3;
    const int g = lane >> 2;
    const int q = lane & 3;

    const int srow = tid >> 1, soff = (tid & 1) * 8;
    const unsigned* Ap = A  + (size_t)(bm + srow) * K2DIM + soff;
    const unsigned* Wp = Wt + (size_t)(bn + srow) * K2DIM + soff;

    auto issue = [&](int s, int k20) {
        unsigned* As = gsm + s*AS_STAGE;
        unsigned* Bs = gsm + (GSTG + s)*AS_STAGE;
        cp16(As + srow*AS2 + soff,     Ap + k20);
        cp16(As + srow*AS2 + soff + 4, Ap + k20 + 4);
        cp16(Bs + srow*AS2 + soff,     Wp + k20);
        cp16(Bs + srow*AS2 + soff + 4, Wp + k20 + 4);
    };

    issue(0, 0);      CP_COMMIT();
    issue(1, GBK2);   CP_COMMIT();
    CP_WAIT1();
    __syncthreads();

    const int a_off = (warp_m*64 + (lane & 15))*AS2 + (lane >> 4)*4;
    const int b_off = (warp_n*32 + (lane >> 4)*8 + (lane & 7))*AS2 + ((lane >> 3) & 1)*4;

    float acc[4][4][4];
#pragma unroll
    for (int mt = 0; mt < 4; mt++)
#pragma unroll
        for (int nt = 0; nt < 4; nt++)
#pragma unroll
            for (int i = 0; i < 4; i++) acc[mt][nt][i] = 0.f;

    for (int k20 = 0; k20 < K2DIM; k20 += GBK2) {
        const int nxt = k20 + 2*GBK2;
        if (nxt < K2DIM) issue((nxt >> 4) % GSTG, nxt);
        CP_COMMIT();

        const int s = (k20 >> 4) % GSTG;
        const unsigned abase = smem_base + (s*AS_STAGE)*4;
        const unsigned bbase = smem_base + ((GSTG + s)*AS_STAGE)*4;

#pragma unroll
        for (int kb = 0; kb < 2; kb++) {
            const int kc = kb*8;
            unsigned a[4][4], b[2][4];
#pragma unroll
            for (int mt = 0; mt < 4; mt++)
                ldsm_x4(a[mt][0], a[mt][1], a[mt][2], a[mt][3],
                        abase + (a_off + mt*16*AS2 + kc)*4);
#pragma unroll
            for (int np = 0; np < 2; np++)
                ldsm_x4(b[np][0], b[np][1], b[np][2], b[np][3],
                        bbase + (b_off + np*16*AS2 + kc)*4);
#pragma unroll
            for (int mt = 0; mt < 4; mt++)
#pragma unroll
                for (int nt = 0; nt < 4; nt++)
                    mma_f16(acc[mt][nt],
                            a[mt][0], a[mt][1], a[mt][2], a[mt][3],
                            b[nt>>1][(nt&1)*2], b[nt>>1][(nt&1)*2+1]);
        }

        if (k20 + GBK2 < K2DIM) {
            CP_WAIT1();
            __syncthreads();
        }
    }

#pragma unroll
    for (int mt = 0; mt < 4; mt++) {
        int r0 = bm + warp_m*64 + mt*16 + g;
#pragma unroll
        for (int nt = 0; nt < 4; nt++) {
            int col = bn + warp_n*32 + nt*8 + 2*q;
            float2 bb = *(const float2*)&bias[col];
            bb.x *= bscale; bb.y *= bscale;
            float v00 = acc[mt][nt][0] + bb.x, v01 = acc[mt][nt][1] + bb.y;
            float v10 = acc[mt][nt][2] + bb.x, v11 = acc[mt][nt][3] + bb.y;
            if (OUT_F16) {
                unsigned* C = (unsigned*)Cv;
                C[(size_t)r0     * ldc + col/2] = packh2(v00, v01);
                C[(size_t)(r0+8) * ldc + col/2] = packh2(v10, v11);
            } else {
                float* C = (float*)Cv;
                *(float2*)&C[(size_t)r0     * ldc + col] = make_float2(v00, v01);
                *(float2*)&C[(size_t)(r0+8) * ldc + col] = make_float2(v10, v11);
            }
        }
    }
}

__global__ __launch_bounds__(256) void qkv_gemm(
    const unsigned* __restrict__ x,
    const unsigned* __restrict__ Wq, const float* __restrict__ bq,
    const unsigned* __restrict__ Wk, const float* __restrict__ bk_,
    const unsigned* __restrict__ Wv, const float* __restrict__ bv_,
    unsigned* __restrict__ gQ, unsigned* __restrict__ gK, unsigned* __restrict__ gV)
{
    const int bn_g = blockIdx.x * 128;
    const int bm   = blockIdx.y * 128;
    const unsigned* W; const float* bias; unsigned* C; int ldc, bn; float bs = 1.f;
    if (bn_g < 768)       { W = Wq; bias = bq;  C = gQ; ldc = 384; bn = bn_g; bs = 0.125f; }
    else if (bn_g < 1536) { W = Wk; bias = bk_; C = gK; ldc = 384; bn = bn_g - 768; }
    else                  { W = Wv; bias = bv_; C = gV; ldc = 512; bn = bn_g - 1536; }
    h16gemm_core<true>(x, W, bias, bs, C, ldc, bm, bn);
}

__global__ __launch_bounds__(256) void o_gemm(
    const unsigned* __restrict__ A, const unsigned* __restrict__ W,
    const float* __restrict__ bias, float* __restrict__ C)
{
    h16gemm_core<false>(A, W, bias, 1.f, C, D_MODEL, blockIdx.y*128, blockIdx.x*128);
}

// ---------------------------------------------------------------------------
// FP16 causal flash attention, BK=64, 4-buffer K/V cp.async pipeline
// (stage 2 tiles ahead, ONE __syncthreads per tile).
// ---------------------------------------------------------------------------
__global__ __launch_bounds__(256, 2) void attn_kernel(
    const unsigned* __restrict__ Qb, const unsigned* __restrict__ Kb,
    const unsigned* __restrict__ Vb, const float* __restrict__ wav,
    unsigned* __restrict__ Ab)
{
    extern __shared__ unsigned sm_u[];
    unsigned* Qs = sm_u;                       // [128][QS2]
    unsigned* KV = sm_u + 128*QS2;             // buf s: K at (2s)*KVBUF, V at (2s+1)*KVBUF
    const unsigned smem_base = (unsigned)__cvta_generic_to_shared(sm_u);
    const unsigned kv_base   = smem_base + 128*QS2*4;

    const int b = blockIdx.z, h = blockIdx.y;
    const int q0 = (gridDim.x - 1 - blockIdx.x) * BQ;   // heavy blocks first
    const int tid = threadIdx.x;
    const int warp = tid >> 5, lane = tid & 31;
    const int g = lane >> 2, q = lane & 3;
    const bool is_wave = (h < N_WAVE);
    const int hh = h - N_WAVE;
    const int wr0 = warp * 16;

    // per-lane ldmatrix offsets (u32 units)
    const int qa_off = (wr0 + (lane & 15))*QS2 + (lane >> 4)*4;
    const int kb_off = ((lane >> 4)*8 + (lane & 7))*KVS + ((lane >> 3) & 1)*4;
    const int vt_off = (((lane >> 3) & 1)*8 + (lane & 7))*KVS + (lane >> 4)*4;

    // ---- stage Q (once; wave q pre-scaled by 1/sqrt(6)) ----
    if (is_wave) {
        if (tid < 128) {
            const float* wr = wav + (size_t)(b*SEQ + q0 + tid)*24 + h*6;
            const float ws = 0.4082482904638631f;
            unsigned* qrow = Qs + tid*QS2;
            qrow[0] = packh2(wr[0]*ws, wr[1]*ws);
            qrow[1] = packh2(wr[2]*ws, wr[3]*ws);
            qrow[2] = packh2(wr[4]*ws, wr[5]*ws);
            qrow[3] = 0u; qrow[4] = 0u; qrow[5] = 0u; qrow[6] = 0u; qrow[7] = 0u;
        }
    } else {
        const unsigned* Qg = Qb + (size_t)(b*SEQ + q0)*384 + hh*32;
#pragma unroll
        for (int p = 0; p < 4; p++) {
            int idx = tid + p*256;
            int row = idx >> 3, c4 = (idx & 7)*4;
            *(uint4*)(Qs + row*QS2 + c4) = *(const uint4*)(Qg + (size_t)row*384 + c4);
        }
    }

    const int ntiles = q0/BK + 2;

    // stage K/V for tile jj into buffer jj & (NKV-1)
    auto stage_kv = [&](int jj) {
        if (jj >= ntiles) return;        // empty commit keeps the ring count
        const int j0s = jj * BK;
        const int s = jj & (NKV - 1);
        unsigned* Kd = KV + (2*s  )*KVBUF;
        unsigned* Vd = KV + (2*s+1)*KVBUF;
        if (is_wave) {
            if (tid < 64) {
                const float* wr = wav + (size_t)(b*SEQ + j0s + tid)*24 + h*6;
                unsigned* kr = Kd + tid*KVS;
                kr[0] = packh2(wr[0], wr[1]);
                kr[1] = packh2(wr[2], wr[3]);
                kr[2] = packh2(wr[4], wr[5]);
                kr[3] = 0u; kr[4] = 0u; kr[5] = 0u; kr[6] = 0u; kr[7] = 0u;
            }
        } else {
#pragma unroll
            for (int p = 0; p < 2; p++) {
                int idx = tid + p*256;
                int row = idx >> 3, c4 = (idx & 7)*4;
                cp16(Kd + row*KVS + c4,
                     Kb + (size_t)(b*SEQ + j0s + row)*384 + hh*32 + c4);
            }
        }
#pragma unroll
        for (int p = 0; p < 2; p++) {
            int idx = tid + p*256;
            int row = idx >> 3, c4 = (idx & 7)*4;
            cp16(Vd + row*KVS + c4,
                 Vb + (size_t)(b*SEQ + j0s + row)*512 + h*32 + c4);
        }
    };

    float m0 = -1e30f, m1 = -1e30f, l0 = 0.f, l1 = 0.f;
    float o[8][4];
#pragma unroll
    for (int nt = 0; nt < 8; nt++)
#pragma unroll
        for (int i = 0; i < 4; i++) o[nt][i] = 0.f;

    // prologue: stage tiles 0 and 1
    stage_kv(0); CP_COMMIT();
    stage_kv(1); CP_COMMIT();

    for (int jt = 0; jt < ntiles; jt++) {
        const int j0 = jt * BK;
        const int cur = jt & (NKV - 1);

        stage_kv(jt + 2);
        CP_COMMIT();
        CP_WAIT2();           // tile jt's group complete (2 newer may be pending)
        __syncthreads();      // staging visible; also orders prior tile's reads

        if (j0 <= q0 + wr0 + 15) {     // warp-uniform causal tile skip
            const unsigned ks_b = kv_base + (2*cur  )*KVBUF*4;
            const unsigned vs_b = kv_base + (2*cur+1)*KVBUF*4;

            // ---- scores: 16x64 per warp (Q pre-scaled) ----
            float sacc[8][4];
#pragma unroll
            for (int nt = 0; nt < 8; nt++)
#pragma unroll
                for (int i = 0; i < 4; i++) sacc[nt][i] = 0.f;

            const int nkb = is_wave ? 1 : 4;
            for (int kb = 0; kb < nkb; kb++) {
                const int kc = kb*8;
                unsigned a0, a1, a2, a3;
                ldsm_x4(a0, a1, a2, a3, smem_base + (qa_off + kc)*4);
#pragma unroll
                for (int np = 0; np < 4; np++) {
                    unsigned b0, b1, b2, b3;
                    ldsm_x4(b0, b1, b2, b3, ks_b + (kb_off + np*16*KVS + kc)*4);
                    mma_f16(sacc[np*2  ], a0, a1, a2, a3, b0, b1);
                    mma_f16(sacc[np*2+1], a0, a1, a2, a3, b2, b3);
                }
            }

            // ---- mask only when the tile crosses this warp's diagonal ----
            if (j0 + 63 > q0 + wr0) {
                const int r0 = q0 + wr0 + g, r1 = r0 + 8;
#pragma unroll
                for (int nt = 0; nt < 8; nt++) {
                    int c0 = j0 + nt*8 + 2*q, c1 = c0 + 1;
                    if (c0 > r0) sacc[nt][0] = -1e30f;
                    if (c1 > r0) sacc[nt][1] = -1e30f;
                    if (c0 > r1) sacc[nt][2] = -1e30f;
                    if (c1 > r1) sacc[nt][3] = -1e30f;
                }
            }

            // ---- online softmax (quad reductions) ----
            float mx0 = -1e30f, mx1 = -1e30f;
#pragma unroll
            for (int nt = 0; nt < 8; nt++) {
                mx0 = fmaxf(mx0, fmaxf(sacc[nt][0], sacc[nt][1]));
                mx1 = fmaxf(mx1, fmaxf(sacc[nt][2], sacc[nt][3]));
            }
            mx0 = fmaxf(mx0, __shfl_xor_sync(0xffffffffu, mx0, 1));
            mx0 = fmaxf(mx0, __shfl_xor_sync(0xffffffffu, mx0, 2));
            mx1 = fmaxf(mx1, __shfl_xor_sync(0xffffffffu, mx1, 1));
            mx1 = fmaxf(mx1, __shfl_xor_sync(0xffffffffu, mx1, 2));

            float mn0 = fmaxf(m0, mx0), mn1 = fmaxf(m1, mx1);
            float fac0 = __expf(m0 - mn0), fac1 = __expf(m1 - mn1);

            float ps0 = 0.f, ps1 = 0.f;
#pragma unroll
            for (int nt = 0; nt < 8; nt++) {
                sacc[nt][0] = __expf(sacc[nt][0] - mn0);
                sacc[nt][1] = __expf(sacc[nt][1] - mn0);
                sacc[nt][2] = __expf(sacc[nt][2] - mn1);
                sacc[nt][3] = __expf(sacc[nt][3] - mn1);
                ps0 += sacc[nt][0] + sacc[nt][1];
                ps1 += sacc[nt][2] + sacc[nt][3];
            }
            ps0 += __shfl_xor_sync(0xffffffffu, ps0, 1);
            ps0 += __shfl_xor_sync(0xffffffffu, ps0, 2);
            ps1 += __shfl_xor_sync(0xffffffffu, ps1, 1);
            ps1 += __shfl_xor_sync(0xffffffffu, ps1, 2);

            l0 = l0*fac0 + ps0;  l1 = l1*fac1 + ps1;
            m0 = mn0;            m1 = mn1;
#pragma unroll
            for (int nt = 0; nt < 8; nt++) {
                o[nt][0] *= fac0; o[nt][1] *= fac0;
                o[nt][2] *= fac1; o[nt][3] *= fac1;
            }

            // ---- PV: O += P(16x64) @ V(64x64); V frags via ldmatrix.trans ----
#pragma unroll
            for (int kb2 = 0; kb2 < 4; kb2++) {
                unsigned pa0 = packh2(sacc[2*kb2  ][0], sacc[2*kb2  ][1]);
                unsigned pa1 = packh2(sacc[2*kb2  ][2], sacc[2*kb2  ][3]);
                unsigned pa2 = packh2(sacc[2*kb2+1][0], sacc[2*kb2+1][1]);
                unsigned pa3 = packh2(sacc[2*kb2+1][2], sacc[2*kb2+1][3]);
#pragma unroll
                for (int ntp = 0; ntp < 4; ntp++) {
                    unsigned b0, b1, b2, b3;
                    ldsm_x4_trans(b0, b1, b2, b3,
                        vs_b + (vt_off + kb2*16*KVS + ntp*8)*4);
                    mma_f16(o[2*ntp  ], pa0, pa1, pa2, pa3, b0, b1);
                    mma_f16(o[2*ntp+1], pa0, pa1, pa2, pa3, b2, b3);
                }
            }
        }
    }

    // ---- epilogue: pack f16x2 for the O-projection ----
    float inv0 = 1.f / l0, inv1 = 1.f / l1;
    unsigned* A0 = Ab + (size_t)(b*SEQ + q0 + wr0 + g)*512 + h*32;
    unsigned* A1 = A0 + 8*512;
#pragma unroll
    for (int nt = 0; nt < 8; nt++) {
        A0[nt*4 + q] = packh2(o[nt][0]*inv0, o[nt][1]*inv0);
        A1[nt*4 + q] = packh2(o[nt][2]*inv1, o[nt][3]*inv1);
    }
}

// ---------------------------------------------------------------------------
extern "C" void kernel_launch(void* const* d_in, const int* in_sizes, int n_in,
                              void* d_out, int out_size)
{
    const float* x   = (const float*)d_in[0];
    const float* wav = (const float*)d_in[1];
    const float* Wq  = (const float*)d_in[3];
    const float* bq  = (const float*)d_in[4];
    const float* Wk  = (const float*)d_in[5];
    const float* bk  = (const float*)d_in[6];
    const float* Wv  = (const float*)d_in[7];
    const float* bv  = (const float*)d_in[8];
    const float* Wo  = (const float*)d_in[9];
    const float* bo  = (const float*)d_in[10];
    float* out = (float*)d_out;

    unsigned *gXt, *gWqt, *gWkt, *gWvt, *gWot, *gQ, *gK, *gV, *gA;
    cudaGetSymbolAddress((void**)&gXt,  g_Xt);
    cudaGetSymbolAddress((void**)&gWqt, g_Wqt);
    cudaGetSymbolAddress((void**)&gWkt, g_Wkt);
    cudaGetSymbolAddress((void**)&gWvt, g_Wvt);
    cudaGetSymbolAddress((void**)&gWot, g_Wot);
    cudaGetSymbolAddress((void**)&gQ,   g_Q);
    cudaGetSymbolAddress((void**)&gK,   g_K);
    cudaGetSymbolAddress((void**)&gV,   g_V);
    cudaGetSymbolAddress((void**)&gA,   g_A);

    cudaFuncSetAttribute(attn_kernel,
        cudaFuncAttributeMaxDynamicSharedMemorySize, ATTN_SMEM_BYTES);
    cudaFuncSetAttribute(qkv_gemm,
        cudaFuncAttributeMaxDynamicSharedMemorySize, GEMM_SMEM_BYTES);
    cudaFuncSetAttribute(o_gemm,
        cudaFuncAttributeMaxDynamicSharedMemorySize, GEMM_SMEM_BYTES);

    // fp32 -> f16x2 conversions (weights transposed to n-major; Wq pre-scaled)
    cvt_x<<<M_ROWS*D_MODEL/4/256, 256>>>((const float4*)x, (uint2*)gXt, M_ROWS*D_MODEL/4);
    cvt_wT<<<dim3(512, 4), 256>>>(Wq, gWqt, Wk, gWkt, Wv, gWvt, Wo, gWot);

    // Fused Q/K/V projections (f16 tensor cores, cp.async + ldmatrix)
    qkv_gemm<<<dim3(20, M_ROWS/128), 256, GEMM_SMEM_BYTES>>>(
        gXt, gWqt, bq, gWkt, bk, gWvt, bv, gQ, gK, gV);

    // f16 tensor-core causal attention -> gA
    attn_kernel<<<dim3(SEQ/BQ, N_WAVE + N_STD, BATCH), 256, ATTN_SMEM_BYTES>>>(
        gQ, gK, gV, wav, gA);

    // Output projection -> d_out (fp32)
    o_gemm<<<dim3(D_MODEL/128, M_ROWS/128), 256, GEMM_SMEM_BYTES>>>(gA, gWot, bo, out);
}

// round 17
// speedup vs baseline: 8.2812x; 1.0284x over previous
#include <cuda_runtime.h>
#include <cuda_fp16.h>
#include <math.h>

#define D_MODEL 1024
#define N_STD   12
#define N_WAVE  4
#define D_K     64
#define STD_DIM 768
#define SEQ     1024
#define BATCH   4
#define M_ROWS  (BATCH*SEQ)   // 4096
#define K2DIM   (D_MODEL/2)   // 512 k-pairs

#define BQ 128
#define BK 64
#define NQT (SEQ/BQ)          // 8 q-tiles per (b,h)

// attn smem (u32 = f16x2): Qs[128][36], then 4x { K[64][36], V[64][36] }
#define QS2 36
#define KVS 36
#define KVBUF (64*KVS)
#define NKV 4
#define ATTN_SMEM_BYTES ((128*QS2 + 2*NKV*KVBUF)*4)   // 92160

// f16 GEMM tiling
#define GBK2 16
#define AS2  20
#define GSTG 3
#define AS_STAGE (128*AS2)    // 2560 u32
#define GEMM_SMEM_BYTES ((GSTG*2*AS_STAGE)*4)   // 61440

// Scratch (allocation-free rule). All f16x2 packed in u32.
// Weights stored N-MAJOR: Wt[n][k2]. Wq pre-scaled by 1/8 (softmax scale fold).
__device__ unsigned g_Xt [M_ROWS*K2DIM];
__device__ unsigned g_Wqt[STD_DIM*K2DIM];
__device__ unsigned g_Wkt[STD_DIM*K2DIM];
__device__ unsigned g_Wvt[D_MODEL*K2DIM];
__device__ unsigned g_Wot[D_MODEL*K2DIM];
__device__ unsigned g_Q  [M_ROWS*(STD_DIM/2)];
__device__ unsigned g_K  [M_ROWS*(STD_DIM/2)];
__device__ unsigned g_V  [M_ROWS*(D_MODEL/2)];
__device__ unsigned g_A  [M_ROWS*(D_MODEL/2)];

__device__ __forceinline__ unsigned packh2(float a, float b) {
    __half2 h = __floats2half2_rn(a, b);
    return *reinterpret_cast<unsigned*>(&h);
}

__device__ __forceinline__ void mma_f16(float c[4],
    unsigned a0, unsigned a1, unsigned a2, unsigned a3,
    unsigned b0, unsigned b1)
{
    asm volatile(
        "mma.sync.aligned.m16n8k16.row.col.f32.f16.f16.f32 "
        "{%0,%1,%2,%3}, {%4,%5,%6,%7}, {%8,%9}, {%0,%1,%2,%3};"
        : "+f"(c[0]), "+f"(c[1]), "+f"(c[2]), "+f"(c[3])
        : "r"(a0), "r"(a1), "r"(a2), "r"(a3), "r"(b0), "r"(b1));
}

__device__ __forceinline__ void ldsm_x4(
    unsigned& r0, unsigned& r1, unsigned& r2, unsigned& r3, unsigned addr)
{
    asm volatile(
        "ldmatrix.sync.aligned.m8n8.x4.shared.b16 {%0,%1,%2,%3}, [%4];"
        : "=r"(r0), "=r"(r1), "=r"(r2), "=r"(r3) : "r"(addr));
}

__device__ __forceinline__ void ldsm_x4_trans(
    unsigned& r0, unsigned& r1, unsigned& r2, unsigned& r3, unsigned addr)
{
    asm volatile(
        "ldmatrix.sync.aligned.m8n8.x4.trans.shared.b16 {%0,%1,%2,%3}, [%4];"
        : "=r"(r0), "=r"(r1), "=r"(r2), "=r"(r3) : "r"(addr));
}

__device__ __forceinline__ void cp16(unsigned* smem_dst, const void* gsrc) {
    unsigned s = (unsigned)__cvta_generic_to_shared(smem_dst);
    asm volatile("cp.async.cg.shared.global [%0], [%1], 16;\n" :: "r"(s), "l"(gsrc));
}
#define CP_COMMIT() asm volatile("cp.async.commit_group;\n")
#define CP_WAIT0()  asm volatile("cp.async.wait_group 0;\n")
#define CP_WAIT1()  asm volatile("cp.async.wait_group 1;\n")
#define CP_WAIT2()  asm volatile("cp.async.wait_group 2;\n")

// ---------------------------------------------------------------------------
// Fused conversions: seg 0 = x -> f16x2 pairs; segs 1-4 = weights -> n-major
// transposed f16x2 (Wq scaled by 0.125).
// ---------------------------------------------------------------------------
__global__ __launch_bounds__(256) void cvt_all(
    const float* __restrict__ x,  unsigned* __restrict__ xt,
    const float* __restrict__ wq, unsigned* __restrict__ wqt,
    const float* __restrict__ wk, unsigned* __restrict__ wkt,
    const float* __restrict__ wv, unsigned* __restrict__ wvt,
    const float* __restrict__ wo, unsigned* __restrict__ wot)
{
    if (blockIdx.y == 0) {
        int i = blockIdx.x * 256 + threadIdx.x;
        int n4 = M_ROWS*D_MODEL/4;
        if (i < n4) {
            float4 v = ((const float4*)x)[i];
            ((uint2*)xt)[i] = make_uint2(packh2(v.x, v.y), packh2(v.z, v.w));
        }
        return;
    }
    const float* W; unsigned* Wt; int N; float sc = 1.f;
    switch (blockIdx.y) {
        case 1: W = wq; Wt = wqt; N = STD_DIM; sc = 0.125f; break;
        case 2: W = wk; Wt = wkt; N = STD_DIM; break;
        case 3: W = wv; Wt = wvt; N = D_MODEL; break;
        default:W = wo; Wt = wot; N = D_MODEL; break;
    }
    const int tiles_n = N / 32;
    const int bx = blockIdx.x;
    if (bx >= tiles_n * 16) return;
    const int n0 = (bx % tiles_n) * 32;
    const int k0 = (bx / tiles_n) * 64;

    __shared__ float sm[64][36];
    const int t = threadIdx.x;
    {
        int row = t >> 3, c4 = (t & 7) * 4;
        *(float4*)&sm[row][c4]    = *(const float4*)(W + (size_t)(k0+row)*N + n0 + c4);
        *(float4*)&sm[row+32][c4] = *(const float4*)(W + (size_t)(k0+row+32)*N + n0 + c4);
    }
    __syncthreads();
    {
        int n = t >> 3, k2q = (t & 7) * 4;
        uint4 o;
        o.x = packh2(sm[2*(k2q+0)][n]*sc, sm[2*(k2q+0)+1][n]*sc);
        o.y = packh2(sm[2*(k2q+1)][n]*sc, sm[2*(k2q+1)+1][n]*sc);
        o.z = packh2(sm[2*(k2q+2)][n]*sc, sm[2*(k2q+2)+1][n]*sc);
        o.w = packh2(sm[2*(k2q+3)][n]*sc, sm[2*(k2q+3)+1][n]*sc);
        *(uint4*)(Wt + (size_t)(n0+n)*K2DIM + k0/2 + k2q) = o;
    }
}

// ---------------------------------------------------------------------------
// FP16 GEMM core with ldmatrix (unchanged).
// ---------------------------------------------------------------------------
template<bool OUT_F16>
__device__ __forceinline__ void h16gemm_core(
    const unsigned* __restrict__ A, const unsigned* __restrict__ Wt,
    const float* __restrict__ bias, float bscale, void* __restrict__ Cv,
    int ldc, int bm, int bn)
{
    extern __shared__ unsigned gsm[];
    const unsigned smem_base = (unsigned)__cvta_generic_to_shared(gsm);

    const int tid  = threadIdx.x;
    const int lane = tid & 31;
    const int wid  = tid >> 5;
    const int warp_m = wid >> 2;
    const int warp_n = wid & 3;
    const int g = lane >> 2;
    const int q = lane & 3;

    const int srow = tid >> 1, soff = (tid & 1) * 8;
    const unsigned* Ap = A  + (size_t)(bm + srow) * K2DIM + soff;
    const unsigned* Wp = Wt + (size_t)(bn + srow) * K2DIM + soff;

    auto issue = [&](int s, int k20) {
        unsigned* As = gsm + s*AS_STAGE;
        unsigned* Bs = gsm + (GSTG + s)*AS_STAGE;
        cp16(As + srow*AS2 + soff,     Ap + k20);
        cp16(As + srow*AS2 + soff + 4, Ap + k20 + 4);
        cp16(Bs + srow*AS2 + soff,     Wp + k20);
        cp16(Bs + srow*AS2 + soff + 4, Wp + k20 + 4);
    };

    issue(0, 0);      CP_COMMIT();
    issue(1, GBK2);   CP_COMMIT();
    CP_WAIT1();
    __syncthreads();

    const int a_off = (warp_m*64 + (lane & 15))*AS2 + (lane >> 4)*4;
    const int b_off = (warp_n*32 + (lane >> 4)*8 + (lane & 7))*AS2 + ((lane >> 3) & 1)*4;

    float acc[4][4][4];
#pragma unroll
    for (int mt = 0; mt < 4; mt++)
#pragma unroll
        for (int nt = 0; nt < 4; nt++)
#pragma unroll
            for (int i = 0; i < 4; i++) acc[mt][nt][i] = 0.f;

    for (int k20 = 0; k20 < K2DIM; k20 += GBK2) {
        const int nxt = k20 + 2*GBK2;
        if (nxt < K2DIM) issue((nxt >> 4) % GSTG, nxt);
        CP_COMMIT();

        const int s = (k20 >> 4) % GSTG;
        const unsigned abase = smem_base + (s*AS_STAGE)*4;
        const unsigned bbase = smem_base + ((GSTG + s)*AS_STAGE)*4;

#pragma unroll
        for (int kb = 0; kb < 2; kb++) {
            const int kc = kb*8;
            unsigned a[4][4], b[2][4];
#pragma unroll
            for (int mt = 0; mt < 4; mt++)
                ldsm_x4(a[mt][0], a[mt][1], a[mt][2], a[mt][3],
                        abase + (a_off + mt*16*AS2 + kc)*4);
#pragma unroll
            for (int np = 0; np < 2; np++)
                ldsm_x4(b[np][0], b[np][1], b[np][2], b[np][3],
                        bbase + (b_off + np*16*AS2 + kc)*4);
#pragma unroll
            for (int mt = 0; mt < 4; mt++)
#pragma unroll
                for (int nt = 0; nt < 4; nt++)
                    mma_f16(acc[mt][nt],
                            a[mt][0], a[mt][1], a[mt][2], a[mt][3],
                            b[nt>>1][(nt&1)*2], b[nt>>1][(nt&1)*2+1]);
        }

        if (k20 + GBK2 < K2DIM) {
            CP_WAIT1();
            __syncthreads();
        }
    }

#pragma unroll
    for (int mt = 0; mt < 4; mt++) {
        int r0 = bm + warp_m*64 + mt*16 + g;
#pragma unroll
        for (int nt = 0; nt < 4; nt++) {
            int col = bn + warp_n*32 + nt*8 + 2*q;
            float2 bb = *(const float2*)&bias[col];
            bb.x *= bscale; bb.y *= bscale;
            float v00 = acc[mt][nt][0] + bb.x, v01 = acc[mt][nt][1] + bb.y;
            float v10 = acc[mt][nt][2] + bb.x, v11 = acc[mt][nt][3] + bb.y;
            if (OUT_F16) {
                unsigned* C = (unsigned*)Cv;
                C[(size_t)r0     * ldc + col/2] = packh2(v00, v01);
                C[(size_t)(r0+8) * ldc + col/2] = packh2(v10, v11);
            } else {
                float* C = (float*)Cv;
                *(float2*)&C[(size_t)r0     * ldc + col] = make_float2(v00, v01);
                *(float2*)&C[(size_t)(r0+8) * ldc + col] = make_float2(v10, v11);
            }
        }
    }
}

__global__ __launch_bounds__(256) void qkv_gemm(
    const unsigned* __restrict__ x,
    const unsigned* __restrict__ Wq, const float* __restrict__ bq,
    const unsigned* __restrict__ Wk, const float* __restrict__ bk_,
    const unsigned* __restrict__ Wv, const float* __restrict__ bv_,
    unsigned* __restrict__ gQ, unsigned* __restrict__ gK, unsigned* __restrict__ gV)
{
    const int bn_g = blockIdx.x * 128;
    const int bm   = blockIdx.y * 128;
    const unsigned* W; const float* bias; unsigned* C; int ldc, bn; float bs = 1.f;
    if (bn_g < 768)       { W = Wq; bias = bq;  C = gQ; ldc = 384; bn = bn_g; bs = 0.125f; }
    else if (bn_g < 1536) { W = Wk; bias = bk_; C = gK; ldc = 384; bn = bn_g - 768; }
    else                  { W = Wv; bias = bv_; C = gV; ldc = 512; bn = bn_g - 1536; }
    h16gemm_core<true>(x, W, bias, bs, C, ldc, bm, bn);
}

__global__ __launch_bounds__(256) void o_gemm(
    const unsigned* __restrict__ A, const unsigned* __restrict__ W,
    const float* __restrict__ bias, float* __restrict__ C)
{
    h16gemm_core<false>(A, W, bias, 1.f, C, D_MODEL, blockIdx.y*128, blockIdx.x*128);
}

// ---------------------------------------------------------------------------
// FP16 causal flash attention, BK=64, 4-buffer cp.async pipeline.
// DIAGONAL PAIRING: block p processes q-tiles (7-p) then (p) sequentially
// -> every block does exactly 18 key-tiles; 256 blocks = one balanced wave.
// ---------------------------------------------------------------------------
__global__ __launch_bounds__(256, 2) void attn_kernel(
    const unsigned* __restrict__ Qb, const unsigned* __restrict__ Kb,
    const unsigned* __restrict__ Vb, const float* __restrict__ wav,
    unsigned* __restrict__ Ab)
{
    extern __shared__ unsigned sm_u[];
    unsigned* Qs = sm_u;                       // [128][QS2]
    unsigned* KV = sm_u + 128*QS2;             // buf s: K at (2s)*KVBUF, V at (2s+1)*KVBUF
    const unsigned smem_base = (unsigned)__cvta_generic_to_shared(sm_u);
    const unsigned kv_base   = smem_base + 128*QS2*4;

    const int b = blockIdx.z, h = blockIdx.y;
    const int pr = blockIdx.x;                 // 0..3 pair index
    const int tid = threadIdx.x;
    const int warp = tid >> 5, lane = tid & 31;
    const int g = lane >> 2, q = lane & 3;
    const bool is_wave = (h < N_WAVE);
    const int hh = h - N_WAVE;
    const int wr0 = warp * 16;

    // per-lane ldmatrix offsets (u32 units)
    const int qa_off = (wr0 + (lane & 15))*QS2 + (lane >> 4)*4;
    const int kb_off = ((lane >> 4)*8 + (lane & 7))*KVS + ((lane >> 3) & 1)*4;
    const int vt_off = (((lane >> 3) & 1)*8 + (lane & 7))*KVS + (lane >> 4)*4;

#pragma unroll 1
    for (int job = 0; job < 2; job++) {
        const int qt = job ? pr : (NQT - 1 - pr);
        const int q0 = qt * BQ;
        const int ntiles = q0/BK + 2;

        // ---- stage Q for this sub-job (visibility via first tile barrier) ----
        if (is_wave) {
            if (tid < 128) {
                const float* wr = wav + (size_t)(b*SEQ + q0 + tid)*24 + h*6;
                const float ws = 0.4082482904638631f;
                unsigned* qrow = Qs + tid*QS2;
                qrow[0] = packh2(wr[0]*ws, wr[1]*ws);
                qrow[1] = packh2(wr[2]*ws, wr[3]*ws);
                qrow[2] = packh2(wr[4]*ws, wr[5]*ws);
                qrow[3] = 0u; qrow[4] = 0u; qrow[5] = 0u; qrow[6] = 0u; qrow[7] = 0u;
            }
        } else {
            const unsigned* Qg = Qb + (size_t)(b*SEQ + q0)*384 + hh*32;
#pragma unroll
            for (int p = 0; p < 4; p++) {
                int idx = tid + p*256;
                int row = idx >> 3, c4 = (idx & 7)*4;
                *(uint4*)(Qs + row*QS2 + c4) = *(const uint4*)(Qg + (size_t)row*384 + c4);
            }
        }

        // stage K/V for tile jj into buffer jj & (NKV-1)
        auto stage_kv = [&](int jj) {
            if (jj >= ntiles) return;          // empty commit keeps ring count
            const int j0s = jj * BK;
            const int s = jj & (NKV - 1);
            unsigned* Kd = KV + (2*s  )*KVBUF;
            unsigned* Vd = KV + (2*s+1)*KVBUF;
            if (is_wave) {
                if (tid < 64) {
                    const float* wr = wav + (size_t)(b*SEQ + j0s + tid)*24 + h*6;
                    unsigned* kr = Kd + tid*KVS;
                    kr[0] = packh2(wr[0], wr[1]);
                    kr[1] = packh2(wr[2], wr[3]);
                    kr[2] = packh2(wr[4], wr[5]);
                    kr[3] = 0u; kr[4] = 0u; kr[5] = 0u; kr[6] = 0u; kr[7] = 0u;
                }
            } else {
#pragma unroll
                for (int p = 0; p < 2; p++) {
                    int idx = tid + p*256;
                    int row = idx >> 3, c4 = (idx & 7)*4;
                    cp16(Kd + row*KVS + c4,
                         Kb + (size_t)(b*SEQ + j0s + row)*384 + hh*32 + c4);
                }
            }
#pragma unroll
            for (int p = 0; p < 2; p++) {
                int idx = tid + p*256;
                int row = idx >> 3, c4 = (idx & 7)*4;
                cp16(Vd + row*KVS + c4,
                     Vb + (size_t)(b*SEQ + j0s + row)*512 + h*32 + c4);
            }
        };

        float m0 = -1e30f, m1 = -1e30f, l0 = 0.f, l1 = 0.f;
        float o[8][4];
#pragma unroll
        for (int nt = 0; nt < 8; nt++)
#pragma unroll
            for (int i = 0; i < 4; i++) o[nt][i] = 0.f;

        stage_kv(0); CP_COMMIT();
        stage_kv(1); CP_COMMIT();

        for (int jt = 0; jt < ntiles; jt++) {
            const int j0 = jt * BK;
            const int cur = jt & (NKV - 1);

            stage_kv(jt + 2);
            CP_COMMIT();
            CP_WAIT2();           // tile jt's group complete
            __syncthreads();      // staging visible to all warps

            if (j0 <= q0 + wr0 + 15) {     // warp-uniform causal tile skip
                const unsigned ks_b = kv_base + (2*cur  )*KVBUF*4;
                const unsigned vs_b = kv_base + (2*cur+1)*KVBUF*4;

                // ---- scores: 16x64 per warp (Q pre-scaled) ----
                float sacc[8][4];
#pragma unroll
                for (int nt = 0; nt < 8; nt++)
#pragma unroll
                    for (int i = 0; i < 4; i++) sacc[nt][i] = 0.f;

                const int nkb = is_wave ? 1 : 4;
                for (int kb = 0; kb < nkb; kb++) {
                    const int kc = kb*8;
                    unsigned a0, a1, a2, a3;
                    ldsm_x4(a0, a1, a2, a3, smem_base + (qa_off + kc)*4);
#pragma unroll
                    for (int np = 0; np < 4; np++) {
                        unsigned b0, b1, b2, b3;
                        ldsm_x4(b0, b1, b2, b3, ks_b + (kb_off + np*16*KVS + kc)*4);
                        mma_f16(sacc[np*2  ], a0, a1, a2, a3, b0, b1);
                        mma_f16(sacc[np*2+1], a0, a1, a2, a3, b2, b3);
                    }
                }

                // ---- mask only when the tile crosses this warp's diagonal ----
                if (j0 + 63 > q0 + wr0) {
                    const int r0 = q0 + wr0 + g, r1 = r0 + 8;
#pragma unroll
                    for (int nt = 0; nt < 8; nt++) {
                        int c0 = j0 + nt*8 + 2*q, c1 = c0 + 1;
                        if (c0 > r0) sacc[nt][0] = -1e30f;
                        if (c1 > r0) sacc[nt][1] = -1e30f;
                        if (c0 > r1) sacc[nt][2] = -1e30f;
                        if (c1 > r1) sacc[nt][3] = -1e30f;
                    }
                }

                // ---- online softmax (quad reductions) ----
                float mx0 = -1e30f, mx1 = -1e30f;
#pragma unroll
                for (int nt = 0; nt < 8; nt++) {
                    mx0 = fmaxf(mx0, fmaxf(sacc[nt][0], sacc[nt][1]));
                    mx1 = fmaxf(mx1, fmaxf(sacc[nt][2], sacc[nt][3]));
                }
                mx0 = fmaxf(mx0, __shfl_xor_sync(0xffffffffu, mx0, 1));
                mx0 = fmaxf(mx0, __shfl_xor_sync(0xffffffffu, mx0, 2));
                mx1 = fmaxf(mx1, __shfl_xor_sync(0xffffffffu, mx1, 1));
                mx1 = fmaxf(mx1, __shfl_xor_sync(0xffffffffu, mx1, 2));

                float mn0 = fmaxf(m0, mx0), mn1 = fmaxf(m1, mx1);
                float fac0 = __expf(m0 - mn0), fac1 = __expf(m1 - mn1);

                float ps0 = 0.f, ps1 = 0.f;
#pragma unroll
                for (int nt = 0; nt < 8; nt++) {
                    sacc[nt][0] = __expf(sacc[nt][0] - mn0);
                    sacc[nt][1] = __expf(sacc[nt][1] - mn0);
                    sacc[nt][2] = __expf(sacc[nt][2] - mn1);
                    sacc[nt][3] = __expf(sacc[nt][3] - mn1);
                    ps0 += sacc[nt][0] + sacc[nt][1];
                    ps1 += sacc[nt][2] + sacc[nt][3];
                }
                ps0 += __shfl_xor_sync(0xffffffffu, ps0, 1);
                ps0 += __shfl_xor_sync(0xffffffffu, ps0, 2);
                ps1 += __shfl_xor_sync(0xffffffffu, ps1, 1);
                ps1 += __shfl_xor_sync(0xffffffffu, ps1, 2);

                l0 = l0*fac0 + ps0;  l1 = l1*fac1 + ps1;
                m0 = mn0;            m1 = mn1;
#pragma unroll
                for (int nt = 0; nt < 8; nt++) {
                    o[nt][0] *= fac0; o[nt][1] *= fac0;
                    o[nt][2] *= fac1; o[nt][3] *= fac1;
                }

                // ---- PV: O += P(16x64) @ V(64x64); V via ldmatrix.trans ----
#pragma unroll
                for (int kb2 = 0; kb2 < 4; kb2++) {
                    unsigned pa0 = packh2(sacc[2*kb2  ][0], sacc[2*kb2  ][1]);
                    unsigned pa1 = packh2(sacc[2*kb2  ][2], sacc[2*kb2  ][3]);
                    unsigned pa2 = packh2(sacc[2*kb2+1][0], sacc[2*kb2+1][1]);
                    unsigned pa3 = packh2(sacc[2*kb2+1][2], sacc[2*kb2+1][3]);
#pragma unroll
                    for (int ntp = 0; ntp < 4; ntp++) {
                        unsigned b0, b1, b2, b3;
                        ldsm_x4_trans(b0, b1, b2, b3,
                            vs_b + (vt_off + kb2*16*KVS + ntp*8)*4);
                        mma_f16(o[2*ntp  ], pa0, pa1, pa2, pa3, b0, b1);
                        mma_f16(o[2*ntp+1], pa0, pa1, pa2, pa3, b2, b3);
                    }
                }
            }
        }

        // ---- epilogue for this sub-job ----
        float inv0 = 1.f / l0, inv1 = 1.f / l1;
        unsigned* A0 = Ab + (size_t)(b*SEQ + q0 + wr0 + g)*512 + h*32;
        unsigned* A1 = A0 + 8*512;
#pragma unroll
        for (int nt = 0; nt < 8; nt++) {
            A0[nt*4 + q] = packh2(o[nt][0]*inv0, o[nt][1]*inv0);
            A1[nt*4 + q] = packh2(o[nt][2]*inv1, o[nt][3]*inv1);
        }

        // drain cp.async ring + protect Qs/KV before next sub-job restages
        CP_WAIT0();
        __syncthreads();
    }
}

// ---------------------------------------------------------------------------
extern "C" void kernel_launch(void* const* d_in, const int* in_sizes, int n_in,
                              void* d_out, int out_size)
{
    const float* x   = (const float*)d_in[0];
    const float* wav = (const float*)d_in[1];
    const float* Wq  = (const float*)d_in[3];
    const float* bq  = (const float*)d_in[4];
    const float* Wk  = (const float*)d_in[5];
    const float* bk  = (const float*)d_in[6];
    const float* Wv  = (const float*)d_in[7];
    const float* bv  = (const float*)d_in[8];
    const float* Wo  = (const float*)d_in[9];
    const float* bo  = (const float*)d_in[10];
    float* out = (float*)d_out;

    unsigned *gXt, *gWqt, *gWkt, *gWvt, *gWot, *gQ, *gK, *gV, *gA;
    cudaGetSymbolAddress((void**)&gXt,  g_Xt);
    cudaGetSymbolAddress((void**)&gWqt, g_Wqt);
    cudaGetSymbolAddress((void**)&gWkt, g_Wkt);
    cudaGetSymbolAddress((void**)&gWvt, g_Wvt);
    cudaGetSymbolAddress((void**)&gWot, g_Wot);
    cudaGetSymbolAddress((void**)&gQ,   g_Q);
    cudaGetSymbolAddress((void**)&gK,   g_K);
    cudaGetSymbolAddress((void**)&gV,   g_V);
    cudaGetSymbolAddress((void**)&gA,   g_A);

    cudaFuncSetAttribute(attn_kernel,
        cudaFuncAttributeMaxDynamicSharedMemorySize, ATTN_SMEM_BYTES);
    cudaFuncSetAttribute(qkv_gemm,
        cudaFuncAttributeMaxDynamicSharedMemorySize, GEMM_SMEM_BYTES);
    cudaFuncSetAttribute(o_gemm,
        cudaFuncAttributeMaxDynamicSharedMemorySize, GEMM_SMEM_BYTES);

    // One fused conversion launch (x + 4 weight matrices)
    cvt_all<<<dim3(M_ROWS*D_MODEL/4/256, 5), 256>>>(
        x, gXt, Wq, gWqt, Wk, gWkt, Wv, gWvt, Wo, gWot);

    // Fused Q/K/V projections (f16 tensor cores, cp.async + ldmatrix)
    qkv_gemm<<<dim3(20, M_ROWS/128), 256, GEMM_SMEM_BYTES>>>(
        gXt, gWqt, bq, gWkt, bk, gWvt, bv, gQ, gK, gV);

    // f16 tensor-core causal attention, diagonal-paired blocks -> gA
    attn_kernel<<<dim3(NQT/2, N_WAVE + N_STD, BATCH), 256, ATTN_SMEM_BYTES>>>(
        gQ, gK, gV, wav, gA);

    // Output projection -> d_out (fp32)
    o_gemm<<<dim3(D_MODEL/128, M_ROWS/128), 256, GEMM_SMEM_BYTES>>>(gA, gWot, bo, out);
}